// round 9
// baseline (speedup 1.0000x reference)
#include <cuda_runtime.h>
#include <cuda_bf16.h>
#include <math.h>
#include <stdint.h>

#define BB 128
#define PP 196
#define EE 2048
#define HH 512
#define VV 10000
#define VPAD 10112
#define TT 20
#define SS 19
#define XK 3072
#define G4 2048
#define QG 2560          // q(512) + gate(2048) merged output width

typedef __nv_bfloat16 bf16;

// ---------------- device global scratch ----------------
__device__ bf16  g_imgh[(size_t)BB * PP * EE];
__device__ bf16  g_imgl[(size_t)BB * PP * EE];
__device__ float g_Ws[(size_t)BB * PP * HH];
__device__ bf16  g_BWatt_h[HH * EE],  g_BWatt_l[HH * EE];
__device__ bf16  g_BWih_h[HH * EE],   g_BWih_l[HH * EE];
__device__ bf16  g_BWic_h[HH * EE],   g_BWic_l[HH * EE];
__device__ bf16  g_Bqg_h[QG * HH],    g_Bqg_l[QG * HH];      // [U_att ; Wfb] rows=out col
__device__ bf16  g_BWcat_h[(size_t)G4 * XK], g_BWcat_l[(size_t)G4 * XK];
__device__ bf16  g_BWdo_h[(size_t)VPAD * HH], g_BWdo_l[(size_t)VPAD * HH];
__device__ bf16  g_avgh[BB * EE], g_avgl[BB * EE];
__device__ bf16  g_Xh[BB * XK],   g_Xl[BB * XK];
__device__ bf16  g_Hh[(size_t)SS * BB * HH], g_Hl[(size_t)SS * BB * HH];
__device__ float g_c[BB * HH];
// split-K partials. g_qgp doubles as h0 partials (8*BB*HH fits), g_gatesp as c0.
__device__ float g_qgp[4 * BB * QG];
__device__ float g_gatesp[8 * BB * G4];

// ---------------- helpers ----------------
__device__ __forceinline__ uint32_t s2u(const void* p) {
    uint32_t a;
    asm("{ .reg .u64 t; cvta.to.shared.u64 t, %1; cvt.u32.u64 %0, t; }" : "=r"(a) : "l"(p));
    return a;
}
__device__ __forceinline__ void cp16(uint32_t s, const void* g) {
    asm volatile("cp.async.cg.shared.global [%0], [%1], 16;" :: "r"(s), "l"(g) : "memory");
}
__device__ __forceinline__ void cp_commit() { asm volatile("cp.async.commit_group;" ::: "memory"); }
template <int N> __device__ __forceinline__ void cp_wait() {
    asm volatile("cp.async.wait_group %0;" :: "n"(N) : "memory");
}
__device__ __forceinline__ void ldsm4(uint32_t* r, uint32_t addr) {
    asm volatile("ldmatrix.sync.aligned.m8n8.x4.shared.b16 {%0,%1,%2,%3}, [%4];"
                 : "=r"(r[0]), "=r"(r[1]), "=r"(r[2]), "=r"(r[3]) : "r"(addr));
}
__device__ __forceinline__ void mma16816(float* d, const uint32_t* a, const uint32_t* b) {
    asm volatile("mma.sync.aligned.m16n8k16.row.col.f32.bf16.bf16.f32 "
                 "{%0,%1,%2,%3}, {%4,%5,%6,%7}, {%8,%9}, {%0,%1,%2,%3};"
                 : "+f"(d[0]), "+f"(d[1]), "+f"(d[2]), "+f"(d[3])
                 : "r"(a[0]), "r"(a[1]), "r"(a[2]), "r"(a[3]), "r"(b[0]), "r"(b[1]));
}
__device__ __forceinline__ float ex2f(float x) { float r; asm("ex2.approx.f32 %0,%1;" : "=f"(r) : "f"(x)); return r; }
__device__ __forceinline__ float rcpf(float x) { float r; asm("rcp.approx.f32 %0,%1;" : "=f"(r) : "f"(x)); return r; }
__device__ __forceinline__ float tanh_fast(float x) {
    float ax = fabsf(x);
    float e  = ex2f(ax * -2.8853900817779268f);
    float r  = (1.0f - e) * rcpf(1.0f + e);
    return copysignf(r, x);
}
__device__ __forceinline__ void split2(float v, bf16* ph, bf16* pl) {
    bf16 h = __float2bfloat16(v);
    *ph = h;
    *pl = __float2bfloat16(v - __bfloat162float(h));
}

// ---------------- split-bf16 HMMA GEMM, 4-stage pipeline, split-K via grid.z ----
#define TILE_B   10240
#define BUF_B    40960
#define SMEM_SZ  163840

__global__ void __launch_bounds__(256, 1)
tc_gemm(const bf16* __restrict__ Ah, const bf16* __restrict__ Al, int lda,
        const bf16* __restrict__ Bh, const bf16* __restrict__ Bl,
        const float* __restrict__ bias, float* __restrict__ C, int ldc,
        long tile_stride, int Nstore, int K)
{
    extern __shared__ char sm[];
    const int tid = threadIdx.x, lane = tid & 31, wid = tid >> 5;
    const int m0 = blockIdx.y << 7, n0 = blockIdx.x << 7;
    const int wy = wid & 1, wx = wid >> 1;
    const uint32_t sb = s2u(sm);

    const int kc = K / gridDim.z;
    const size_t kofs = (size_t)blockIdx.z * kc * 2;
    C += (size_t)blockIdx.z * gridDim.y * tile_stride + (size_t)blockIdx.y * tile_stride;

    const char* gAh = (const char*)(Ah + (size_t)m0 * lda) + kofs;
    const char* gAl = (const char*)(Al + (size_t)m0 * lda) + kofs;
    const char* gBh = (const char*)(Bh + (size_t)n0 * K) + kofs;
    const char* gBl = (const char*)(Bl + (size_t)n0 * K) + kofs;
    const size_t strA = (size_t)lda * 2, strB = (size_t)K * 2;

    const int arow = lane & 15;
    const int acol = (lane >> 4) << 4;
    const int brow = ((lane >> 4) << 3) + (lane & 7);
    const int bcol = ((lane >> 3) & 1) << 4;
    const uint32_t aoff = (uint32_t)((wy * 64 + arow) * 80 + acol);
    const uint32_t boff = (uint32_t)((wx * 32 + brow) * 80 + bcol);

    float acc[4][4][4] = {};
    const int nk = kc >> 5;

    auto issue = [&](int ch) {
        if (ch < nk) {
            const int k0b = ch << 6;
            const uint32_t s0 = sb + (ch & 3) * BUF_B;
            #pragma unroll
            for (int half = 0; half < 2; half++) {
                int u  = tid + half * 256;
                int r  = u >> 2;
                int sg = (u & 3) << 4;
                uint32_t s = s0 + r * 80 + sg;
                size_t gA = (size_t)r * strA + k0b + sg;
                size_t gB = (size_t)r * strB + k0b + sg;
                cp16(s,              gAh + gA);
                cp16(s + TILE_B,     gAl + gA);
                cp16(s + 2 * TILE_B, gBh + gB);
                cp16(s + 3 * TILE_B, gBl + gB);
            }
        }
        cp_commit();
    };

    issue(0); issue(1); issue(2);

    for (int ch = 0; ch < nk; ch++) {
        cp_wait<2>();
        __syncthreads();
        issue(ch + 3);

        const uint32_t base = sb + (ch & 3) * BUF_B;
        #pragma unroll
        for (int ks = 0; ks < 2; ks++) {
            uint32_t ah[4][4], al[4][4];
            #pragma unroll
            for (int mi = 0; mi < 4; mi++) {
                uint32_t o = aoff + mi * (16 * 80) + ks * 32;
                ldsm4(ah[mi], base + o);
                ldsm4(al[mi], base + TILE_B + o);
            }
            uint32_t bh[2][4], bl[2][4];
            #pragma unroll
            for (int nj = 0; nj < 2; nj++) {
                uint32_t o = boff + nj * (16 * 80) + ks * 32;
                ldsm4(bh[nj], base + 2 * TILE_B + o);
                ldsm4(bl[nj], base + 3 * TILE_B + o);
            }
            #pragma unroll
            for (int mi = 0; mi < 4; mi++) {
                #pragma unroll
                for (int n8 = 0; n8 < 4; n8++) {
                    const uint32_t* pbh = &bh[n8 >> 1][(n8 & 1) << 1];
                    const uint32_t* pbl = &bl[n8 >> 1][(n8 & 1) << 1];
                    mma16816(acc[mi][n8], ah[mi], pbh);
                    mma16816(acc[mi][n8], ah[mi], pbl);
                    mma16816(acc[mi][n8], al[mi], pbh);
                }
            }
        }
    }

    #pragma unroll
    for (int mi = 0; mi < 4; mi++) {
        #pragma unroll
        for (int n8 = 0; n8 < 4; n8++) {
            int rb = wy * 64 + mi * 16 + (lane >> 2);
            int nb = n0 + wx * 32 + n8 * 8 + ((lane & 3) << 1);
            #pragma unroll
            for (int g = 0; g < 2; g++) {
                int r = rb + g * 8;
                #pragma unroll
                for (int j = 0; j < 2; j++) {
                    int n = nb + j;
                    if (n < Nstore) {
                        float v = acc[mi][n8][g * 2 + j];
                        if (bias) v += bias[n];
                        C[(size_t)r * ldc + n] = v;
                    }
                }
            }
        }
    }
}

// ---------------- conversion kernels ----------------
__global__ void split_kernel(const float* __restrict__ src, bf16* __restrict__ dh,
                             bf16* __restrict__ dl, int n)
{
    int i = blockIdx.x * 256 + threadIdx.x;
    if (i < n) split2(src[i], dh + i, dl + i);
}

__global__ void tsplit_kernel(const float* __restrict__ src, bf16* __restrict__ dh,
                              bf16* __restrict__ dl, int Ksrc, int N, int dst_ld, int koff)
{
    __shared__ float t[32][33];
    const int n0 = blockIdx.x << 5, k0 = blockIdx.y << 5;
    #pragma unroll
    for (int j = 0; j < 4; j++) {
        int kk = k0 + threadIdx.y + (j << 3);
        int n  = n0 + threadIdx.x;
        t[threadIdx.y + (j << 3)][threadIdx.x] = (n < N) ? src[(size_t)kk * N + n] : 0.0f;
    }
    __syncthreads();
    #pragma unroll
    for (int j = 0; j < 4; j++) {
        int nn = n0 + threadIdx.y + (j << 3);
        int k  = k0 + threadIdx.x;
        size_t o = (size_t)nn * dst_ld + koff + k;
        split2(t[threadIdx.x][threadIdx.y + (j << 3)], dh + o, dl + o);
    }
}

// ---------------- pointwise kernels ----------------
__global__ void avg_kernel(const float* __restrict__ img,
                           bf16* __restrict__ ah, bf16* __restrict__ al)
{
    int b = blockIdx.y;
    int e = blockIdx.x * 256 + threadIdx.x;
    const float* ib = img + (size_t)b * PP * EE + e;
    float s = 0;
    #pragma unroll 4
    for (int p = 0; p < PP; p++) s += ib[(size_t)p * EE];
    split2(s * (1.0f / PP), ah + b * EE + e, al + b * EE + e);
}

__global__ void combine_init(const float* __restrict__ hp, const float* __restrict__ cp,
                             const float* __restrict__ bih, const float* __restrict__ bic,
                             const float* __restrict__ Wemb, const int* __restrict__ cap,
                             float* __restrict__ c, bf16* __restrict__ Xh, bf16* __restrict__ Xl)
{
    int i = blockIdx.x * 256 + threadIdx.x;   // B*H
    int b = i >> 9, h = i & 511;
    float sh = bih[h], sc = bic[h];
    #pragma unroll
    for (int z = 0; z < 8; z++) { sh += hp[z * BB * HH + i]; sc += cp[z * BB * HH + i]; }
    c[i] = tanhf(sc);
    size_t o = (size_t)b * XK + 2560 + h;
    split2(tanhf(sh), Xh + o, Xl + o);
    int cw = cap[b * TT + 0];
    size_t oe = (size_t)b * XK + h;
    split2(Wemb[(size_t)cw * HH + h], Xh + oe, Xl + oe);
}

// ---------------- fused attention + softmax + context + gate + X-write ----------
__global__ void __launch_bounds__(256)
att_ctx_kernel(const float* __restrict__ Ws, const float* __restrict__ qgp,
               const float* __restrict__ bU, const float* __restrict__ bfb,
               const float* __restrict__ v_att, const float* __restrict__ bv,
               const float* __restrict__ img,
               bf16* __restrict__ Xh, bf16* __restrict__ Xl,
               float* __restrict__ alpha_out)
{
    __shared__ float qs[HH], vs[HH], es[PP], gate[EE], al[PP], red[8];
    const int b = blockIdx.x, tid = threadIdx.x;
    const int lane = tid & 31, warp = tid >> 5;
    const size_t qb = (size_t)b * QG;

    for (int i = tid; i < HH; i += 256) {
        float s = bU[i];
        #pragma unroll
        for (int z = 0; z < 4; z++) s += qgp[(size_t)z * BB * QG + qb + i];
        qs[i] = s;
        vs[i] = v_att[i];
    }
    for (int e = tid; e < EE; e += 256) {
        float s = bfb[e];
        #pragma unroll
        for (int z = 0; z < 4; z++) s += qgp[(size_t)z * BB * QG + qb + HH + e];
        gate[e] = 1.0f / (1.0f + expf(-s));
    }
    __syncthreads();

    // attention scores
    const float* Wb = Ws + (size_t)b * PP * HH;
    const float bv0 = bv[0];
    for (int p = warp; p < PP; p += 8) {
        const float* row = Wb + (size_t)p * HH;
        float s = 0.0f;
        #pragma unroll
        for (int i = 0; i < HH / 32; i++) {
            int h = lane + 32 * i;
            s += vs[h] * tanh_fast(row[h] + qs[h]);
        }
        #pragma unroll
        for (int o = 16; o; o >>= 1) s += __shfl_xor_sync(0xffffffffu, s, o);
        if (lane == 0) es[p] = s + bv0;
    }
    __syncthreads();

    // softmax over P
    float m = -1e30f;
    for (int p = tid; p < PP; p += 256) m = fmaxf(m, es[p]);
    #pragma unroll
    for (int o = 16; o; o >>= 1) m = fmaxf(m, __shfl_xor_sync(0xffffffffu, m, o));
    if (lane == 0) red[warp] = m;
    __syncthreads();
    if (warp == 0) {
        float t = (lane < 8) ? red[lane] : -1e30f;
        #pragma unroll
        for (int o = 4; o; o >>= 1) t = fmaxf(t, __shfl_xor_sync(0xffffffffu, t, o));
        if (lane == 0) red[0] = t;
    }
    __syncthreads();
    m = red[0];
    __syncthreads();
    float sum = 0.0f;
    for (int p = tid; p < PP; p += 256) { float ev = expf(es[p] - m); es[p] = ev; sum += ev; }
    #pragma unroll
    for (int o = 16; o; o >>= 1) sum += __shfl_xor_sync(0xffffffffu, sum, o);
    if (lane == 0) red[warp] = sum;
    __syncthreads();
    if (warp == 0) {
        float t = (lane < 8) ? red[lane] : 0.0f;
        #pragma unroll
        for (int o = 4; o; o >>= 1) t += __shfl_xor_sync(0xffffffffu, t, o);
        if (lane == 0) red[0] = t;
    }
    __syncthreads();
    float inv = 1.0f / red[0];
    for (int p = tid; p < PP; p += 256) {
        float a = es[p] * inv;
        al[p] = a;
        alpha_out[(size_t)b * (SS * PP) + p] = a;
    }
    __syncthreads();

    // context: each thread owns cols [e0,e0+4) and [e1,e1+4)
    const float4* ib = (const float4*)(img + (size_t)b * PP * EE);
    const int e0 = tid << 2, e1 = 1024 + (tid << 2);
    float4 a0 = {0, 0, 0, 0}, a1 = {0, 0, 0, 0};
    #pragma unroll 2
    for (int p = 0; p < PP; p++) {
        float ap = al[p];
        float4 v0 = ib[(p * EE + e0) >> 2];
        float4 v1 = ib[(p * EE + e1) >> 2];
        a0.x += ap * v0.x; a0.y += ap * v0.y; a0.z += ap * v0.z; a0.w += ap * v0.w;
        a1.x += ap * v1.x; a1.y += ap * v1.y; a1.z += ap * v1.z; a1.w += ap * v1.w;
    }
    size_t xo = (size_t)b * XK + HH;
    split2(a0.x * gate[e0    ], Xh + xo + e0,     Xl + xo + e0);
    split2(a0.y * gate[e0 + 1], Xh + xo + e0 + 1, Xl + xo + e0 + 1);
    split2(a0.z * gate[e0 + 2], Xh + xo + e0 + 2, Xl + xo + e0 + 2);
    split2(a0.w * gate[e0 + 3], Xh + xo + e0 + 3, Xl + xo + e0 + 3);
    split2(a1.x * gate[e1    ], Xh + xo + e1,     Xl + xo + e1);
    split2(a1.y * gate[e1 + 1], Xh + xo + e1 + 1, Xl + xo + e1 + 1);
    split2(a1.z * gate[e1 + 2], Xh + xo + e1 + 2, Xl + xo + e1 + 2);
    split2(a1.w * gate[e1 + 3], Xh + xo + e1 + 3, Xl + xo + e1 + 3);
}

// LSTM + h history + emb for next step
__global__ void lstm_kernel(const float* __restrict__ gatesp, const float* __restrict__ bl,
                            float* __restrict__ c, bf16* __restrict__ Xh, bf16* __restrict__ Xl,
                            bf16* __restrict__ Hh, bf16* __restrict__ Hl,
                            const float* __restrict__ Wemb, const int* __restrict__ cap, int t)
{
    int i = blockIdx.x * 256 + threadIdx.x;
    int b = i >> 9, h = i & 511;
    float g[4];
    #pragma unroll
    for (int k = 0; k < 4; k++) {
        int j = k * HH + h;
        float s = bl[j];
        #pragma unroll
        for (int z = 0; z < 8; z++) s += gatesp[(size_t)z * BB * G4 + b * G4 + j];
        g[k] = s;
    }
    float ig = 1.0f / (1.0f + expf(-g[0]));
    float fg = 1.0f / (1.0f + expf(-g[1]));
    float gg = tanhf(g[2]);
    float og = 1.0f / (1.0f + expf(-g[3]));
    float cn = fg * c[i] + ig * gg;
    c[i] = cn;
    float hn = og * tanhf(cn);
    size_t o = (size_t)b * XK + 2560 + h;
    split2(hn, Xh + o, Xl + o);
    size_t oh = (size_t)(t * BB + b) * HH + h;
    split2(hn, Hh + oh, Hl + oh);
    int cw = cap[b * TT + (t + 1)];
    size_t oe = (size_t)b * XK + h;
    split2(Wemb[(size_t)cw * HH + h], Xh + oe, Xl + oe);
}

// ---------------- host launch ----------------
extern "C" void kernel_launch(void* const* d_in, const int* in_sizes, int n_in,
                              void* d_out, int out_size)
{
    const float* img   = (const float*)d_in[0];
    const int*   cap   = (const int*)  d_in[1];
    const float* U_att = (const float*)d_in[2];
    const float* bU    = (const float*)d_in[3];
    const float* W_att = (const float*)d_in[4];
    const float* bW    = (const float*)d_in[5];
    const float* v_att = (const float*)d_in[6];
    const float* bv    = (const float*)d_in[7];
    const float* Wih   = (const float*)d_in[8];
    const float* bih   = (const float*)d_in[9];
    const float* Wic   = (const float*)d_in[10];
    const float* bic   = (const float*)d_in[11];
    const float* Wfb   = (const float*)d_in[12];
    const float* bfb   = (const float*)d_in[13];
    const float* Wdo   = (const float*)d_in[14];
    const float* bdo   = (const float*)d_in[15];
    const float* Wemb  = (const float*)d_in[16];
    const float* Wl    = (const float*)d_in[17];
    const float* Ul    = (const float*)d_in[18];
    const float* bl    = (const float*)d_in[19];

    float* preds  = (float*)d_out;
    float* alphas = (float*)d_out + (size_t)BB * SS * VV;

    bf16 *imgh, *imgl, *BWatt_h, *BWatt_l, *BWih_h, *BWih_l, *BWic_h, *BWic_l;
    bf16 *Bqg_h, *Bqg_l, *BWcat_h, *BWcat_l, *BWdo_h, *BWdo_l;
    bf16 *avgh, *avgl, *Xh, *Xl, *Hh, *Hl;
    float *pWs, *pc, *pqgp, *pgatesp;
    cudaGetSymbolAddress((void**)&imgh, g_imgh);     cudaGetSymbolAddress((void**)&imgl, g_imgl);
    cudaGetSymbolAddress((void**)&BWatt_h, g_BWatt_h); cudaGetSymbolAddress((void**)&BWatt_l, g_BWatt_l);
    cudaGetSymbolAddress((void**)&BWih_h, g_BWih_h); cudaGetSymbolAddress((void**)&BWih_l, g_BWih_l);
    cudaGetSymbolAddress((void**)&BWic_h, g_BWic_h); cudaGetSymbolAddress((void**)&BWic_l, g_BWic_l);
    cudaGetSymbolAddress((void**)&Bqg_h, g_Bqg_h);   cudaGetSymbolAddress((void**)&Bqg_l, g_Bqg_l);
    cudaGetSymbolAddress((void**)&BWcat_h, g_BWcat_h); cudaGetSymbolAddress((void**)&BWcat_l, g_BWcat_l);
    cudaGetSymbolAddress((void**)&BWdo_h, g_BWdo_h); cudaGetSymbolAddress((void**)&BWdo_l, g_BWdo_l);
    cudaGetSymbolAddress((void**)&avgh, g_avgh);     cudaGetSymbolAddress((void**)&avgl, g_avgl);
    cudaGetSymbolAddress((void**)&Xh, g_Xh);         cudaGetSymbolAddress((void**)&Xl, g_Xl);
    cudaGetSymbolAddress((void**)&Hh, g_Hh);         cudaGetSymbolAddress((void**)&Hl, g_Hl);
    cudaGetSymbolAddress((void**)&pWs, g_Ws);        cudaGetSymbolAddress((void**)&pc, g_c);
    cudaGetSymbolAddress((void**)&pqgp, g_qgp);
    cudaGetSymbolAddress((void**)&pgatesp, g_gatesp);

    cudaFuncSetAttribute(tc_gemm, cudaFuncAttributeMaxDynamicSharedMemorySize, SMEM_SZ);

    // one-time conversions
    {
        int n = BB * PP * EE;
        split_kernel<<<(n + 255) / 256, 256>>>(img, imgh, imgl, n);
        dim3 blk(32, 8);
        tsplit_kernel<<<dim3(16, 64), blk>>>(W_att, BWatt_h, BWatt_l, EE, HH, EE, 0);
        tsplit_kernel<<<dim3(16, 64), blk>>>(Wih,   BWih_h,  BWih_l,  EE, HH, EE, 0);
        tsplit_kernel<<<dim3(16, 64), blk>>>(Wic,   BWic_h,  BWic_l,  EE, HH, EE, 0);
        // merged B = [U_att ; Wfb] as [2560, 512]
        tsplit_kernel<<<dim3(16, 16), blk>>>(U_att, Bqg_h, Bqg_l, HH, HH, HH, 0);
        tsplit_kernel<<<dim3(64, 16), blk>>>(Wfb,   Bqg_h + (size_t)HH * HH,
                                             Bqg_l + (size_t)HH * HH, HH, EE, HH, 0);
        tsplit_kernel<<<dim3(64, 80), blk>>>(Wl,    BWcat_h, BWcat_l, 2560, G4, XK, 0);
        tsplit_kernel<<<dim3(64, 16), blk>>>(Ul,    BWcat_h, BWcat_l, HH,   G4, XK, 2560);
        tsplit_kernel<<<dim3(VPAD / 32, 16), blk>>>(Wdo, BWdo_h, BWdo_l, HH, VV, HH, 0);
    }

    // init: avg -> h0/c0 partials (split-K x8, reuse partial buffers) -> combine
    avg_kernel<<<dim3(EE / 256, BB), 256>>>(img, avgh, avgl);
    tc_gemm<<<dim3(4, 1, 8), 256, SMEM_SZ>>>(avgh, avgl, EE, BWih_h, BWih_l,
                                             nullptr, pqgp, HH, (long)128 * HH, HH, EE);
    tc_gemm<<<dim3(4, 1, 8), 256, SMEM_SZ>>>(avgh, avgl, EE, BWic_h, BWic_l,
                                             nullptr, pgatesp, HH, (long)128 * HH, HH, EE);
    combine_init<<<(BB * HH) / 256, 256>>>(pqgp, pgatesp, bih, bic, Wemb, cap, pc, Xh, Xl);

    // W_s = img @ W_att + bW
    tc_gemm<<<dim3(4, 196, 1), 256, SMEM_SZ>>>(imgh, imgl, EE, BWatt_h, BWatt_l,
                                               bW, pWs, HH, (long)128 * HH, HH, EE);

    for (int t = 0; t < SS; t++) {
        // merged q+gate partials: [128, 2560] = h @ [U_att; Wfb]^T, split-K x4
        tc_gemm<<<dim3(QG / 128, 1, 4), 256, SMEM_SZ>>>(Xh + 2560, Xl + 2560, XK,
                                                        Bqg_h, Bqg_l, nullptr, pqgp,
                                                        QG, (long)128 * QG, QG, HH);
        // fused attention + softmax + context + gate + X write
        att_ctx_kernel<<<BB, 256>>>(pWs, pqgp, bU, bfb, v_att, bv, img,
                                    Xh, Xl, alphas + (size_t)t * PP);
        // gates partials (split-K x8)
        tc_gemm<<<dim3(16, 1, 8), 256, SMEM_SZ>>>(Xh, Xl, XK,
                                                  BWcat_h, BWcat_l, nullptr, pgatesp,
                                                  G4, (long)128 * G4, G4, XK);
        lstm_kernel<<<(BB * HH) / 256, 256>>>(pgatesp, bl, pc, Xh, Xl, Hh, Hl, Wemb, cap, t);
    }

    // batched preds for all 19 steps
    tc_gemm<<<dim3(VPAD / 128, SS, 1), 256, SMEM_SZ>>>(Hh, Hl, HH, BWdo_h, BWdo_l,
                                                       bdo, preds, SS * VV, (long)VV,
                                                       VV, HH);
}

// round 10
// speedup vs baseline: 1.0009x; 1.0009x over previous
#include <cuda_runtime.h>
#include <cuda_bf16.h>
#include <math.h>
#include <stdint.h>

#define BB 128
#define PP 196
#define EE 2048
#define HH 512
#define VV 10000
#define VPAD 10112
#define TT 20
#define SS 19
#define XK 3072
#define G4 2048
#define QG 2560          // q(512) + gate(2048) merged output width

typedef __nv_bfloat16 bf16;

// ---------------- device global scratch ----------------
__device__ bf16  g_imgh[(size_t)BB * PP * EE];
__device__ bf16  g_imgl[(size_t)BB * PP * EE];
__device__ float g_Ws[(size_t)BB * PP * HH];
__device__ bf16  g_BWatt_h[HH * EE],  g_BWatt_l[HH * EE];
__device__ bf16  g_BWih_h[HH * EE],   g_BWih_l[HH * EE];
__device__ bf16  g_BWic_h[HH * EE],   g_BWic_l[HH * EE];
__device__ bf16  g_Bqg_h[QG * HH],    g_Bqg_l[QG * HH];      // [U_att ; Wfb] rows=out col
__device__ bf16  g_BWcat_h[(size_t)G4 * XK], g_BWcat_l[(size_t)G4 * XK];
__device__ bf16  g_BWdo_h[(size_t)VPAD * HH], g_BWdo_l[(size_t)VPAD * HH];
__device__ bf16  g_avgh[BB * EE], g_avgl[BB * EE];
__device__ bf16  g_Xh[BB * XK],   g_Xl[BB * XK];
__device__ bf16  g_Hh[(size_t)SS * BB * HH], g_Hl[(size_t)SS * BB * HH];
__device__ float g_c[BB * HH];
// split-K partials. g_qgp doubles as h0 partials (8*BB*HH fits), g_gatesp as c0.
__device__ float g_qgp[4 * BB * QG];
__device__ float g_gatesp[8 * BB * G4];

// ---------------- helpers ----------------
__device__ __forceinline__ uint32_t s2u(const void* p) {
    uint32_t a;
    asm("{ .reg .u64 t; cvta.to.shared.u64 t, %1; cvt.u32.u64 %0, t; }" : "=r"(a) : "l"(p));
    return a;
}
__device__ __forceinline__ void cp16(uint32_t s, const void* g) {
    asm volatile("cp.async.cg.shared.global [%0], [%1], 16;" :: "r"(s), "l"(g) : "memory");
}
__device__ __forceinline__ void cp_commit() { asm volatile("cp.async.commit_group;" ::: "memory"); }
template <int N> __device__ __forceinline__ void cp_wait() {
    asm volatile("cp.async.wait_group %0;" :: "n"(N) : "memory");
}
__device__ __forceinline__ void ldsm4(uint32_t* r, uint32_t addr) {
    asm volatile("ldmatrix.sync.aligned.m8n8.x4.shared.b16 {%0,%1,%2,%3}, [%4];"
                 : "=r"(r[0]), "=r"(r[1]), "=r"(r[2]), "=r"(r[3]) : "r"(addr));
}
__device__ __forceinline__ void mma16816(float* d, const uint32_t* a, const uint32_t* b) {
    asm volatile("mma.sync.aligned.m16n8k16.row.col.f32.bf16.bf16.f32 "
                 "{%0,%1,%2,%3}, {%4,%5,%6,%7}, {%8,%9}, {%0,%1,%2,%3};"
                 : "+f"(d[0]), "+f"(d[1]), "+f"(d[2]), "+f"(d[3])
                 : "r"(a[0]), "r"(a[1]), "r"(a[2]), "r"(a[3]), "r"(b[0]), "r"(b[1]));
}
__device__ __forceinline__ float ex2f(float x) { float r; asm("ex2.approx.f32 %0,%1;" : "=f"(r) : "f"(x)); return r; }
__device__ __forceinline__ float rcpf(float x) { float r; asm("rcp.approx.f32 %0,%1;" : "=f"(r) : "f"(x)); return r; }
__device__ __forceinline__ float tanh_fast(float x) {
    float ax = fabsf(x);
    float e  = ex2f(ax * -2.8853900817779268f);
    float r  = (1.0f - e) * rcpf(1.0f + e);
    return copysignf(r, x);
}
__device__ __forceinline__ void split2(float v, bf16* ph, bf16* pl) {
    bf16 h = __float2bfloat16(v);
    *ph = h;
    *pl = __float2bfloat16(v - __bfloat162float(h));
}

// ---------------- split-bf16 HMMA GEMM, 4-stage pipeline, split-K via grid.z ----
#define TILE_B   10240
#define BUF_B    40960
#define SMEM_SZ  163840

__global__ void __launch_bounds__(256, 1)
tc_gemm(const bf16* __restrict__ Ah, const bf16* __restrict__ Al, int lda,
        const bf16* __restrict__ Bh, const bf16* __restrict__ Bl,
        const float* __restrict__ bias, float* __restrict__ C, int ldc,
        long tile_stride, int Nstore, int K)
{
    extern __shared__ char sm[];
    const int tid = threadIdx.x, lane = tid & 31, wid = tid >> 5;
    const int m0 = blockIdx.y << 7, n0 = blockIdx.x << 7;
    const int wy = wid & 1, wx = wid >> 1;
    const uint32_t sb = s2u(sm);

    const int kc = K / gridDim.z;
    const size_t kofs = (size_t)blockIdx.z * kc * 2;
    C += (size_t)blockIdx.z * gridDim.y * tile_stride + (size_t)blockIdx.y * tile_stride;

    const char* gAh = (const char*)(Ah + (size_t)m0 * lda) + kofs;
    const char* gAl = (const char*)(Al + (size_t)m0 * lda) + kofs;
    const char* gBh = (const char*)(Bh + (size_t)n0 * K) + kofs;
    const char* gBl = (const char*)(Bl + (size_t)n0 * K) + kofs;
    const size_t strA = (size_t)lda * 2, strB = (size_t)K * 2;

    const int arow = lane & 15;
    const int acol = (lane >> 4) << 4;
    const int brow = ((lane >> 4) << 3) + (lane & 7);
    const int bcol = ((lane >> 3) & 1) << 4;
    const uint32_t aoff = (uint32_t)((wy * 64 + arow) * 80 + acol);
    const uint32_t boff = (uint32_t)((wx * 32 + brow) * 80 + bcol);

    float acc[4][4][4] = {};
    const int nk = kc >> 5;

    auto issue = [&](int ch) {
        if (ch < nk) {
            const int k0b = ch << 6;
            const uint32_t s0 = sb + (ch & 3) * BUF_B;
            #pragma unroll
            for (int half = 0; half < 2; half++) {
                int u  = tid + half * 256;
                int r  = u >> 2;
                int sg = (u & 3) << 4;
                uint32_t s = s0 + r * 80 + sg;
                size_t gA = (size_t)r * strA + k0b + sg;
                size_t gB = (size_t)r * strB + k0b + sg;
                cp16(s,              gAh + gA);
                cp16(s + TILE_B,     gAl + gA);
                cp16(s + 2 * TILE_B, gBh + gB);
                cp16(s + 3 * TILE_B, gBl + gB);
            }
        }
        cp_commit();
    };

    issue(0); issue(1); issue(2);

    for (int ch = 0; ch < nk; ch++) {
        cp_wait<2>();
        __syncthreads();
        issue(ch + 3);

        const uint32_t base = sb + (ch & 3) * BUF_B;
        #pragma unroll
        for (int ks = 0; ks < 2; ks++) {
            uint32_t ah[4][4], al[4][4];
            #pragma unroll
            for (int mi = 0; mi < 4; mi++) {
                uint32_t o = aoff + mi * (16 * 80) + ks * 32;
                ldsm4(ah[mi], base + o);
                ldsm4(al[mi], base + TILE_B + o);
            }
            uint32_t bh[2][4], bl[2][4];
            #pragma unroll
            for (int nj = 0; nj < 2; nj++) {
                uint32_t o = boff + nj * (16 * 80) + ks * 32;
                ldsm4(bh[nj], base + 2 * TILE_B + o);
                ldsm4(bl[nj], base + 3 * TILE_B + o);
            }
            #pragma unroll
            for (int mi = 0; mi < 4; mi++) {
                #pragma unroll
                for (int n8 = 0; n8 < 4; n8++) {
                    const uint32_t* pbh = &bh[n8 >> 1][(n8 & 1) << 1];
                    const uint32_t* pbl = &bl[n8 >> 1][(n8 & 1) << 1];
                    mma16816(acc[mi][n8], ah[mi], pbh);
                    mma16816(acc[mi][n8], ah[mi], pbl);
                    mma16816(acc[mi][n8], al[mi], pbh);
                }
            }
        }
    }

    #pragma unroll
    for (int mi = 0; mi < 4; mi++) {
        #pragma unroll
        for (int n8 = 0; n8 < 4; n8++) {
            int rb = wy * 64 + mi * 16 + (lane >> 2);
            int nb = n0 + wx * 32 + n8 * 8 + ((lane & 3) << 1);
            #pragma unroll
            for (int g = 0; g < 2; g++) {
                int r = rb + g * 8;
                #pragma unroll
                for (int j = 0; j < 2; j++) {
                    int n = nb + j;
                    if (n < Nstore) {
                        float v = acc[mi][n8][g * 2 + j];
                        if (bias) v += bias[n];
                        C[(size_t)r * ldc + n] = v;
                    }
                }
            }
        }
    }
}

// ---------------- conversion kernels ----------------
__global__ void split_kernel(const float* __restrict__ src, bf16* __restrict__ dh,
                             bf16* __restrict__ dl, int n)
{
    int i = blockIdx.x * 256 + threadIdx.x;
    if (i < n) split2(src[i], dh + i, dl + i);
}

__global__ void tsplit_kernel(const float* __restrict__ src, bf16* __restrict__ dh,
                              bf16* __restrict__ dl, int Ksrc, int N, int dst_ld, int koff)
{
    __shared__ float t[32][33];
    const int n0 = blockIdx.x << 5, k0 = blockIdx.y << 5;
    #pragma unroll
    for (int j = 0; j < 4; j++) {
        int kk = k0 + threadIdx.y + (j << 3);
        int n  = n0 + threadIdx.x;
        t[threadIdx.y + (j << 3)][threadIdx.x] = (n < N) ? src[(size_t)kk * N + n] : 0.0f;
    }
    __syncthreads();
    #pragma unroll
    for (int j = 0; j < 4; j++) {
        int nn = n0 + threadIdx.y + (j << 3);
        int k  = k0 + threadIdx.x;
        size_t o = (size_t)nn * dst_ld + koff + k;
        split2(t[threadIdx.x][threadIdx.y + (j << 3)], dh + o, dl + o);
    }
}

// ---------------- pointwise kernels ----------------
__global__ void avg_kernel(const float* __restrict__ img,
                           bf16* __restrict__ ah, bf16* __restrict__ al)
{
    int b = blockIdx.y;
    int e = blockIdx.x * 256 + threadIdx.x;
    const float* ib = img + (size_t)b * PP * EE + e;
    float s = 0;
    #pragma unroll 4
    for (int p = 0; p < PP; p++) s += ib[(size_t)p * EE];
    split2(s * (1.0f / PP), ah + b * EE + e, al + b * EE + e);
}

__global__ void combine_init(const float* __restrict__ hp, const float* __restrict__ cp,
                             const float* __restrict__ bih, const float* __restrict__ bic,
                             const float* __restrict__ Wemb, const int* __restrict__ cap,
                             float* __restrict__ c, bf16* __restrict__ Xh, bf16* __restrict__ Xl)
{
    int i = blockIdx.x * 256 + threadIdx.x;   // B*H
    int b = i >> 9, h = i & 511;
    float sh = bih[h], sc = bic[h];
    #pragma unroll
    for (int z = 0; z < 8; z++) { sh += hp[z * BB * HH + i]; sc += cp[z * BB * HH + i]; }
    c[i] = tanhf(sc);
    size_t o = (size_t)b * XK + 2560 + h;
    split2(tanhf(sh), Xh + o, Xl + o);
    int cw = cap[b * TT + 0];
    size_t oe = (size_t)b * XK + h;
    split2(Wemb[(size_t)cw * HH + h], Xh + oe, Xl + oe);
}

// ---------------- fused attention + softmax + context + gate + X-write ----------
__global__ void __launch_bounds__(256)
att_ctx_kernel(const float* __restrict__ Ws, const float* __restrict__ qgp,
               const float* __restrict__ bU, const float* __restrict__ bfb,
               const float* __restrict__ v_att, const float* __restrict__ bv,
               const float* __restrict__ img,
               bf16* __restrict__ Xh, bf16* __restrict__ Xl,
               float* __restrict__ alpha_out)
{
    __shared__ float qs[HH], vs[HH], es[PP], gate[EE], al[PP], red[8];
    const int b = blockIdx.x, tid = threadIdx.x;
    const int lane = tid & 31, warp = tid >> 5;
    const size_t qb = (size_t)b * QG;

    for (int i = tid; i < HH; i += 256) {
        float s = bU[i];
        #pragma unroll
        for (int z = 0; z < 4; z++) s += qgp[(size_t)z * BB * QG + qb + i];
        qs[i] = s;
        vs[i] = v_att[i];
    }
    for (int e = tid; e < EE; e += 256) {
        float s = bfb[e];
        #pragma unroll
        for (int z = 0; z < 4; z++) s += qgp[(size_t)z * BB * QG + qb + HH + e];
        gate[e] = 1.0f / (1.0f + expf(-s));
    }
    __syncthreads();

    // attention scores
    const float* Wb = Ws + (size_t)b * PP * HH;
    const float bv0 = bv[0];
    for (int p = warp; p < PP; p += 8) {
        const float* row = Wb + (size_t)p * HH;
        float s = 0.0f;
        #pragma unroll
        for (int i = 0; i < HH / 32; i++) {
            int h = lane + 32 * i;
            s += vs[h] * tanh_fast(row[h] + qs[h]);
        }
        #pragma unroll
        for (int o = 16; o; o >>= 1) s += __shfl_xor_sync(0xffffffffu, s, o);
        if (lane == 0) es[p] = s + bv0;
    }
    __syncthreads();

    // softmax over P
    float m = -1e30f;
    for (int p = tid; p < PP; p += 256) m = fmaxf(m, es[p]);
    #pragma unroll
    for (int o = 16; o; o >>= 1) m = fmaxf(m, __shfl_xor_sync(0xffffffffu, m, o));
    if (lane == 0) red[warp] = m;
    __syncthreads();
    if (warp == 0) {
        float t = (lane < 8) ? red[lane] : -1e30f;
        #pragma unroll
        for (int o = 4; o; o >>= 1) t = fmaxf(t, __shfl_xor_sync(0xffffffffu, t, o));
        if (lane == 0) red[0] = t;
    }
    __syncthreads();
    m = red[0];
    __syncthreads();
    float sum = 0.0f;
    for (int p = tid; p < PP; p += 256) { float ev = expf(es[p] - m); es[p] = ev; sum += ev; }
    #pragma unroll
    for (int o = 16; o; o >>= 1) sum += __shfl_xor_sync(0xffffffffu, sum, o);
    if (lane == 0) red[warp] = sum;
    __syncthreads();
    if (warp == 0) {
        float t = (lane < 8) ? red[lane] : 0.0f;
        #pragma unroll
        for (int o = 4; o; o >>= 1) t += __shfl_xor_sync(0xffffffffu, t, o);
        if (lane == 0) red[0] = t;
    }
    __syncthreads();
    float inv = 1.0f / red[0];
    for (int p = tid; p < PP; p += 256) {
        float a = es[p] * inv;
        al[p] = a;
        alpha_out[(size_t)b * (SS * PP) + p] = a;
    }
    __syncthreads();

    // context: each thread owns cols [e0,e0+4) and [e1,e1+4)
    const float4* ib = (const float4*)(img + (size_t)b * PP * EE);
    const int e0 = tid << 2, e1 = 1024 + (tid << 2);
    float4 a0 = {0, 0, 0, 0}, a1 = {0, 0, 0, 0};
    #pragma unroll 2
    for (int p = 0; p < PP; p++) {
        float ap = al[p];
        float4 v0 = ib[(p * EE + e0) >> 2];
        float4 v1 = ib[(p * EE + e1) >> 2];
        a0.x += ap * v0.x; a0.y += ap * v0.y; a0.z += ap * v0.z; a0.w += ap * v0.w;
        a1.x += ap * v1.x; a1.y += ap * v1.y; a1.z += ap * v1.z; a1.w += ap * v1.w;
    }
    size_t xo = (size_t)b * XK + HH;
    split2(a0.x * gate[e0    ], Xh + xo + e0,     Xl + xo + e0);
    split2(a0.y * gate[e0 + 1], Xh + xo + e0 + 1, Xl + xo + e0 + 1);
    split2(a0.z * gate[e0 + 2], Xh + xo + e0 + 2, Xl + xo + e0 + 2);
    split2(a0.w * gate[e0 + 3], Xh + xo + e0 + 3, Xl + xo + e0 + 3);
    split2(a1.x * gate[e1    ], Xh + xo + e1,     Xl + xo + e1);
    split2(a1.y * gate[e1 + 1], Xh + xo + e1 + 1, Xl + xo + e1 + 1);
    split2(a1.z * gate[e1 + 2], Xh + xo + e1 + 2, Xl + xo + e1 + 2);
    split2(a1.w * gate[e1 + 3], Xh + xo + e1 + 3, Xl + xo + e1 + 3);
}

// LSTM + h history + emb for next step
__global__ void lstm_kernel(const float* __restrict__ gatesp, const float* __restrict__ bl,
                            float* __restrict__ c, bf16* __restrict__ Xh, bf16* __restrict__ Xl,
                            bf16* __restrict__ Hh, bf16* __restrict__ Hl,
                            const float* __restrict__ Wemb, const int* __restrict__ cap, int t)
{
    int i = blockIdx.x * 256 + threadIdx.x;
    int b = i >> 9, h = i & 511;
    float g[4];
    #pragma unroll
    for (int k = 0; k < 4; k++) {
        int j = k * HH + h;
        float s = bl[j];
        #pragma unroll
        for (int z = 0; z < 8; z++) s += gatesp[(size_t)z * BB * G4 + b * G4 + j];
        g[k] = s;
    }
    float ig = 1.0f / (1.0f + expf(-g[0]));
    float fg = 1.0f / (1.0f + expf(-g[1]));
    float gg = tanhf(g[2]);
    float og = 1.0f / (1.0f + expf(-g[3]));
    float cn = fg * c[i] + ig * gg;
    c[i] = cn;
    float hn = og * tanhf(cn);
    size_t o = (size_t)b * XK + 2560 + h;
    split2(hn, Xh + o, Xl + o);
    size_t oh = (size_t)(t * BB + b) * HH + h;
    split2(hn, Hh + oh, Hl + oh);
    int cw = cap[b * TT + (t + 1)];
    size_t oe = (size_t)b * XK + h;
    split2(Wemb[(size_t)cw * HH + h], Xh + oe, Xl + oe);
}

// ---------------- host launch ----------------
extern "C" void kernel_launch(void* const* d_in, const int* in_sizes, int n_in,
                              void* d_out, int out_size)
{
    const float* img   = (const float*)d_in[0];
    const int*   cap   = (const int*)  d_in[1];
    const float* U_att = (const float*)d_in[2];
    const float* bU    = (const float*)d_in[3];
    const float* W_att = (const float*)d_in[4];
    const float* bW    = (const float*)d_in[5];
    const float* v_att = (const float*)d_in[6];
    const float* bv    = (const float*)d_in[7];
    const float* Wih   = (const float*)d_in[8];
    const float* bih   = (const float*)d_in[9];
    const float* Wic   = (const float*)d_in[10];
    const float* bic   = (const float*)d_in[11];
    const float* Wfb   = (const float*)d_in[12];
    const float* bfb   = (const float*)d_in[13];
    const float* Wdo   = (const float*)d_in[14];
    const float* bdo   = (const float*)d_in[15];
    const float* Wemb  = (const float*)d_in[16];
    const float* Wl    = (const float*)d_in[17];
    const float* Ul    = (const float*)d_in[18];
    const float* bl    = (const float*)d_in[19];

    float* preds  = (float*)d_out;
    float* alphas = (float*)d_out + (size_t)BB * SS * VV;

    bf16 *imgh, *imgl, *BWatt_h, *BWatt_l, *BWih_h, *BWih_l, *BWic_h, *BWic_l;
    bf16 *Bqg_h, *Bqg_l, *BWcat_h, *BWcat_l, *BWdo_h, *BWdo_l;
    bf16 *avgh, *avgl, *Xh, *Xl, *Hh, *Hl;
    float *pWs, *pc, *pqgp, *pgatesp;
    cudaGetSymbolAddress((void**)&imgh, g_imgh);     cudaGetSymbolAddress((void**)&imgl, g_imgl);
    cudaGetSymbolAddress((void**)&BWatt_h, g_BWatt_h); cudaGetSymbolAddress((void**)&BWatt_l, g_BWatt_l);
    cudaGetSymbolAddress((void**)&BWih_h, g_BWih_h); cudaGetSymbolAddress((void**)&BWih_l, g_BWih_l);
    cudaGetSymbolAddress((void**)&BWic_h, g_BWic_h); cudaGetSymbolAddress((void**)&BWic_l, g_BWic_l);
    cudaGetSymbolAddress((void**)&Bqg_h, g_Bqg_h);   cudaGetSymbolAddress((void**)&Bqg_l, g_Bqg_l);
    cudaGetSymbolAddress((void**)&BWcat_h, g_BWcat_h); cudaGetSymbolAddress((void**)&BWcat_l, g_BWcat_l);
    cudaGetSymbolAddress((void**)&BWdo_h, g_BWdo_h); cudaGetSymbolAddress((void**)&BWdo_l, g_BWdo_l);
    cudaGetSymbolAddress((void**)&avgh, g_avgh);     cudaGetSymbolAddress((void**)&avgl, g_avgl);
    cudaGetSymbolAddress((void**)&Xh, g_Xh);         cudaGetSymbolAddress((void**)&Xl, g_Xl);
    cudaGetSymbolAddress((void**)&Hh, g_Hh);         cudaGetSymbolAddress((void**)&Hl, g_Hl);
    cudaGetSymbolAddress((void**)&pWs, g_Ws);        cudaGetSymbolAddress((void**)&pc, g_c);
    cudaGetSymbolAddress((void**)&pqgp, g_qgp);
    cudaGetSymbolAddress((void**)&pgatesp, g_gatesp);

    cudaFuncSetAttribute(tc_gemm, cudaFuncAttributeMaxDynamicSharedMemorySize, SMEM_SZ);

    // one-time conversions
    {
        int n = BB * PP * EE;
        split_kernel<<<(n + 255) / 256, 256>>>(img, imgh, imgl, n);
        dim3 blk(32, 8);
        tsplit_kernel<<<dim3(16, 64), blk>>>(W_att, BWatt_h, BWatt_l, EE, HH, EE, 0);
        tsplit_kernel<<<dim3(16, 64), blk>>>(Wih,   BWih_h,  BWih_l,  EE, HH, EE, 0);
        tsplit_kernel<<<dim3(16, 64), blk>>>(Wic,   BWic_h,  BWic_l,  EE, HH, EE, 0);
        // merged B = [U_att ; Wfb] as [2560, 512]
        tsplit_kernel<<<dim3(16, 16), blk>>>(U_att, Bqg_h, Bqg_l, HH, HH, HH, 0);
        tsplit_kernel<<<dim3(64, 16), blk>>>(Wfb,   Bqg_h + (size_t)HH * HH,
                                             Bqg_l + (size_t)HH * HH, HH, EE, HH, 0);
        tsplit_kernel<<<dim3(64, 80), blk>>>(Wl,    BWcat_h, BWcat_l, 2560, G4, XK, 0);
        tsplit_kernel<<<dim3(64, 16), blk>>>(Ul,    BWcat_h, BWcat_l, HH,   G4, XK, 2560);
        tsplit_kernel<<<dim3(VPAD / 32, 16), blk>>>(Wdo, BWdo_h, BWdo_l, HH, VV, HH, 0);
    }

    // init: avg -> h0/c0 partials (split-K x8, reuse partial buffers) -> combine
    avg_kernel<<<dim3(EE / 256, BB), 256>>>(img, avgh, avgl);
    tc_gemm<<<dim3(4, 1, 8), 256, SMEM_SZ>>>(avgh, avgl, EE, BWih_h, BWih_l,
                                             nullptr, pqgp, HH, (long)128 * HH, HH, EE);
    tc_gemm<<<dim3(4, 1, 8), 256, SMEM_SZ>>>(avgh, avgl, EE, BWic_h, BWic_l,
                                             nullptr, pgatesp, HH, (long)128 * HH, HH, EE);
    combine_init<<<(BB * HH) / 256, 256>>>(pqgp, pgatesp, bih, bic, Wemb, cap, pc, Xh, Xl);

    // W_s = img @ W_att + bW
    tc_gemm<<<dim3(4, 196, 1), 256, SMEM_SZ>>>(imgh, imgl, EE, BWatt_h, BWatt_l,
                                               bW, pWs, HH, (long)128 * HH, HH, EE);

    for (int t = 0; t < SS; t++) {
        // merged q+gate partials: [128, 2560] = h @ [U_att; Wfb]^T, split-K x4
        tc_gemm<<<dim3(QG / 128, 1, 4), 256, SMEM_SZ>>>(Xh + 2560, Xl + 2560, XK,
                                                        Bqg_h, Bqg_l, nullptr, pqgp,
                                                        QG, (long)128 * QG, QG, HH);
        // fused attention + softmax + context + gate + X write
        att_ctx_kernel<<<BB, 256>>>(pWs, pqgp, bU, bfb, v_att, bv, img,
                                    Xh, Xl, alphas + (size_t)t * PP);
        // gates partials (split-K x8)
        tc_gemm<<<dim3(16, 1, 8), 256, SMEM_SZ>>>(Xh, Xl, XK,
                                                  BWcat_h, BWcat_l, nullptr, pgatesp,
                                                  G4, (long)128 * G4, G4, XK);
        lstm_kernel<<<(BB * HH) / 256, 256>>>(pgatesp, bl, pc, Xh, Xl, Hh, Hl, Wemb, cap, t);
    }

    // batched preds for all 19 steps
    tc_gemm<<<dim3(VPAD / 128, SS, 1), 256, SMEM_SZ>>>(Hh, Hl, HH, BWdo_h, BWdo_l,
                                                       bdo, preds, SS * VV, (long)VV,
                                                       VV, HH);
}

// round 11
// speedup vs baseline: 1.2799x; 1.2788x over previous
#include <cuda_runtime.h>
#include <cuda_bf16.h>
#include <math.h>
#include <stdint.h>

#define BB 128
#define PP 196
#define EE 2048
#define HH 512
#define VV 10000
#define VPAD 10112
#define TT 20
#define SS 19
#define XK 3072
#define G4 2048
#define QG 2560          // q(512) + gate(2048) merged output width

typedef __nv_bfloat16 bf16;

// ---------------- device global scratch ----------------
__device__ bf16  g_imgh[(size_t)BB * PP * EE];
__device__ bf16  g_imgl[(size_t)BB * PP * EE];
__device__ float g_Ws[(size_t)BB * PP * HH];
__device__ bf16  g_BWatt_h[HH * EE],  g_BWatt_l[HH * EE];
__device__ bf16  g_BWih_h[HH * EE],   g_BWih_l[HH * EE];
__device__ bf16  g_BWic_h[HH * EE],   g_BWic_l[HH * EE];
__device__ bf16  g_Bqg_h[QG * HH],    g_Bqg_l[QG * HH];
__device__ bf16  g_BWcat_h[(size_t)G4 * XK], g_BWcat_l[(size_t)G4 * XK];
__device__ bf16  g_BWdo_h[(size_t)VPAD * HH], g_BWdo_l[(size_t)VPAD * HH];
__device__ bf16  g_avgh[BB * EE], g_avgl[BB * EE];
__device__ bf16  g_Xh[BB * XK],   g_Xl[BB * XK];
__device__ bf16  g_Hh[(size_t)SS * BB * HH], g_Hl[(size_t)SS * BB * HH];
__device__ float g_c[BB * HH];
__device__ float g_alpha[BB * PP];
// split-K partials. g_qgp doubles as h0 partials (4*QG=10240 >= 8*HH floats/row), g_gatesp as c0.
__device__ float g_qgp[4 * BB * QG];
__device__ float g_gatesp[8 * BB * G4];

// ---------------- helpers ----------------
__device__ __forceinline__ uint32_t s2u(const void* p) {
    uint32_t a;
    asm("{ .reg .u64 t; cvta.to.shared.u64 t, %1; cvt.u32.u64 %0, t; }" : "=r"(a) : "l"(p));
    return a;
}
__device__ __forceinline__ void cp16(uint32_t s, const void* g) {
    asm volatile("cp.async.cg.shared.global [%0], [%1], 16;" :: "r"(s), "l"(g) : "memory");
}
__device__ __forceinline__ void cp_commit() { asm volatile("cp.async.commit_group;" ::: "memory"); }
template <int N> __device__ __forceinline__ void cp_wait() {
    asm volatile("cp.async.wait_group %0;" :: "n"(N) : "memory");
}
__device__ __forceinline__ void ldsm4(uint32_t* r, uint32_t addr) {
    asm volatile("ldmatrix.sync.aligned.m8n8.x4.shared.b16 {%0,%1,%2,%3}, [%4];"
                 : "=r"(r[0]), "=r"(r[1]), "=r"(r[2]), "=r"(r[3]) : "r"(addr));
}
__device__ __forceinline__ void mma16816(float* d, const uint32_t* a, const uint32_t* b) {
    asm volatile("mma.sync.aligned.m16n8k16.row.col.f32.bf16.bf16.f32 "
                 "{%0,%1,%2,%3}, {%4,%5,%6,%7}, {%8,%9}, {%0,%1,%2,%3};"
                 : "+f"(d[0]), "+f"(d[1]), "+f"(d[2]), "+f"(d[3])
                 : "r"(a[0]), "r"(a[1]), "r"(a[2]), "r"(a[3]), "r"(b[0]), "r"(b[1]));
}
__device__ __forceinline__ float ex2f(float x) { float r; asm("ex2.approx.f32 %0,%1;" : "=f"(r) : "f"(x)); return r; }
__device__ __forceinline__ float rcpf(float x) { float r; asm("rcp.approx.f32 %0,%1;" : "=f"(r) : "f"(x)); return r; }
__device__ __forceinline__ float tanh_fast(float x) {
    float ax = fabsf(x);
    float e  = ex2f(ax * -2.8853900817779268f);
    float r  = (1.0f - e) * rcpf(1.0f + e);
    return copysignf(r, x);
}
__device__ __forceinline__ void split2(float v, bf16* ph, bf16* pl) {
    bf16 h = __float2bfloat16(v);
    *ph = h;
    *pl = __float2bfloat16(v - __bfloat162float(h));
}

// ---------------- split-bf16 HMMA GEMM, 4-stage pipeline, split-K via grid.z ----
#define TILE_B   10240
#define BUF_B    40960
#define SMEM_SZ  163840

__global__ void __launch_bounds__(256, 1)
tc_gemm(const bf16* __restrict__ Ah, const bf16* __restrict__ Al, int lda,
        const bf16* __restrict__ Bh, const bf16* __restrict__ Bl,
        const float* __restrict__ bias, float* __restrict__ C, int ldc,
        long tile_stride, int Nstore, int K)
{
    extern __shared__ char sm[];
    const int tid = threadIdx.x, lane = tid & 31, wid = tid >> 5;
    const int m0 = blockIdx.y << 7, n0 = blockIdx.x << 7;
    const int wy = wid & 1, wx = wid >> 1;
    const uint32_t sb = s2u(sm);

    const int kc = K / gridDim.z;
    const size_t kofs = (size_t)blockIdx.z * kc * 2;
    C += (size_t)blockIdx.z * gridDim.y * tile_stride + (size_t)blockIdx.y * tile_stride;

    const char* gAh = (const char*)(Ah + (size_t)m0 * lda) + kofs;
    const char* gAl = (const char*)(Al + (size_t)m0 * lda) + kofs;
    const char* gBh = (const char*)(Bh + (size_t)n0 * K) + kofs;
    const char* gBl = (const char*)(Bl + (size_t)n0 * K) + kofs;
    const size_t strA = (size_t)lda * 2, strB = (size_t)K * 2;

    const int arow = lane & 15;
    const int acol = (lane >> 4) << 4;
    const int brow = ((lane >> 4) << 3) + (lane & 7);
    const int bcol = ((lane >> 3) & 1) << 4;
    const uint32_t aoff = (uint32_t)((wy * 64 + arow) * 80 + acol);
    const uint32_t boff = (uint32_t)((wx * 32 + brow) * 80 + bcol);

    float acc[4][4][4] = {};
    const int nk = kc >> 5;

    auto issue = [&](int ch) {
        if (ch < nk) {
            const int k0b = ch << 6;
            const uint32_t s0 = sb + (ch & 3) * BUF_B;
            #pragma unroll
            for (int half = 0; half < 2; half++) {
                int u  = tid + half * 256;
                int r  = u >> 2;
                int sg = (u & 3) << 4;
                uint32_t s = s0 + r * 80 + sg;
                size_t gA = (size_t)r * strA + k0b + sg;
                size_t gB = (size_t)r * strB + k0b + sg;
                cp16(s,              gAh + gA);
                cp16(s + TILE_B,     gAl + gA);
                cp16(s + 2 * TILE_B, gBh + gB);
                cp16(s + 3 * TILE_B, gBl + gB);
            }
        }
        cp_commit();
    };

    issue(0); issue(1); issue(2);

    for (int ch = 0; ch < nk; ch++) {
        cp_wait<2>();
        __syncthreads();
        issue(ch + 3);

        const uint32_t base = sb + (ch & 3) * BUF_B;
        #pragma unroll
        for (int ks = 0; ks < 2; ks++) {
            uint32_t ah[4][4], al[4][4];
            #pragma unroll
            for (int mi = 0; mi < 4; mi++) {
                uint32_t o = aoff + mi * (16 * 80) + ks * 32;
                ldsm4(ah[mi], base + o);
                ldsm4(al[mi], base + TILE_B + o);
            }
            uint32_t bh[2][4], bl[2][4];
            #pragma unroll
            for (int nj = 0; nj < 2; nj++) {
                uint32_t o = boff + nj * (16 * 80) + ks * 32;
                ldsm4(bh[nj], base + 2 * TILE_B + o);
                ldsm4(bl[nj], base + 3 * TILE_B + o);
            }
            #pragma unroll
            for (int mi = 0; mi < 4; mi++) {
                #pragma unroll
                for (int n8 = 0; n8 < 4; n8++) {
                    const uint32_t* pbh = &bh[n8 >> 1][(n8 & 1) << 1];
                    const uint32_t* pbl = &bl[n8 >> 1][(n8 & 1) << 1];
                    mma16816(acc[mi][n8], ah[mi], pbh);
                    mma16816(acc[mi][n8], ah[mi], pbl);
                    mma16816(acc[mi][n8], al[mi], pbh);
                }
            }
        }
    }

    #pragma unroll
    for (int mi = 0; mi < 4; mi++) {
        #pragma unroll
        for (int n8 = 0; n8 < 4; n8++) {
            int rb = wy * 64 + mi * 16 + (lane >> 2);
            int nb = n0 + wx * 32 + n8 * 8 + ((lane & 3) << 1);
            #pragma unroll
            for (int g = 0; g < 2; g++) {
                int r = rb + g * 8;
                #pragma unroll
                for (int j = 0; j < 2; j++) {
                    int n = nb + j;
                    if (n < Nstore) {
                        float v = acc[mi][n8][g * 2 + j];
                        if (bias) v += bias[n];
                        C[(size_t)r * ldc + n] = v;
                    }
                }
            }
        }
    }
}

// ---------------- conversion kernels ----------------
__global__ void split_kernel(const float* __restrict__ src, bf16* __restrict__ dh,
                             bf16* __restrict__ dl, int n)
{
    int i = blockIdx.x * 256 + threadIdx.x;
    if (i < n) split2(src[i], dh + i, dl + i);
}

__global__ void tsplit_kernel(const float* __restrict__ src, bf16* __restrict__ dh,
                              bf16* __restrict__ dl, int Ksrc, int N, int dst_ld, int koff)
{
    __shared__ float t[32][33];
    const int n0 = blockIdx.x << 5, k0 = blockIdx.y << 5;
    #pragma unroll
    for (int j = 0; j < 4; j++) {
        int kk = k0 + threadIdx.y + (j << 3);
        int n  = n0 + threadIdx.x;
        t[threadIdx.y + (j << 3)][threadIdx.x] = (n < N) ? src[(size_t)kk * N + n] : 0.0f;
    }
    __syncthreads();
    #pragma unroll
    for (int j = 0; j < 4; j++) {
        int nn = n0 + threadIdx.y + (j << 3);
        int k  = k0 + threadIdx.x;
        size_t o = (size_t)nn * dst_ld + koff + k;
        split2(t[threadIdx.x][threadIdx.y + (j << 3)], dh + o, dl + o);
    }
}

// ---------------- pointwise kernels ----------------
__global__ void avg_kernel(const float* __restrict__ img,
                           bf16* __restrict__ ah, bf16* __restrict__ al)
{
    int b = blockIdx.y;
    int e = blockIdx.x * 256 + threadIdx.x;
    const float* ib = img + (size_t)b * PP * EE + e;
    float s = 0;
    #pragma unroll 4
    for (int p = 0; p < PP; p++) s += ib[(size_t)p * EE];
    split2(s * (1.0f / PP), ah + b * EE + e, al + b * EE + e);
}

__global__ void combine_init(const float* __restrict__ hp, const float* __restrict__ cp,
                             const float* __restrict__ bih, const float* __restrict__ bic,
                             const float* __restrict__ Wemb, const int* __restrict__ cap,
                             float* __restrict__ c, bf16* __restrict__ Xh, bf16* __restrict__ Xl)
{
    int i = blockIdx.x * 256 + threadIdx.x;   // B*H
    int b = i >> 9, h = i & 511;
    float sh = bih[h], sc = bic[h];
    #pragma unroll
    for (int z = 0; z < 8; z++) { sh += hp[z * BB * HH + i]; sc += cp[z * BB * HH + i]; }
    c[i] = tanhf(sc);
    size_t o = (size_t)b * XK + 2560 + h;
    split2(tanhf(sh), Xh + o, Xl + o);
    int cw = cap[b * TT + 0];
    size_t oe = (size_t)b * XK + h;
    split2(Wemb[(size_t)cw * HH + h], Xh + oe, Xl + oe);
}

// ---------------- attention (scores + softmax), 512 threads ----------------
__global__ void __launch_bounds__(512)
attention_kernel(const float* __restrict__ Ws, const float* __restrict__ qgp,
                 const float* __restrict__ bU,
                 const float* __restrict__ v_att, const float* __restrict__ bv,
                 float* __restrict__ alpha, float* __restrict__ alpha_out)
{
    __shared__ float qs[HH], vs[HH], es[PP], red[16];
    const int b = blockIdx.x, tid = threadIdx.x;
    const int lane = tid & 31, warp = tid >> 5;
    const size_t qb = (size_t)b * QG;

    for (int i = tid; i < HH; i += 512) {
        float s = bU[i];
        #pragma unroll
        for (int z = 0; z < 4; z++) s += qgp[(size_t)z * BB * QG + qb + i];
        qs[i] = s;
        vs[i] = v_att[i];
    }
    __syncthreads();

    const float* Wb = Ws + (size_t)b * PP * HH;
    const float bv0 = bv[0];
    for (int p = warp; p < PP; p += 16) {
        const float* row = Wb + (size_t)p * HH;
        float s = 0.0f;
        #pragma unroll
        for (int i = 0; i < HH / 32; i++) {
            int h = lane + 32 * i;
            s += vs[h] * tanh_fast(row[h] + qs[h]);
        }
        #pragma unroll
        for (int o = 16; o; o >>= 1) s += __shfl_xor_sync(0xffffffffu, s, o);
        if (lane == 0) es[p] = s + bv0;
    }
    __syncthreads();

    float m = -1e30f;
    for (int p = tid; p < PP; p += 512) m = fmaxf(m, es[p]);
    #pragma unroll
    for (int o = 16; o; o >>= 1) m = fmaxf(m, __shfl_xor_sync(0xffffffffu, m, o));
    if (lane == 0) red[warp] = m;
    __syncthreads();
    if (warp == 0) {
        float t = (lane < 16) ? red[lane] : -1e30f;
        #pragma unroll
        for (int o = 8; o; o >>= 1) t = fmaxf(t, __shfl_xor_sync(0xffffffffu, t, o));
        if (lane == 0) red[0] = t;
    }
    __syncthreads();
    m = red[0];
    __syncthreads();
    float sum = 0.0f;
    for (int p = tid; p < PP; p += 512) { float ev = expf(es[p] - m); es[p] = ev; sum += ev; }
    #pragma unroll
    for (int o = 16; o; o >>= 1) sum += __shfl_xor_sync(0xffffffffu, sum, o);
    if (lane == 0) red[warp] = sum;
    __syncthreads();
    if (warp == 0) {
        float t = (lane < 16) ? red[lane] : 0.0f;
        #pragma unroll
        for (int o = 8; o; o >>= 1) t += __shfl_xor_sync(0xffffffffu, t, o);
        if (lane == 0) red[0] = t;
    }
    __syncthreads();
    float inv = 1.0f / red[0];
    for (int p = tid; p < PP; p += 512) {
        float a = es[p] * inv;
        alpha[b * PP + p] = a;
        alpha_out[(size_t)b * (SS * PP) + p] = a;
    }
}

// ---------------- context (1024 CTAs) + gate-sigmoid + X-write ----------------
__global__ void context_kernel(const float* __restrict__ img, const float* __restrict__ alpha,
                               const float* __restrict__ qgp, const float* __restrict__ bfb,
                               bf16* __restrict__ Xh, bf16* __restrict__ Xl)
{
    __shared__ float al[PP];
    const int b = blockIdx.y;
    const int e = blockIdx.x * 256 + threadIdx.x;
    if (threadIdx.x < PP) al[threadIdx.x] = alpha[b * PP + threadIdx.x];
    __syncthreads();
    const float* ib = img + (size_t)b * PP * EE + e;
    float s0 = 0, s1 = 0, s2 = 0, s3 = 0;
    #pragma unroll 4
    for (int p = 0; p < PP; p += 4) {
        s0 += al[p    ] * ib[(size_t)(p    ) * EE];
        s1 += al[p + 1] * ib[(size_t)(p + 1) * EE];
        s2 += al[p + 2] * ib[(size_t)(p + 2) * EE];
        s3 += al[p + 3] * ib[(size_t)(p + 3) * EE];
    }
    float gs = bfb[e];
    #pragma unroll
    for (int z = 0; z < 4; z++) gs += qgp[(size_t)z * BB * QG + (size_t)b * QG + HH + e];
    float gate = 1.0f / (1.0f + expf(-gs));
    float v = (s0 + s1 + s2 + s3) * gate;
    size_t o = (size_t)b * XK + HH + e;
    split2(v, Xh + o, Xl + o);
}

// LSTM + h history + emb for next step
__global__ void lstm_kernel(const float* __restrict__ gatesp, const float* __restrict__ bl,
                            float* __restrict__ c, bf16* __restrict__ Xh, bf16* __restrict__ Xl,
                            bf16* __restrict__ Hh, bf16* __restrict__ Hl,
                            const float* __restrict__ Wemb, const int* __restrict__ cap, int t)
{
    int i = blockIdx.x * 256 + threadIdx.x;
    int b = i >> 9, h = i & 511;
    float g[4];
    #pragma unroll
    for (int k = 0; k < 4; k++) {
        int j = k * HH + h;
        float s = bl[j];
        #pragma unroll
        for (int z = 0; z < 8; z++) s += gatesp[(size_t)z * BB * G4 + b * G4 + j];
        g[k] = s;
    }
    float ig = 1.0f / (1.0f + expf(-g[0]));
    float fg = 1.0f / (1.0f + expf(-g[1]));
    float gg = tanhf(g[2]);
    float og = 1.0f / (1.0f + expf(-g[3]));
    float cn = fg * c[i] + ig * gg;
    c[i] = cn;
    float hn = og * tanhf(cn);
    size_t o = (size_t)b * XK + 2560 + h;
    split2(hn, Xh + o, Xl + o);
    size_t oh = (size_t)(t * BB + b) * HH + h;
    split2(hn, Hh + oh, Hl + oh);
    int cw = cap[b * TT + (t + 1)];
    size_t oe = (size_t)b * XK + h;
    split2(Wemb[(size_t)cw * HH + h], Xh + oe, Xl + oe);
}

// ---------------- host launch ----------------
extern "C" void kernel_launch(void* const* d_in, const int* in_sizes, int n_in,
                              void* d_out, int out_size)
{
    const float* img   = (const float*)d_in[0];
    const int*   cap   = (const int*)  d_in[1];
    const float* U_att = (const float*)d_in[2];
    const float* bU    = (const float*)d_in[3];
    const float* W_att = (const float*)d_in[4];
    const float* bW    = (const float*)d_in[5];
    const float* v_att = (const float*)d_in[6];
    const float* bv    = (const float*)d_in[7];
    const float* Wih   = (const float*)d_in[8];
    const float* bih   = (const float*)d_in[9];
    const float* Wic   = (const float*)d_in[10];
    const float* bic   = (const float*)d_in[11];
    const float* Wfb   = (const float*)d_in[12];
    const float* bfb   = (const float*)d_in[13];
    const float* Wdo   = (const float*)d_in[14];
    const float* bdo   = (const float*)d_in[15];
    const float* Wemb  = (const float*)d_in[16];
    const float* Wl    = (const float*)d_in[17];
    const float* Ul    = (const float*)d_in[18];
    const float* bl    = (const float*)d_in[19];

    float* preds  = (float*)d_out;
    float* alphas = (float*)d_out + (size_t)BB * SS * VV;

    bf16 *imgh, *imgl, *BWatt_h, *BWatt_l, *BWih_h, *BWih_l, *BWic_h, *BWic_l;
    bf16 *Bqg_h, *Bqg_l, *BWcat_h, *BWcat_l, *BWdo_h, *BWdo_l;
    bf16 *avgh, *avgl, *Xh, *Xl, *Hh, *Hl;
    float *pWs, *pc, *palpha, *pqgp, *pgatesp;
    cudaGetSymbolAddress((void**)&imgh, g_imgh);     cudaGetSymbolAddress((void**)&imgl, g_imgl);
    cudaGetSymbolAddress((void**)&BWatt_h, g_BWatt_h); cudaGetSymbolAddress((void**)&BWatt_l, g_BWatt_l);
    cudaGetSymbolAddress((void**)&BWih_h, g_BWih_h); cudaGetSymbolAddress((void**)&BWih_l, g_BWih_l);
    cudaGetSymbolAddress((void**)&BWic_h, g_BWic_h); cudaGetSymbolAddress((void**)&BWic_l, g_BWic_l);
    cudaGetSymbolAddress((void**)&Bqg_h, g_Bqg_h);   cudaGetSymbolAddress((void**)&Bqg_l, g_Bqg_l);
    cudaGetSymbolAddress((void**)&BWcat_h, g_BWcat_h); cudaGetSymbolAddress((void**)&BWcat_l, g_BWcat_l);
    cudaGetSymbolAddress((void**)&BWdo_h, g_BWdo_h); cudaGetSymbolAddress((void**)&BWdo_l, g_BWdo_l);
    cudaGetSymbolAddress((void**)&avgh, g_avgh);     cudaGetSymbolAddress((void**)&avgl, g_avgl);
    cudaGetSymbolAddress((void**)&Xh, g_Xh);         cudaGetSymbolAddress((void**)&Xl, g_Xl);
    cudaGetSymbolAddress((void**)&Hh, g_Hh);         cudaGetSymbolAddress((void**)&Hl, g_Hl);
    cudaGetSymbolAddress((void**)&pWs, g_Ws);        cudaGetSymbolAddress((void**)&pc, g_c);
    cudaGetSymbolAddress((void**)&palpha, g_alpha);
    cudaGetSymbolAddress((void**)&pqgp, g_qgp);
    cudaGetSymbolAddress((void**)&pgatesp, g_gatesp);

    cudaFuncSetAttribute(tc_gemm, cudaFuncAttributeMaxDynamicSharedMemorySize, SMEM_SZ);

    // one-time conversions
    {
        int n = BB * PP * EE;
        split_kernel<<<(n + 255) / 256, 256>>>(img, imgh, imgl, n);
        dim3 blk(32, 8);
        tsplit_kernel<<<dim3(16, 64), blk>>>(W_att, BWatt_h, BWatt_l, EE, HH, EE, 0);
        tsplit_kernel<<<dim3(16, 64), blk>>>(Wih,   BWih_h,  BWih_l,  EE, HH, EE, 0);
        tsplit_kernel<<<dim3(16, 64), blk>>>(Wic,   BWic_h,  BWic_l,  EE, HH, EE, 0);
        tsplit_kernel<<<dim3(16, 16), blk>>>(U_att, Bqg_h, Bqg_l, HH, HH, HH, 0);
        tsplit_kernel<<<dim3(64, 16), blk>>>(Wfb,   Bqg_h + (size_t)HH * HH,
                                             Bqg_l + (size_t)HH * HH, HH, EE, HH, 0);
        tsplit_kernel<<<dim3(64, 80), blk>>>(Wl,    BWcat_h, BWcat_l, 2560, G4, XK, 0);
        tsplit_kernel<<<dim3(64, 16), blk>>>(Ul,    BWcat_h, BWcat_l, HH,   G4, XK, 2560);
        tsplit_kernel<<<dim3(VPAD / 32, 16), blk>>>(Wdo, BWdo_h, BWdo_l, HH, VV, HH, 0);
    }

    // init: avg -> h0/c0 partials (split-K x8) -> combine (+ emb(0))
    avg_kernel<<<dim3(EE / 256, BB), 256>>>(img, avgh, avgl);
    tc_gemm<<<dim3(4, 1, 8), 256, SMEM_SZ>>>(avgh, avgl, EE, BWih_h, BWih_l,
                                             nullptr, pqgp, HH, (long)128 * HH, HH, EE);
    tc_gemm<<<dim3(4, 1, 8), 256, SMEM_SZ>>>(avgh, avgl, EE, BWic_h, BWic_l,
                                             nullptr, pgatesp, HH, (long)128 * HH, HH, EE);
    combine_init<<<(BB * HH) / 256, 256>>>(pqgp, pgatesp, bih, bic, Wemb, cap, pc, Xh, Xl);

    // W_s = img @ W_att + bW
    tc_gemm<<<dim3(4, 196, 1), 256, SMEM_SZ>>>(imgh, imgl, EE, BWatt_h, BWatt_l,
                                               bW, pWs, HH, (long)128 * HH, HH, EE);

    for (int t = 0; t < SS; t++) {
        // merged q+gate partials: [128, 2560] = h @ [U_att; Wfb]^T, split-K x4
        tc_gemm<<<dim3(QG / 128, 1, 4), 256, SMEM_SZ>>>(Xh + 2560, Xl + 2560, XK,
                                                        Bqg_h, Bqg_l, nullptr, pqgp,
                                                        QG, (long)128 * QG, QG, HH);
        attention_kernel<<<BB, 512>>>(pWs, pqgp, bU, v_att, bv, palpha,
                                      alphas + (size_t)t * PP);
        context_kernel<<<dim3(EE / 256, BB), 256>>>(img, palpha, pqgp, bfb, Xh, Xl);
        // gates partials (split-K x8)
        tc_gemm<<<dim3(16, 1, 8), 256, SMEM_SZ>>>(Xh, Xl, XK,
                                                  BWcat_h, BWcat_l, nullptr, pgatesp,
                                                  G4, (long)128 * G4, G4, XK);
        lstm_kernel<<<(BB * HH) / 256, 256>>>(pgatesp, bl, pc, Xh, Xl, Hh, Hl, Wemb, cap, t);
    }

    // batched preds for all 19 steps
    tc_gemm<<<dim3(VPAD / 128, SS, 1), 256, SMEM_SZ>>>(Hh, Hl, HH, BWdo_h, BWdo_l,
                                                       bdo, preds, SS * VV, (long)VV,
                                                       VV, HH);
}

// round 12
// speedup vs baseline: 1.2944x; 1.0113x over previous
#include <cuda_runtime.h>
#include <cuda_bf16.h>
#include <math.h>
#include <stdint.h>

#define BB 128
#define PP 196
#define EE 2048
#define HH 512
#define VV 10000
#define VPAD 10112
#define TT 20
#define SS 19
#define XK 3072
#define G4 2048
#define QG 2560          // q(512) + gate(2048) merged output width

typedef __nv_bfloat16 bf16;

// ---------------- device global scratch ----------------
__device__ bf16  g_imgh[(size_t)BB * PP * EE];
__device__ bf16  g_imgl[(size_t)BB * PP * EE];
__device__ float g_Ws[(size_t)BB * PP * HH];
__device__ bf16  g_BWatt_h[HH * EE],  g_BWatt_l[HH * EE];
__device__ bf16  g_BWih_h[HH * EE],   g_BWih_l[HH * EE];
__device__ bf16  g_BWic_h[HH * EE],   g_BWic_l[HH * EE];
__device__ bf16  g_Bqg_h[QG * HH],    g_Bqg_l[QG * HH];
__device__ bf16  g_BWcat_h[(size_t)G4 * XK], g_BWcat_l[(size_t)G4 * XK];
__device__ bf16  g_BWdo_h[(size_t)VPAD * HH], g_BWdo_l[(size_t)VPAD * HH];
__device__ bf16  g_avgh[BB * EE], g_avgl[BB * EE];
__device__ bf16  g_Xh[BB * XK],   g_Xl[BB * XK];
__device__ bf16  g_Hh[(size_t)SS * BB * HH], g_Hl[(size_t)SS * BB * HH];
__device__ float g_c[BB * HH];
__device__ float g_alpha[BB * PP];
// split-K partials. g_qgp doubles as h0 partials, g_gatesp as c0.
__device__ float g_qgp[4 * BB * QG];
__device__ float g_gatesp[8 * BB * G4];

// ---------------- helpers ----------------
__device__ __forceinline__ uint32_t s2u(const void* p) {
    uint32_t a;
    asm("{ .reg .u64 t; cvta.to.shared.u64 t, %1; cvt.u32.u64 %0, t; }" : "=r"(a) : "l"(p));
    return a;
}
__device__ __forceinline__ void cp16(uint32_t s, const void* g) {
    asm volatile("cp.async.cg.shared.global [%0], [%1], 16;" :: "r"(s), "l"(g) : "memory");
}
__device__ __forceinline__ void cp_commit() { asm volatile("cp.async.commit_group;" ::: "memory"); }
template <int N> __device__ __forceinline__ void cp_wait() {
    asm volatile("cp.async.wait_group %0;" :: "n"(N) : "memory");
}
__device__ __forceinline__ void ldsm4(uint32_t* r, uint32_t addr) {
    asm volatile("ldmatrix.sync.aligned.m8n8.x4.shared.b16 {%0,%1,%2,%3}, [%4];"
                 : "=r"(r[0]), "=r"(r[1]), "=r"(r[2]), "=r"(r[3]) : "r"(addr));
}
__device__ __forceinline__ void mma16816(float* d, const uint32_t* a, const uint32_t* b) {
    asm volatile("mma.sync.aligned.m16n8k16.row.col.f32.bf16.bf16.f32 "
                 "{%0,%1,%2,%3}, {%4,%5,%6,%7}, {%8,%9}, {%0,%1,%2,%3};"
                 : "+f"(d[0]), "+f"(d[1]), "+f"(d[2]), "+f"(d[3])
                 : "r"(a[0]), "r"(a[1]), "r"(a[2]), "r"(a[3]), "r"(b[0]), "r"(b[1]));
}
__device__ __forceinline__ float ex2f(float x) { float r; asm("ex2.approx.f32 %0,%1;" : "=f"(r) : "f"(x)); return r; }
__device__ __forceinline__ float rcpf(float x) { float r; asm("rcp.approx.f32 %0,%1;" : "=f"(r) : "f"(x)); return r; }
__device__ __forceinline__ float tanh_fast(float x) {
    float ax = fabsf(x);
    float e  = ex2f(ax * -2.8853900817779268f);
    float r  = (1.0f - e) * rcpf(1.0f + e);
    return copysignf(r, x);
}
__device__ __forceinline__ void split2(float v, bf16* ph, bf16* pl) {
    bf16 h = __float2bfloat16(v);
    *ph = h;
    *pl = __float2bfloat16(v - __bfloat162float(h));
}

// ---------------- split-bf16 HMMA GEMM, 4-stage pipeline, split-K via grid.z ----
#define TILE_B   10240
#define BUF_B    40960
#define SMEM_SZ  163840

__global__ void __launch_bounds__(256, 1)
tc_gemm(const bf16* __restrict__ Ah, const bf16* __restrict__ Al, int lda,
        const bf16* __restrict__ Bh, const bf16* __restrict__ Bl,
        const float* __restrict__ bias, float* __restrict__ C, int ldc,
        long tile_stride, int Nstore, int K)
{
    extern __shared__ char sm[];
    const int tid = threadIdx.x, lane = tid & 31, wid = tid >> 5;
    const int m0 = blockIdx.y << 7, n0 = blockIdx.x << 7;
    const int wy = wid & 1, wx = wid >> 1;
    const uint32_t sb = s2u(sm);

    const int kc = K / gridDim.z;
    const size_t kofs = (size_t)blockIdx.z * kc * 2;
    C += (size_t)blockIdx.z * gridDim.y * tile_stride + (size_t)blockIdx.y * tile_stride;

    const char* gAh = (const char*)(Ah + (size_t)m0 * lda) + kofs;
    const char* gAl = (const char*)(Al + (size_t)m0 * lda) + kofs;
    const char* gBh = (const char*)(Bh + (size_t)n0 * K) + kofs;
    const char* gBl = (const char*)(Bl + (size_t)n0 * K) + kofs;
    const size_t strA = (size_t)lda * 2, strB = (size_t)K * 2;

    const int arow = lane & 15;
    const int acol = (lane >> 4) << 4;
    const int brow = ((lane >> 4) << 3) + (lane & 7);
    const int bcol = ((lane >> 3) & 1) << 4;
    const uint32_t aoff = (uint32_t)((wy * 64 + arow) * 80 + acol);
    const uint32_t boff = (uint32_t)((wx * 32 + brow) * 80 + bcol);

    float acc[4][4][4] = {};
    const int nk = kc >> 5;

    auto issue = [&](int ch) {
        if (ch < nk) {
            const int k0b = ch << 6;
            const uint32_t s0 = sb + (ch & 3) * BUF_B;
            #pragma unroll
            for (int half = 0; half < 2; half++) {
                int u  = tid + half * 256;
                int r  = u >> 2;
                int sg = (u & 3) << 4;
                uint32_t s = s0 + r * 80 + sg;
                size_t gA = (size_t)r * strA + k0b + sg;
                size_t gB = (size_t)r * strB + k0b + sg;
                cp16(s,              gAh + gA);
                cp16(s + TILE_B,     gAl + gA);
                cp16(s + 2 * TILE_B, gBh + gB);
                cp16(s + 3 * TILE_B, gBl + gB);
            }
        }
        cp_commit();
    };

    issue(0); issue(1); issue(2);

    for (int ch = 0; ch < nk; ch++) {
        cp_wait<2>();
        __syncthreads();
        issue(ch + 3);

        const uint32_t base = sb + (ch & 3) * BUF_B;
        #pragma unroll
        for (int ks = 0; ks < 2; ks++) {
            uint32_t ah[4][4], al[4][4];
            #pragma unroll
            for (int mi = 0; mi < 4; mi++) {
                uint32_t o = aoff + mi * (16 * 80) + ks * 32;
                ldsm4(ah[mi], base + o);
                ldsm4(al[mi], base + TILE_B + o);
            }
            uint32_t bh[2][4], bl[2][4];
            #pragma unroll
            for (int nj = 0; nj < 2; nj++) {
                uint32_t o = boff + nj * (16 * 80) + ks * 32;
                ldsm4(bh[nj], base + 2 * TILE_B + o);
                ldsm4(bl[nj], base + 3 * TILE_B + o);
            }
            #pragma unroll
            for (int mi = 0; mi < 4; mi++) {
                #pragma unroll
                for (int n8 = 0; n8 < 4; n8++) {
                    const uint32_t* pbh = &bh[n8 >> 1][(n8 & 1) << 1];
                    const uint32_t* pbl = &bl[n8 >> 1][(n8 & 1) << 1];
                    mma16816(acc[mi][n8], ah[mi], pbh);
                    mma16816(acc[mi][n8], ah[mi], pbl);
                    mma16816(acc[mi][n8], al[mi], pbh);
                }
            }
        }
    }

    #pragma unroll
    for (int mi = 0; mi < 4; mi++) {
        #pragma unroll
        for (int n8 = 0; n8 < 4; n8++) {
            int rb = wy * 64 + mi * 16 + (lane >> 2);
            int nb = n0 + wx * 32 + n8 * 8 + ((lane & 3) << 1);
            #pragma unroll
            for (int g = 0; g < 2; g++) {
                int r = rb + g * 8;
                #pragma unroll
                for (int j = 0; j < 2; j++) {
                    int n = nb + j;
                    if (n < Nstore) {
                        float v = acc[mi][n8][g * 2 + j];
                        if (bias) v += bias[n];
                        C[(size_t)r * ldc + n] = v;
                    }
                }
            }
        }
    }
}

// ---------------- conversion kernels ----------------
// fused: img -> (imgh, imgl) split AND patch average -> (avgh, avgl); ONE img pass
__global__ void imgprep_kernel(const float* __restrict__ img,
                               bf16* __restrict__ imgh, bf16* __restrict__ imgl,
                               bf16* __restrict__ ah, bf16* __restrict__ al)
{
    int b = blockIdx.y;
    int e = blockIdx.x * 256 + threadIdx.x;
    const size_t base = (size_t)b * PP * EE + e;
    const float* ib = img + base;
    float s = 0;
    #pragma unroll 4
    for (int p = 0; p < PP; p++) {
        float v = ib[(size_t)p * EE];
        s += v;
        split2(v, imgh + base + (size_t)p * EE, imgl + base + (size_t)p * EE);
    }
    split2(s * (1.0f / PP), ah + b * EE + e, al + b * EE + e);
}

__global__ void tsplit_kernel(const float* __restrict__ src, bf16* __restrict__ dh,
                              bf16* __restrict__ dl, int Ksrc, int N, int dst_ld, int koff)
{
    __shared__ float t[32][33];
    const int n0 = blockIdx.x << 5, k0 = blockIdx.y << 5;
    #pragma unroll
    for (int j = 0; j < 4; j++) {
        int kk = k0 + threadIdx.y + (j << 3);
        int n  = n0 + threadIdx.x;
        t[threadIdx.y + (j << 3)][threadIdx.x] = (n < N) ? src[(size_t)kk * N + n] : 0.0f;
    }
    __syncthreads();
    #pragma unroll
    for (int j = 0; j < 4; j++) {
        int nn = n0 + threadIdx.y + (j << 3);
        int k  = k0 + threadIdx.x;
        size_t o = (size_t)nn * dst_ld + koff + k;
        split2(t[threadIdx.x][threadIdx.y + (j << 3)], dh + o, dl + o);
    }
}

// ---------------- pointwise kernels ----------------
__global__ void combine_init(const float* __restrict__ hp, const float* __restrict__ cp,
                             const float* __restrict__ bih, const float* __restrict__ bic,
                             const float* __restrict__ Wemb, const int* __restrict__ cap,
                             float* __restrict__ c, bf16* __restrict__ Xh, bf16* __restrict__ Xl)
{
    int i = blockIdx.x * 256 + threadIdx.x;   // B*H
    int b = i >> 9, h = i & 511;
    float sh = bih[h], sc = bic[h];
    #pragma unroll
    for (int z = 0; z < 8; z++) { sh += hp[z * BB * HH + i]; sc += cp[z * BB * HH + i]; }
    c[i] = tanhf(sc);
    size_t o = (size_t)b * XK + 2560 + h;
    split2(tanhf(sh), Xh + o, Xl + o);
    int cw = cap[b * TT + 0];
    size_t oe = (size_t)b * XK + h;
    split2(Wemb[(size_t)cw * HH + h], Xh + oe, Xl + oe);
}

// ---------------- attention (scores + softmax), 512 threads ----------------
__global__ void __launch_bounds__(512)
attention_kernel(const float* __restrict__ Ws, const float* __restrict__ qgp,
                 const float* __restrict__ bU,
                 const float* __restrict__ v_att, const float* __restrict__ bv,
                 float* __restrict__ alpha, float* __restrict__ alpha_out)
{
    __shared__ float qs[HH], vs[HH], es[PP], red[16];
    const int b = blockIdx.x, tid = threadIdx.x;
    const int lane = tid & 31, warp = tid >> 5;
    const size_t qb = (size_t)b * QG;

    for (int i = tid; i < HH; i += 512) {
        float s = bU[i];
        #pragma unroll
        for (int z = 0; z < 4; z++) s += qgp[(size_t)z * BB * QG + qb + i];
        qs[i] = s;
        vs[i] = v_att[i];
    }
    __syncthreads();

    const float* Wb = Ws + (size_t)b * PP * HH;
    const float bv0 = bv[0];
    for (int p = warp; p < PP; p += 16) {
        const float* row = Wb + (size_t)p * HH;
        float s = 0.0f;
        #pragma unroll
        for (int i = 0; i < HH / 32; i++) {
            int h = lane + 32 * i;
            s += vs[h] * tanh_fast(row[h] + qs[h]);
        }
        #pragma unroll
        for (int o = 16; o; o >>= 1) s += __shfl_xor_sync(0xffffffffu, s, o);
        if (lane == 0) es[p] = s + bv0;
    }
    __syncthreads();

    float m = -1e30f;
    for (int p = tid; p < PP; p += 512) m = fmaxf(m, es[p]);
    #pragma unroll
    for (int o = 16; o; o >>= 1) m = fmaxf(m, __shfl_xor_sync(0xffffffffu, m, o));
    if (lane == 0) red[warp] = m;
    __syncthreads();
    if (warp == 0) {
        float t = (lane < 16) ? red[lane] : -1e30f;
        #pragma unroll
        for (int o = 8; o; o >>= 1) t = fmaxf(t, __shfl_xor_sync(0xffffffffu, t, o));
        if (lane == 0) red[0] = t;
    }
    __syncthreads();
    m = red[0];
    __syncthreads();
    float sum = 0.0f;
    for (int p = tid; p < PP; p += 512) { float ev = expf(es[p] - m); es[p] = ev; sum += ev; }
    #pragma unroll
    for (int o = 16; o; o >>= 1) sum += __shfl_xor_sync(0xffffffffu, sum, o);
    if (lane == 0) red[warp] = sum;
    __syncthreads();
    if (warp == 0) {
        float t = (lane < 16) ? red[lane] : 0.0f;
        #pragma unroll
        for (int o = 8; o; o >>= 1) t += __shfl_xor_sync(0xffffffffu, t, o);
        if (lane == 0) red[0] = t;
    }
    __syncthreads();
    float inv = 1.0f / red[0];
    for (int p = tid; p < PP; p += 512) {
        float a = es[p] * inv;
        alpha[b * PP + p] = a;
        alpha_out[(size_t)b * (SS * PP) + p] = a;
    }
}

// ---------------- context: float4 loads, 512 CTAs, 128 thr, high MLP ----------
__global__ void __launch_bounds__(128)
context_kernel(const float4* __restrict__ img4, const float* __restrict__ alpha,
               const float* __restrict__ qgp, const float* __restrict__ bfb,
               bf16* __restrict__ Xh, bf16* __restrict__ Xl)
{
    __shared__ float al[PP];
    const int b = blockIdx.y;
    const int e4 = blockIdx.x * 128 + threadIdx.x;   // float4 index in [0,512)
    for (int p = threadIdx.x; p < PP; p += 128) al[p] = alpha[b * PP + p];
    __syncthreads();

    const float4* ib = img4 + (size_t)b * PP * (EE / 4) + e4;
    float4 a = {0, 0, 0, 0};
    #pragma unroll 4
    for (int p = 0; p < PP; p++) {
        float ap = al[p];
        float4 v = ib[(size_t)p * (EE / 4)];
        a.x += ap * v.x; a.y += ap * v.y; a.z += ap * v.z; a.w += ap * v.w;
    }

    const int e = e4 << 2;
    float4 gs = *(const float4*)(bfb + e);
    #pragma unroll
    for (int z = 0; z < 4; z++) {
        float4 gp = *(const float4*)(qgp + (size_t)z * BB * QG + (size_t)b * QG + HH + e);
        gs.x += gp.x; gs.y += gp.y; gs.z += gp.z; gs.w += gp.w;
    }
    size_t o = (size_t)b * XK + HH + e;
    split2(a.x / (1.0f + expf(-gs.x)) * 1.0f, Xh + o,     Xl + o);
    split2(a.y / (1.0f + expf(-gs.y)),        Xh + o + 1, Xl + o + 1);
    split2(a.z / (1.0f + expf(-gs.z)),        Xh + o + 2, Xl + o + 2);
    split2(a.w / (1.0f + expf(-gs.w)),        Xh + o + 3, Xl + o + 3);
}

// LSTM + h history + emb for next step
__global__ void lstm_kernel(const float* __restrict__ gatesp, const float* __restrict__ bl,
                            float* __restrict__ c, bf16* __restrict__ Xh, bf16* __restrict__ Xl,
                            bf16* __restrict__ Hh, bf16* __restrict__ Hl,
                            const float* __restrict__ Wemb, const int* __restrict__ cap, int t)
{
    int i = blockIdx.x * 256 + threadIdx.x;
    int b = i >> 9, h = i & 511;
    float g[4];
    #pragma unroll
    for (int k = 0; k < 4; k++) {
        int j = k * HH + h;
        float s = bl[j];
        #pragma unroll
        for (int z = 0; z < 8; z++) s += gatesp[(size_t)z * BB * G4 + b * G4 + j];
        g[k] = s;
    }
    float ig = 1.0f / (1.0f + expf(-g[0]));
    float fg = 1.0f / (1.0f + expf(-g[1]));
    float gg = tanhf(g[2]);
    float og = 1.0f / (1.0f + expf(-g[3]));
    float cn = fg * c[i] + ig * gg;
    c[i] = cn;
    float hn = og * tanhf(cn);
    size_t o = (size_t)b * XK + 2560 + h;
    split2(hn, Xh + o, Xl + o);
    size_t oh = (size_t)(t * BB + b) * HH + h;
    split2(hn, Hh + oh, Hl + oh);
    int cw = cap[b * TT + (t + 1)];
    size_t oe = (size_t)b * XK + h;
    split2(Wemb[(size_t)cw * HH + h], Xh + oe, Xl + oe);
}

// ---------------- host launch ----------------
extern "C" void kernel_launch(void* const* d_in, const int* in_sizes, int n_in,
                              void* d_out, int out_size)
{
    const float* img   = (const float*)d_in[0];
    const int*   cap   = (const int*)  d_in[1];
    const float* U_att = (const float*)d_in[2];
    const float* bU    = (const float*)d_in[3];
    const float* W_att = (const float*)d_in[4];
    const float* bW    = (const float*)d_in[5];
    const float* v_att = (const float*)d_in[6];
    const float* bv    = (const float*)d_in[7];
    const float* Wih   = (const float*)d_in[8];
    const float* bih   = (const float*)d_in[9];
    const float* Wic   = (const float*)d_in[10];
    const float* bic   = (const float*)d_in[11];
    const float* Wfb   = (const float*)d_in[12];
    const float* bfb   = (const float*)d_in[13];
    const float* Wdo   = (const float*)d_in[14];
    const float* bdo   = (const float*)d_in[15];
    const float* Wemb  = (const float*)d_in[16];
    const float* Wl    = (const float*)d_in[17];
    const float* Ul    = (const float*)d_in[18];
    const float* bl    = (const float*)d_in[19];

    float* preds  = (float*)d_out;
    float* alphas = (float*)d_out + (size_t)BB * SS * VV;

    bf16 *imgh, *imgl, *BWatt_h, *BWatt_l, *BWih_h, *BWih_l, *BWic_h, *BWic_l;
    bf16 *Bqg_h, *Bqg_l, *BWcat_h, *BWcat_l, *BWdo_h, *BWdo_l;
    bf16 *avgh, *avgl, *Xh, *Xl, *Hh, *Hl;
    float *pWs, *pc, *palpha, *pqgp, *pgatesp;
    cudaGetSymbolAddress((void**)&imgh, g_imgh);     cudaGetSymbolAddress((void**)&imgl, g_imgl);
    cudaGetSymbolAddress((void**)&BWatt_h, g_BWatt_h); cudaGetSymbolAddress((void**)&BWatt_l, g_BWatt_l);
    cudaGetSymbolAddress((void**)&BWih_h, g_BWih_h); cudaGetSymbolAddress((void**)&BWih_l, g_BWih_l);
    cudaGetSymbolAddress((void**)&BWic_h, g_BWic_h); cudaGetSymbolAddress((void**)&BWic_l, g_BWic_l);
    cudaGetSymbolAddress((void**)&Bqg_h, g_Bqg_h);   cudaGetSymbolAddress((void**)&Bqg_l, g_Bqg_l);
    cudaGetSymbolAddress((void**)&BWcat_h, g_BWcat_h); cudaGetSymbolAddress((void**)&BWcat_l, g_BWcat_l);
    cudaGetSymbolAddress((void**)&BWdo_h, g_BWdo_h); cudaGetSymbolAddress((void**)&BWdo_l, g_BWdo_l);
    cudaGetSymbolAddress((void**)&avgh, g_avgh);     cudaGetSymbolAddress((void**)&avgl, g_avgl);
    cudaGetSymbolAddress((void**)&Xh, g_Xh);         cudaGetSymbolAddress((void**)&Xl, g_Xl);
    cudaGetSymbolAddress((void**)&Hh, g_Hh);         cudaGetSymbolAddress((void**)&Hl, g_Hl);
    cudaGetSymbolAddress((void**)&pWs, g_Ws);        cudaGetSymbolAddress((void**)&pc, g_c);
    cudaGetSymbolAddress((void**)&palpha, g_alpha);
    cudaGetSymbolAddress((void**)&pqgp, g_qgp);
    cudaGetSymbolAddress((void**)&pgatesp, g_gatesp);

    cudaFuncSetAttribute(tc_gemm, cudaFuncAttributeMaxDynamicSharedMemorySize, SMEM_SZ);

    // one-time conversions: single img pass (split + avg), then weight transposes
    imgprep_kernel<<<dim3(EE / 256, BB), 256>>>(img, imgh, imgl, avgh, avgl);
    {
        dim3 blk(32, 8);
        tsplit_kernel<<<dim3(16, 64), blk>>>(W_att, BWatt_h, BWatt_l, EE, HH, EE, 0);
        tsplit_kernel<<<dim3(16, 64), blk>>>(Wih,   BWih_h,  BWih_l,  EE, HH, EE, 0);
        tsplit_kernel<<<dim3(16, 64), blk>>>(Wic,   BWic_h,  BWic_l,  EE, HH, EE, 0);
        tsplit_kernel<<<dim3(16, 16), blk>>>(U_att, Bqg_h, Bqg_l, HH, HH, HH, 0);
        tsplit_kernel<<<dim3(64, 16), blk>>>(Wfb,   Bqg_h + (size_t)HH * HH,
                                             Bqg_l + (size_t)HH * HH, HH, EE, HH, 0);
        tsplit_kernel<<<dim3(64, 80), blk>>>(Wl,    BWcat_h, BWcat_l, 2560, G4, XK, 0);
        tsplit_kernel<<<dim3(64, 16), blk>>>(Ul,    BWcat_h, BWcat_l, HH,   G4, XK, 2560);
        tsplit_kernel<<<dim3(VPAD / 32, 16), blk>>>(Wdo, BWdo_h, BWdo_l, HH, VV, HH, 0);
    }

    // init: h0/c0 partials (split-K x8) -> combine (+ emb(0))
    tc_gemm<<<dim3(4, 1, 8), 256, SMEM_SZ>>>(avgh, avgl, EE, BWih_h, BWih_l,
                                             nullptr, pqgp, HH, (long)128 * HH, HH, EE);
    tc_gemm<<<dim3(4, 1, 8), 256, SMEM_SZ>>>(avgh, avgl, EE, BWic_h, BWic_l,
                                             nullptr, pgatesp, HH, (long)128 * HH, HH, EE);
    combine_init<<<(BB * HH) / 256, 256>>>(pqgp, pgatesp, bih, bic, Wemb, cap, pc, Xh, Xl);

    // W_s = img @ W_att + bW
    tc_gemm<<<dim3(4, 196, 1), 256, SMEM_SZ>>>(imgh, imgl, EE, BWatt_h, BWatt_l,
                                               bW, pWs, HH, (long)128 * HH, HH, EE);

    for (int t = 0; t < SS; t++) {
        // merged q+gate partials: [128, 2560] = h @ [U_att; Wfb]^T, split-K x4
        tc_gemm<<<dim3(QG / 128, 1, 4), 256, SMEM_SZ>>>(Xh + 2560, Xl + 2560, XK,
                                                        Bqg_h, Bqg_l, nullptr, pqgp,
                                                        QG, (long)128 * QG, QG, HH);
        attention_kernel<<<BB, 512>>>(pWs, pqgp, bU, v_att, bv, palpha,
                                      alphas + (size_t)t * PP);
        context_kernel<<<dim3(4, BB), 128>>>((const float4*)img, palpha, pqgp, bfb, Xh, Xl);
        // gates partials (split-K x8)
        tc_gemm<<<dim3(16, 1, 8), 256, SMEM_SZ>>>(Xh, Xl, XK,
                                                  BWcat_h, BWcat_l, nullptr, pgatesp,
                                                  G4, (long)128 * G4, G4, XK);
        lstm_kernel<<<(BB * HH) / 256, 256>>>(pgatesp, bl, pc, Xh, Xl, Hh, Hl, Wemb, cap, t);
    }

    // batched preds for all 19 steps
    tc_gemm<<<dim3(VPAD / 128, SS, 1), 256, SMEM_SZ>>>(Hh, Hl, HH, BWdo_h, BWdo_l,
                                                       bdo, preds, SS * VV, (long)VV,
                                                       VV, HH);
}

// round 13
// speedup vs baseline: 1.3274x; 1.0255x over previous
#include <cuda_runtime.h>
#include <cuda_bf16.h>
#include <math.h>
#include <stdint.h>

#define BB 128
#define PP 196
#define EE 2048
#define HH 512
#define VV 10000
#define VPAD 10112
#define TT 20
#define SS 19
#define XK 3072
#define G4 2048
#define QG 2560          // q(512) + gate(2048) merged output width

typedef __nv_bfloat16 bf16;

// ---------------- device global scratch ----------------
__device__ bf16  g_imgh[(size_t)BB * PP * EE];
__device__ bf16  g_imgl[(size_t)BB * PP * EE];
__device__ float g_Ws[(size_t)BB * PP * HH];
__device__ bf16  g_BWatt_h[HH * EE],  g_BWatt_l[HH * EE];
__device__ bf16  g_BWih_h[HH * EE],   g_BWih_l[HH * EE];
__device__ bf16  g_BWic_h[HH * EE],   g_BWic_l[HH * EE];
__device__ bf16  g_Bqg_h[QG * HH],    g_Bqg_l[QG * HH];
__device__ bf16  g_BWcat_h[(size_t)G4 * XK], g_BWcat_l[(size_t)G4 * XK];
__device__ bf16  g_BWdo_h[(size_t)VPAD * HH], g_BWdo_l[(size_t)VPAD * HH];
__device__ bf16  g_avgh[BB * EE], g_avgl[BB * EE];
__device__ bf16  g_Xh[BB * XK],   g_Xl[BB * XK];
__device__ bf16  g_Hh[(size_t)SS * BB * HH], g_Hl[(size_t)SS * BB * HH];
__device__ float g_c[BB * HH];
__device__ float g_alpha[BB * PP];
// split-K partials. g_qgp doubles as h0 partials, g_gatesp as c0.
__device__ float g_qgp[4 * BB * QG];
__device__ float g_gatesp[8 * BB * G4];

// ---------------- helpers ----------------
__device__ __forceinline__ uint32_t s2u(const void* p) {
    uint32_t a;
    asm("{ .reg .u64 t; cvta.to.shared.u64 t, %1; cvt.u32.u64 %0, t; }" : "=r"(a) : "l"(p));
    return a;
}
__device__ __forceinline__ void cp16(uint32_t s, const void* g) {
    asm volatile("cp.async.cg.shared.global [%0], [%1], 16;" :: "r"(s), "l"(g) : "memory");
}
__device__ __forceinline__ void cp_commit() { asm volatile("cp.async.commit_group;" ::: "memory"); }
template <int N> __device__ __forceinline__ void cp_wait() {
    asm volatile("cp.async.wait_group %0;" :: "n"(N) : "memory");
}
__device__ __forceinline__ void ldsm4(uint32_t* r, uint32_t addr) {
    asm volatile("ldmatrix.sync.aligned.m8n8.x4.shared.b16 {%0,%1,%2,%3}, [%4];"
                 : "=r"(r[0]), "=r"(r[1]), "=r"(r[2]), "=r"(r[3]) : "r"(addr));
}
__device__ __forceinline__ void mma16816(float* d, const uint32_t* a, const uint32_t* b) {
    asm volatile("mma.sync.aligned.m16n8k16.row.col.f32.bf16.bf16.f32 "
                 "{%0,%1,%2,%3}, {%4,%5,%6,%7}, {%8,%9}, {%0,%1,%2,%3};"
                 : "+f"(d[0]), "+f"(d[1]), "+f"(d[2]), "+f"(d[3])
                 : "r"(a[0]), "r"(a[1]), "r"(a[2]), "r"(a[3]), "r"(b[0]), "r"(b[1]));
}
// sm_75+ hardware tanh: single MUFU op, ~2^-10.5 max abs error
__device__ __forceinline__ float tanh_hw(float x) {
    float r;
    asm("tanh.approx.f32 %0, %1;" : "=f"(r) : "f"(x));
    return r;
}
__device__ __forceinline__ void split2(float v, bf16* ph, bf16* pl) {
    bf16 h = __float2bfloat16(v);
    *ph = h;
    *pl = __float2bfloat16(v - __bfloat162float(h));
}

// ---------------- split-bf16 HMMA GEMM, 4-stage pipeline, split-K via grid.z ----
#define TILE_B   10240
#define BUF_B    40960
#define SMEM_SZ  163840

__global__ void __launch_bounds__(256, 1)
tc_gemm(const bf16* __restrict__ Ah, const bf16* __restrict__ Al, int lda,
        const bf16* __restrict__ Bh, const bf16* __restrict__ Bl,
        const float* __restrict__ bias, float* __restrict__ C, int ldc,
        long tile_stride, int Nstore, int K)
{
    extern __shared__ char sm[];
    const int tid = threadIdx.x, lane = tid & 31, wid = tid >> 5;
    const int m0 = blockIdx.y << 7, n0 = blockIdx.x << 7;
    const int wy = wid & 1, wx = wid >> 1;
    const uint32_t sb = s2u(sm);

    const int kc = K / gridDim.z;
    const size_t kofs = (size_t)blockIdx.z * kc * 2;
    C += (size_t)blockIdx.z * gridDim.y * tile_stride + (size_t)blockIdx.y * tile_stride;

    const char* gAh = (const char*)(Ah + (size_t)m0 * lda) + kofs;
    const char* gAl = (const char*)(Al + (size_t)m0 * lda) + kofs;
    const char* gBh = (const char*)(Bh + (size_t)n0 * K) + kofs;
    const char* gBl = (const char*)(Bl + (size_t)n0 * K) + kofs;
    const size_t strA = (size_t)lda * 2, strB = (size_t)K * 2;

    const int arow = lane & 15;
    const int acol = (lane >> 4) << 4;
    const int brow = ((lane >> 4) << 3) + (lane & 7);
    const int bcol = ((lane >> 3) & 1) << 4;
    const uint32_t aoff = (uint32_t)((wy * 64 + arow) * 80 + acol);
    const uint32_t boff = (uint32_t)((wx * 32 + brow) * 80 + bcol);

    float acc[4][4][4] = {};
    const int nk = kc >> 5;

    auto issue = [&](int ch) {
        if (ch < nk) {
            const int k0b = ch << 6;
            const uint32_t s0 = sb + (ch & 3) * BUF_B;
            #pragma unroll
            for (int half = 0; half < 2; half++) {
                int u  = tid + half * 256;
                int r  = u >> 2;
                int sg = (u & 3) << 4;
                uint32_t s = s0 + r * 80 + sg;
                size_t gA = (size_t)r * strA + k0b + sg;
                size_t gB = (size_t)r * strB + k0b + sg;
                cp16(s,              gAh + gA);
                cp16(s + TILE_B,     gAl + gA);
                cp16(s + 2 * TILE_B, gBh + gB);
                cp16(s + 3 * TILE_B, gBl + gB);
            }
        }
        cp_commit();
    };

    issue(0); issue(1); issue(2);

    for (int ch = 0; ch < nk; ch++) {
        cp_wait<2>();
        __syncthreads();
        issue(ch + 3);

        const uint32_t base = sb + (ch & 3) * BUF_B;
        #pragma unroll
        for (int ks = 0; ks < 2; ks++) {
            uint32_t ah[4][4], al[4][4];
            #pragma unroll
            for (int mi = 0; mi < 4; mi++) {
                uint32_t o = aoff + mi * (16 * 80) + ks * 32;
                ldsm4(ah[mi], base + o);
                ldsm4(al[mi], base + TILE_B + o);
            }
            uint32_t bh[2][4], bl[2][4];
            #pragma unroll
            for (int nj = 0; nj < 2; nj++) {
                uint32_t o = boff + nj * (16 * 80) + ks * 32;
                ldsm4(bh[nj], base + 2 * TILE_B + o);
                ldsm4(bl[nj], base + 3 * TILE_B + o);
            }
            #pragma unroll
            for (int mi = 0; mi < 4; mi++) {
                #pragma unroll
                for (int n8 = 0; n8 < 4; n8++) {
                    const uint32_t* pbh = &bh[n8 >> 1][(n8 & 1) << 1];
                    const uint32_t* pbl = &bl[n8 >> 1][(n8 & 1) << 1];
                    mma16816(acc[mi][n8], ah[mi], pbh);
                    mma16816(acc[mi][n8], ah[mi], pbl);
                    mma16816(acc[mi][n8], al[mi], pbh);
                }
            }
        }
    }

    #pragma unroll
    for (int mi = 0; mi < 4; mi++) {
        #pragma unroll
        for (int n8 = 0; n8 < 4; n8++) {
            int rb = wy * 64 + mi * 16 + (lane >> 2);
            int nb = n0 + wx * 32 + n8 * 8 + ((lane & 3) << 1);
            #pragma unroll
            for (int g = 0; g < 2; g++) {
                int r = rb + g * 8;
                #pragma unroll
                for (int j = 0; j < 2; j++) {
                    int n = nb + j;
                    if (n < Nstore) {
                        float v = acc[mi][n8][g * 2 + j];
                        if (bias) v += bias[n];
                        C[(size_t)r * ldc + n] = v;
                    }
                }
            }
        }
    }
}

// ---------------- conversion kernels ----------------
// fused: img -> (imgh, imgl) split AND patch average -> (avgh, avgl); ONE img pass
__global__ void imgprep_kernel(const float* __restrict__ img,
                               bf16* __restrict__ imgh, bf16* __restrict__ imgl,
                               bf16* __restrict__ ah, bf16* __restrict__ al)
{
    int b = blockIdx.y;
    int e = blockIdx.x * 256 + threadIdx.x;
    const size_t base = (size_t)b * PP * EE + e;
    const float* ib = img + base;
    float s = 0;
    #pragma unroll 4
    for (int p = 0; p < PP; p++) {
        float v = ib[(size_t)p * EE];
        s += v;
        split2(v, imgh + base + (size_t)p * EE, imgl + base + (size_t)p * EE);
    }
    split2(s * (1.0f / PP), ah + b * EE + e, al + b * EE + e);
}

__global__ void tsplit_kernel(const float* __restrict__ src, bf16* __restrict__ dh,
                              bf16* __restrict__ dl, int Ksrc, int N, int dst_ld, int koff)
{
    __shared__ float t[32][33];
    const int n0 = blockIdx.x << 5, k0 = blockIdx.y << 5;
    #pragma unroll
    for (int j = 0; j < 4; j++) {
        int kk = k0 + threadIdx.y + (j << 3);
        int n  = n0 + threadIdx.x;
        t[threadIdx.y + (j << 3)][threadIdx.x] = (n < N) ? src[(size_t)kk * N + n] : 0.0f;
    }
    __syncthreads();
    #pragma unroll
    for (int j = 0; j < 4; j++) {
        int nn = n0 + threadIdx.y + (j << 3);
        int k  = k0 + threadIdx.x;
        size_t o = (size_t)nn * dst_ld + koff + k;
        split2(t[threadIdx.x][threadIdx.y + (j << 3)], dh + o, dl + o);
    }
}

// ---------------- pointwise kernels ----------------
__global__ void combine_init(const float* __restrict__ hp, const float* __restrict__ cp,
                             const float* __restrict__ bih, const float* __restrict__ bic,
                             const float* __restrict__ Wemb, const int* __restrict__ cap,
                             float* __restrict__ c, bf16* __restrict__ Xh, bf16* __restrict__ Xl)
{
    int i = blockIdx.x * 256 + threadIdx.x;   // B*H
    int b = i >> 9, h = i & 511;
    float sh = bih[h], sc = bic[h];
    #pragma unroll
    for (int z = 0; z < 8; z++) { sh += hp[z * BB * HH + i]; sc += cp[z * BB * HH + i]; }
    c[i] = tanhf(sc);
    size_t o = (size_t)b * XK + 2560 + h;
    split2(tanhf(sh), Xh + o, Xl + o);
    int cw = cap[b * TT + 0];
    size_t oe = (size_t)b * XK + h;
    split2(Wemb[(size_t)cw * HH + h], Xh + oe, Xl + oe);
}

// ---------------- attention (scores + softmax), 1024 threads, hw tanh ---------
__global__ void __launch_bounds__(1024)
attention_kernel(const float* __restrict__ Ws, const float* __restrict__ qgp,
                 const float* __restrict__ bU,
                 const float* __restrict__ v_att, const float* __restrict__ bv,
                 float* __restrict__ alpha, float* __restrict__ alpha_out)
{
    __shared__ float qs[HH], vs[HH], es[PP], red[32];
    const int b = blockIdx.x, tid = threadIdx.x;
    const int lane = tid & 31, warp = tid >> 5;
    const size_t qb = (size_t)b * QG;

    for (int i = tid; i < HH; i += 1024) {
        float s = bU[i];
        #pragma unroll
        for (int z = 0; z < 4; z++) s += qgp[(size_t)z * BB * QG + qb + i];
        qs[i] = s;
        vs[i] = v_att[i];
    }
    __syncthreads();

    const float* Wb = Ws + (size_t)b * PP * HH;
    const float bv0 = bv[0];
    for (int p = warp; p < PP; p += 32) {
        const float* row = Wb + (size_t)p * HH;
        float s = 0.0f;
        #pragma unroll
        for (int i = 0; i < HH / 32; i++) {
            int h = lane + 32 * i;
            s += vs[h] * tanh_hw(row[h] + qs[h]);
        }
        #pragma unroll
        for (int o = 16; o; o >>= 1) s += __shfl_xor_sync(0xffffffffu, s, o);
        if (lane == 0) es[p] = s + bv0;
    }
    __syncthreads();

    float m = -1e30f;
    for (int p = tid; p < PP; p += 1024) m = fmaxf(m, es[p]);
    #pragma unroll
    for (int o = 16; o; o >>= 1) m = fmaxf(m, __shfl_xor_sync(0xffffffffu, m, o));
    if (lane == 0) red[warp] = m;
    __syncthreads();
    if (warp == 0) {
        float t = red[lane];
        #pragma unroll
        for (int o = 16; o; o >>= 1) t = fmaxf(t, __shfl_xor_sync(0xffffffffu, t, o));
        if (lane == 0) red[0] = t;
    }
    __syncthreads();
    m = red[0];
    __syncthreads();
    float sum = 0.0f;
    for (int p = tid; p < PP; p += 1024) { float ev = expf(es[p] - m); es[p] = ev; sum += ev; }
    #pragma unroll
    for (int o = 16; o; o >>= 1) sum += __shfl_xor_sync(0xffffffffu, sum, o);
    if (lane == 0) red[warp] = sum;
    __syncthreads();
    if (warp == 0) {
        float t = red[lane];
        #pragma unroll
        for (int o = 16; o; o >>= 1) t += __shfl_xor_sync(0xffffffffu, t, o);
        if (lane == 0) red[0] = t;
    }
    __syncthreads();
    float inv = 1.0f / red[0];
    for (int p = tid; p < PP; p += 1024) {
        float a = es[p] * inv;
        alpha[b * PP + p] = a;
        alpha_out[(size_t)b * (SS * PP) + p] = a;
    }
}

// ---------------- context: float4 loads, 512 CTAs, 128 thr ----------
__global__ void __launch_bounds__(128)
context_kernel(const float4* __restrict__ img4, const float* __restrict__ alpha,
               const float* __restrict__ qgp, const float* __restrict__ bfb,
               bf16* __restrict__ Xh, bf16* __restrict__ Xl)
{
    __shared__ float al[PP];
    const int b = blockIdx.y;
    const int e4 = blockIdx.x * 128 + threadIdx.x;   // float4 index in [0,512)
    for (int p = threadIdx.x; p < PP; p += 128) al[p] = alpha[b * PP + p];
    __syncthreads();

    const float4* ib = img4 + (size_t)b * PP * (EE / 4) + e4;
    float4 a = {0, 0, 0, 0};
    #pragma unroll 4
    for (int p = 0; p < PP; p++) {
        float ap = al[p];
        float4 v = ib[(size_t)p * (EE / 4)];
        a.x += ap * v.x; a.y += ap * v.y; a.z += ap * v.z; a.w += ap * v.w;
    }

    const int e = e4 << 2;
    float4 gs = *(const float4*)(bfb + e);
    #pragma unroll
    for (int z = 0; z < 4; z++) {
        float4 gp = *(const float4*)(qgp + (size_t)z * BB * QG + (size_t)b * QG + HH + e);
        gs.x += gp.x; gs.y += gp.y; gs.z += gp.z; gs.w += gp.w;
    }
    size_t o = (size_t)b * XK + HH + e;
    split2(a.x / (1.0f + expf(-gs.x)), Xh + o,     Xl + o);
    split2(a.y / (1.0f + expf(-gs.y)), Xh + o + 1, Xl + o + 1);
    split2(a.z / (1.0f + expf(-gs.z)), Xh + o + 2, Xl + o + 2);
    split2(a.w / (1.0f + expf(-gs.w)), Xh + o + 3, Xl + o + 3);
}

// LSTM + h history + emb for next step (accurate tanh/exp — tiny count, high sensitivity)
__global__ void lstm_kernel(const float* __restrict__ gatesp, const float* __restrict__ bl,
                            float* __restrict__ c, bf16* __restrict__ Xh, bf16* __restrict__ Xl,
                            bf16* __restrict__ Hh, bf16* __restrict__ Hl,
                            const float* __restrict__ Wemb, const int* __restrict__ cap, int t)
{
    int i = blockIdx.x * 256 + threadIdx.x;
    int b = i >> 9, h = i & 511;
    float g[4];
    #pragma unroll
    for (int k = 0; k < 4; k++) {
        int j = k * HH + h;
        float s = bl[j];
        #pragma unroll
        for (int z = 0; z < 8; z++) s += gatesp[(size_t)z * BB * G4 + b * G4 + j];
        g[k] = s;
    }
    float ig = 1.0f / (1.0f + expf(-g[0]));
    float fg = 1.0f / (1.0f + expf(-g[1]));
    float gg = tanhf(g[2]);
    float og = 1.0f / (1.0f + expf(-g[3]));
    float cn = fg * c[i] + ig * gg;
    c[i] = cn;
    float hn = og * tanhf(cn);
    size_t o = (size_t)b * XK + 2560 + h;
    split2(hn, Xh + o, Xl + o);
    size_t oh = (size_t)(t * BB + b) * HH + h;
    split2(hn, Hh + oh, Hl + oh);
    int cw = cap[b * TT + (t + 1)];
    size_t oe = (size_t)b * XK + h;
    split2(Wemb[(size_t)cw * HH + h], Xh + oe, Xl + oe);
}

// ---------------- host launch ----------------
extern "C" void kernel_launch(void* const* d_in, const int* in_sizes, int n_in,
                              void* d_out, int out_size)
{
    const float* img   = (const float*)d_in[0];
    const int*   cap   = (const int*)  d_in[1];
    const float* U_att = (const float*)d_in[2];
    const float* bU    = (const float*)d_in[3];
    const float* W_att = (const float*)d_in[4];
    const float* bW    = (const float*)d_in[5];
    const float* v_att = (const float*)d_in[6];
    const float* bv    = (const float*)d_in[7];
    const float* Wih   = (const float*)d_in[8];
    const float* bih   = (const float*)d_in[9];
    const float* Wic   = (const float*)d_in[10];
    const float* bic   = (const float*)d_in[11];
    const float* Wfb   = (const float*)d_in[12];
    const float* bfb   = (const float*)d_in[13];
    const float* Wdo   = (const float*)d_in[14];
    const float* bdo   = (const float*)d_in[15];
    const float* Wemb  = (const float*)d_in[16];
    const float* Wl    = (const float*)d_in[17];
    const float* Ul    = (const float*)d_in[18];
    const float* bl    = (const float*)d_in[19];

    float* preds  = (float*)d_out;
    float* alphas = (float*)d_out + (size_t)BB * SS * VV;

    bf16 *imgh, *imgl, *BWatt_h, *BWatt_l, *BWih_h, *BWih_l, *BWic_h, *BWic_l;
    bf16 *Bqg_h, *Bqg_l, *BWcat_h, *BWcat_l, *BWdo_h, *BWdo_l;
    bf16 *avgh, *avgl, *Xh, *Xl, *Hh, *Hl;
    float *pWs, *pc, *palpha, *pqgp, *pgatesp;
    cudaGetSymbolAddress((void**)&imgh, g_imgh);     cudaGetSymbolAddress((void**)&imgl, g_imgl);
    cudaGetSymbolAddress((void**)&BWatt_h, g_BWatt_h); cudaGetSymbolAddress((void**)&BWatt_l, g_BWatt_l);
    cudaGetSymbolAddress((void**)&BWih_h, g_BWih_h); cudaGetSymbolAddress((void**)&BWih_l, g_BWih_l);
    cudaGetSymbolAddress((void**)&BWic_h, g_BWic_h); cudaGetSymbolAddress((void**)&BWic_l, g_BWic_l);
    cudaGetSymbolAddress((void**)&Bqg_h, g_Bqg_h);   cudaGetSymbolAddress((void**)&Bqg_l, g_Bqg_l);
    cudaGetSymbolAddress((void**)&BWcat_h, g_BWcat_h); cudaGetSymbolAddress((void**)&BWcat_l, g_BWcat_l);
    cudaGetSymbolAddress((void**)&BWdo_h, g_BWdo_h); cudaGetSymbolAddress((void**)&BWdo_l, g_BWdo_l);
    cudaGetSymbolAddress((void**)&avgh, g_avgh);     cudaGetSymbolAddress((void**)&avgl, g_avgl);
    cudaGetSymbolAddress((void**)&Xh, g_Xh);         cudaGetSymbolAddress((void**)&Xl, g_Xl);
    cudaGetSymbolAddress((void**)&Hh, g_Hh);         cudaGetSymbolAddress((void**)&Hl, g_Hl);
    cudaGetSymbolAddress((void**)&pWs, g_Ws);        cudaGetSymbolAddress((void**)&pc, g_c);
    cudaGetSymbolAddress((void**)&palpha, g_alpha);
    cudaGetSymbolAddress((void**)&pqgp, g_qgp);
    cudaGetSymbolAddress((void**)&pgatesp, g_gatesp);

    cudaFuncSetAttribute(tc_gemm, cudaFuncAttributeMaxDynamicSharedMemorySize, SMEM_SZ);

    // one-time conversions: single img pass (split + avg), then weight transposes
    imgprep_kernel<<<dim3(EE / 256, BB), 256>>>(img, imgh, imgl, avgh, avgl);
    {
        dim3 blk(32, 8);
        tsplit_kernel<<<dim3(16, 64), blk>>>(W_att, BWatt_h, BWatt_l, EE, HH, EE, 0);
        tsplit_kernel<<<dim3(16, 64), blk>>>(Wih,   BWih_h,  BWih_l,  EE, HH, EE, 0);
        tsplit_kernel<<<dim3(16, 64), blk>>>(Wic,   BWic_h,  BWic_l,  EE, HH, EE, 0);
        tsplit_kernel<<<dim3(16, 16), blk>>>(U_att, Bqg_h, Bqg_l, HH, HH, HH, 0);
        tsplit_kernel<<<dim3(64, 16), blk>>>(Wfb,   Bqg_h + (size_t)HH * HH,
                                             Bqg_l + (size_t)HH * HH, HH, EE, HH, 0);
        tsplit_kernel<<<dim3(64, 80), blk>>>(Wl,    BWcat_h, BWcat_l, 2560, G4, XK, 0);
        tsplit_kernel<<<dim3(64, 16), blk>>>(Ul,    BWcat_h, BWcat_l, HH,   G4, XK, 2560);
        tsplit_kernel<<<dim3(VPAD / 32, 16), blk>>>(Wdo, BWdo_h, BWdo_l, HH, VV, HH, 0);
    }

    // init: h0/c0 partials (split-K x8) -> combine (+ emb(0))
    tc_gemm<<<dim3(4, 1, 8), 256, SMEM_SZ>>>(avgh, avgl, EE, BWih_h, BWih_l,
                                             nullptr, pqgp, HH, (long)128 * HH, HH, EE);
    tc_gemm<<<dim3(4, 1, 8), 256, SMEM_SZ>>>(avgh, avgl, EE, BWic_h, BWic_l,
                                             nullptr, pgatesp, HH, (long)128 * HH, HH, EE);
    combine_init<<<(BB * HH) / 256, 256>>>(pqgp, pgatesp, bih, bic, Wemb, cap, pc, Xh, Xl);

    // W_s = img @ W_att + bW
    tc_gemm<<<dim3(4, 196, 1), 256, SMEM_SZ>>>(imgh, imgl, EE, BWatt_h, BWatt_l,
                                               bW, pWs, HH, (long)128 * HH, HH, EE);

    for (int t = 0; t < SS; t++) {
        // merged q+gate partials: [128, 2560] = h @ [U_att; Wfb]^T, split-K x4
        tc_gemm<<<dim3(QG / 128, 1, 4), 256, SMEM_SZ>>>(Xh + 2560, Xl + 2560, XK,
                                                        Bqg_h, Bqg_l, nullptr, pqgp,
                                                        QG, (long)128 * QG, QG, HH);
        attention_kernel<<<BB, 1024>>>(pWs, pqgp, bU, v_att, bv, palpha,
                                       alphas + (size_t)t * PP);
        context_kernel<<<dim3(4, BB), 128>>>((const float4*)img, palpha, pqgp, bfb, Xh, Xl);
        // gates partials (split-K x8)
        tc_gemm<<<dim3(16, 1, 8), 256, SMEM_SZ>>>(Xh, Xl, XK,
                                                  BWcat_h, BWcat_l, nullptr, pgatesp,
                                                  G4, (long)128 * G4, G4, XK);
        lstm_kernel<<<(BB * HH) / 256, 256>>>(pgatesp, bl, pc, Xh, Xl, Hh, Hl, Wemb, cap, t);
    }

    // batched preds for all 19 steps
    tc_gemm<<<dim3(VPAD / 128, SS, 1), 256, SMEM_SZ>>>(Hh, Hl, HH, BWdo_h, BWdo_l,
                                                       bdo, preds, SS * VV, (long)VV,
                                                       VV, HH);
}

// round 14
// speedup vs baseline: 1.3332x; 1.0043x over previous
#include <cuda_runtime.h>
#include <cuda_bf16.h>
#include <math.h>
#include <stdint.h>

#define BB 128
#define PP 196
#define EE 2048
#define HH 512
#define VV 10000
#define VPAD 10112
#define TT 20
#define SS 19
#define XK 3072
#define G4 2048
#define QG 2560          // q(512) + gate(2048) merged output width
#define HC 1024          // h0(512) + c0(512) merged init output width

typedef __nv_bfloat16 bf16;

// ---------------- device global scratch ----------------
__device__ bf16  g_imgh[(size_t)BB * PP * EE];
__device__ bf16  g_imgl[(size_t)BB * PP * EE];
__device__ float g_Ws[(size_t)BB * PP * HH];
__device__ bf16  g_BWatt_h[HH * EE],  g_BWatt_l[HH * EE];
__device__ bf16  g_BWihc_h[HC * EE],  g_BWihc_l[HC * EE];   // [Wih ; Wic] merged
__device__ bf16  g_Bqg_h[QG * HH],    g_Bqg_l[QG * HH];
__device__ bf16  g_BWcat_h[(size_t)G4 * XK], g_BWcat_l[(size_t)G4 * XK];
__device__ bf16  g_BWdo_h[(size_t)VPAD * HH], g_BWdo_l[(size_t)VPAD * HH];
__device__ bf16  g_avgh[BB * EE], g_avgl[BB * EE];
__device__ bf16  g_Xh[BB * XK],   g_Xl[BB * XK];
__device__ bf16  g_Hh[(size_t)SS * BB * HH], g_Hl[(size_t)SS * BB * HH];
__device__ float g_c[BB * HH];
__device__ float g_alpha[BB * PP];
// split-K partials. g_gatesp doubles as h0/c0 partial buffer (8*BB*HC <= 8*BB*G4).
__device__ float g_qgp[4 * BB * QG];
__device__ float g_gatesp[8 * BB * G4];

// ---------------- helpers ----------------
__device__ __forceinline__ uint32_t s2u(const void* p) {
    uint32_t a;
    asm("{ .reg .u64 t; cvta.to.shared.u64 t, %1; cvt.u32.u64 %0, t; }" : "=r"(a) : "l"(p));
    return a;
}
__device__ __forceinline__ void cp16(uint32_t s, const void* g) {
    asm volatile("cp.async.cg.shared.global [%0], [%1], 16;" :: "r"(s), "l"(g) : "memory");
}
__device__ __forceinline__ void cp_commit() { asm volatile("cp.async.commit_group;" ::: "memory"); }
template <int N> __device__ __forceinline__ void cp_wait() {
    asm volatile("cp.async.wait_group %0;" :: "n"(N) : "memory");
}
__device__ __forceinline__ void ldsm4(uint32_t* r, uint32_t addr) {
    asm volatile("ldmatrix.sync.aligned.m8n8.x4.shared.b16 {%0,%1,%2,%3}, [%4];"
                 : "=r"(r[0]), "=r"(r[1]), "=r"(r[2]), "=r"(r[3]) : "r"(addr));
}
__device__ __forceinline__ void mma16816(float* d, const uint32_t* a, const uint32_t* b) {
    asm volatile("mma.sync.aligned.m16n8k16.row.col.f32.bf16.bf16.f32 "
                 "{%0,%1,%2,%3}, {%4,%5,%6,%7}, {%8,%9}, {%0,%1,%2,%3};"
                 : "+f"(d[0]), "+f"(d[1]), "+f"(d[2]), "+f"(d[3])
                 : "r"(a[0]), "r"(a[1]), "r"(a[2]), "r"(a[3]), "r"(b[0]), "r"(b[1]));
}
__device__ __forceinline__ float tanh_hw(float x) {
    float r;
    asm("tanh.approx.f32 %0, %1;" : "=f"(r) : "f"(x));
    return r;
}
__device__ __forceinline__ void split2(float v, bf16* ph, bf16* pl) {
    bf16 h = __float2bfloat16(v);
    *ph = h;
    *pl = __float2bfloat16(v - __bfloat162float(h));
}

// ---------------- split-bf16 HMMA GEMM, 4-stage pipeline, split-K via grid.z ----
#define TILE_B   10240
#define BUF_B    40960
#define SMEM_SZ  163840

__global__ void __launch_bounds__(256, 1)
tc_gemm(const bf16* __restrict__ Ah, const bf16* __restrict__ Al, int lda,
        const bf16* __restrict__ Bh, const bf16* __restrict__ Bl,
        const float* __restrict__ bias, float* __restrict__ C, int ldc,
        long tile_stride, int Nstore, int K)
{
    extern __shared__ char sm[];
    const int tid = threadIdx.x, lane = tid & 31, wid = tid >> 5;
    const int m0 = blockIdx.y << 7, n0 = blockIdx.x << 7;
    const int wy = wid & 1, wx = wid >> 1;
    const uint32_t sb = s2u(sm);

    const int kc = K / gridDim.z;
    const size_t kofs = (size_t)blockIdx.z * kc * 2;
    C += (size_t)blockIdx.z * gridDim.y * tile_stride + (size_t)blockIdx.y * tile_stride;

    const char* gAh = (const char*)(Ah + (size_t)m0 * lda) + kofs;
    const char* gAl = (const char*)(Al + (size_t)m0 * lda) + kofs;
    const char* gBh = (const char*)(Bh + (size_t)n0 * K) + kofs;
    const char* gBl = (const char*)(Bl + (size_t)n0 * K) + kofs;
    const size_t strA = (size_t)lda * 2, strB = (size_t)K * 2;

    const int arow = lane & 15;
    const int acol = (lane >> 4) << 4;
    const int brow = ((lane >> 4) << 3) + (lane & 7);
    const int bcol = ((lane >> 3) & 1) << 4;
    const uint32_t aoff = (uint32_t)((wy * 64 + arow) * 80 + acol);
    const uint32_t boff = (uint32_t)((wx * 32 + brow) * 80 + bcol);

    float acc[4][4][4] = {};
    const int nk = kc >> 5;

    auto issue = [&](int ch) {
        if (ch < nk) {
            const int k0b = ch << 6;
            const uint32_t s0 = sb + (ch & 3) * BUF_B;
            #pragma unroll
            for (int half = 0; half < 2; half++) {
                int u  = tid + half * 256;
                int r  = u >> 2;
                int sg = (u & 3) << 4;
                uint32_t s = s0 + r * 80 + sg;
                size_t gA = (size_t)r * strA + k0b + sg;
                size_t gB = (size_t)r * strB + k0b + sg;
                cp16(s,              gAh + gA);
                cp16(s + TILE_B,     gAl + gA);
                cp16(s + 2 * TILE_B, gBh + gB);
                cp16(s + 3 * TILE_B, gBl + gB);
            }
        }
        cp_commit();
    };

    issue(0); issue(1); issue(2);

    for (int ch = 0; ch < nk; ch++) {
        cp_wait<2>();
        __syncthreads();
        issue(ch + 3);

        const uint32_t base = sb + (ch & 3) * BUF_B;
        #pragma unroll
        for (int ks = 0; ks < 2; ks++) {
            uint32_t ah[4][4], al[4][4];
            #pragma unroll
            for (int mi = 0; mi < 4; mi++) {
                uint32_t o = aoff + mi * (16 * 80) + ks * 32;
                ldsm4(ah[mi], base + o);
                ldsm4(al[mi], base + TILE_B + o);
            }
            uint32_t bh[2][4], bl[2][4];
            #pragma unroll
            for (int nj = 0; nj < 2; nj++) {
                uint32_t o = boff + nj * (16 * 80) + ks * 32;
                ldsm4(bh[nj], base + 2 * TILE_B + o);
                ldsm4(bl[nj], base + 3 * TILE_B + o);
            }
            #pragma unroll
            for (int mi = 0; mi < 4; mi++) {
                #pragma unroll
                for (int n8 = 0; n8 < 4; n8++) {
                    const uint32_t* pbh = &bh[n8 >> 1][(n8 & 1) << 1];
                    const uint32_t* pbl = &bl[n8 >> 1][(n8 & 1) << 1];
                    mma16816(acc[mi][n8], ah[mi], pbh);
                    mma16816(acc[mi][n8], ah[mi], pbl);
                    mma16816(acc[mi][n8], al[mi], pbh);
                }
            }
        }
    }

    #pragma unroll
    for (int mi = 0; mi < 4; mi++) {
        #pragma unroll
        for (int n8 = 0; n8 < 4; n8++) {
            int rb = wy * 64 + mi * 16 + (lane >> 2);
            int nb = n0 + wx * 32 + n8 * 8 + ((lane & 3) << 1);
            #pragma unroll
            for (int g = 0; g < 2; g++) {
                int r = rb + g * 8;
                #pragma unroll
                for (int j = 0; j < 2; j++) {
                    int n = nb + j;
                    if (n < Nstore) {
                        float v = acc[mi][n8][g * 2 + j];
                        if (bias) v += bias[n];
                        C[(size_t)r * ldc + n] = v;
                    }
                }
            }
        }
    }
}

// ---------------- conversion kernels ----------------
__global__ void imgprep_kernel(const float* __restrict__ img,
                               bf16* __restrict__ imgh, bf16* __restrict__ imgl,
                               bf16* __restrict__ ah, bf16* __restrict__ al)
{
    int b = blockIdx.y;
    int e = blockIdx.x * 256 + threadIdx.x;
    const size_t base = (size_t)b * PP * EE + e;
    const float* ib = img + base;
    float s = 0;
    #pragma unroll 4
    for (int p = 0; p < PP; p++) {
        float v = ib[(size_t)p * EE];
        s += v;
        split2(v, imgh + base + (size_t)p * EE, imgl + base + (size_t)p * EE);
    }
    split2(s * (1.0f / PP), ah + b * EE + e, al + b * EE + e);
}

__global__ void tsplit_kernel(const float* __restrict__ src, bf16* __restrict__ dh,
                              bf16* __restrict__ dl, int Ksrc, int N, int dst_ld, int koff)
{
    __shared__ float t[32][33];
    const int n0 = blockIdx.x << 5, k0 = blockIdx.y << 5;
    #pragma unroll
    for (int j = 0; j < 4; j++) {
        int kk = k0 + threadIdx.y + (j << 3);
        int n  = n0 + threadIdx.x;
        t[threadIdx.y + (j << 3)][threadIdx.x] = (n < N) ? src[(size_t)kk * N + n] : 0.0f;
    }
    __syncthreads();
    #pragma unroll
    for (int j = 0; j < 4; j++) {
        int nn = n0 + threadIdx.y + (j << 3);
        int k  = k0 + threadIdx.x;
        size_t o = (size_t)nn * dst_ld + koff + k;
        split2(t[threadIdx.x][threadIdx.y + (j << 3)], dh + o, dl + o);
    }
}

// ---------------- pointwise kernels ----------------
// sum 8 partials of merged [h0|c0] GEMM, tanh, write c + X h-slice + emb(0)
__global__ void combine_init(const float* __restrict__ hcp,
                             const float* __restrict__ bih, const float* __restrict__ bic,
                             const float* __restrict__ Wemb, const int* __restrict__ cap,
                             float* __restrict__ c, bf16* __restrict__ Xh, bf16* __restrict__ Xl)
{
    int i = blockIdx.x * 256 + threadIdx.x;   // B*H
    int b = i >> 9, h = i & 511;
    float sh = bih[h], sc = bic[h];
    #pragma unroll
    for (int z = 0; z < 8; z++) {
        sh += hcp[(size_t)z * BB * HC + b * HC + h];
        sc += hcp[(size_t)z * BB * HC + b * HC + HH + h];
    }
    c[i] = tanhf(sc);
    size_t o = (size_t)b * XK + 2560 + h;
    split2(tanhf(sh), Xh + o, Xl + o);
    int cw = cap[b * TT + 0];
    size_t oe = (size_t)b * XK + h;
    split2(Wemb[(size_t)cw * HH + h], Xh + oe, Xl + oe);
}

// ---------------- attention (scores + softmax), 1024 threads, hw tanh ---------
__global__ void __launch_bounds__(1024)
attention_kernel(const float* __restrict__ Ws, const float* __restrict__ qgp,
                 const float* __restrict__ bU,
                 const float* __restrict__ v_att, const float* __restrict__ bv,
                 float* __restrict__ alpha, float* __restrict__ alpha_out)
{
    __shared__ float qs[HH], vs[HH], es[PP], red[32];
    const int b = blockIdx.x, tid = threadIdx.x;
    const int lane = tid & 31, warp = tid >> 5;
    const size_t qb = (size_t)b * QG;

    for (int i = tid; i < HH; i += 1024) {
        float s = bU[i];
        #pragma unroll
        for (int z = 0; z < 4; z++) s += qgp[(size_t)z * BB * QG + qb + i];
        qs[i] = s;
        vs[i] = v_att[i];
    }
    __syncthreads();

    const float* Wb = Ws + (size_t)b * PP * HH;
    const float bv0 = bv[0];
    for (int p = warp; p < PP; p += 32) {
        const float* row = Wb + (size_t)p * HH;
        float s = 0.0f;
        #pragma unroll
        for (int i = 0; i < HH / 32; i++) {
            int h = lane + 32 * i;
            s += vs[h] * tanh_hw(row[h] + qs[h]);
        }
        #pragma unroll
        for (int o = 16; o; o >>= 1) s += __shfl_xor_sync(0xffffffffu, s, o);
        if (lane == 0) es[p] = s + bv0;
    }
    __syncthreads();

    float m = -1e30f;
    for (int p = tid; p < PP; p += 1024) m = fmaxf(m, es[p]);
    #pragma unroll
    for (int o = 16; o; o >>= 1) m = fmaxf(m, __shfl_xor_sync(0xffffffffu, m, o));
    if (lane == 0) red[warp] = m;
    __syncthreads();
    if (warp == 0) {
        float t = red[lane];
        #pragma unroll
        for (int o = 16; o; o >>= 1) t = fmaxf(t, __shfl_xor_sync(0xffffffffu, t, o));
        if (lane == 0) red[0] = t;
    }
    __syncthreads();
    m = red[0];
    __syncthreads();
    float sum = 0.0f;
    for (int p = tid; p < PP; p += 1024) { float ev = expf(es[p] - m); es[p] = ev; sum += ev; }
    #pragma unroll
    for (int o = 16; o; o >>= 1) sum += __shfl_xor_sync(0xffffffffu, sum, o);
    if (lane == 0) red[warp] = sum;
    __syncthreads();
    if (warp == 0) {
        float t = red[lane];
        #pragma unroll
        for (int o = 16; o; o >>= 1) t += __shfl_xor_sync(0xffffffffu, t, o);
        if (lane == 0) red[0] = t;
    }
    __syncthreads();
    float inv = 1.0f / red[0];
    for (int p = tid; p < PP; p += 1024) {
        float a = es[p] * inv;
        alpha[b * PP + p] = a;
        alpha_out[(size_t)b * (SS * PP) + p] = a;
    }
}

// ---------------- context: float4 loads, 512 CTAs, 128 thr ----------
__global__ void __launch_bounds__(128)
context_kernel(const float4* __restrict__ img4, const float* __restrict__ alpha,
               const float* __restrict__ qgp, const float* __restrict__ bfb,
               bf16* __restrict__ Xh, bf16* __restrict__ Xl)
{
    __shared__ float al[PP];
    const int b = blockIdx.y;
    const int e4 = blockIdx.x * 128 + threadIdx.x;
    for (int p = threadIdx.x; p < PP; p += 128) al[p] = alpha[b * PP + p];
    __syncthreads();

    const float4* ib = img4 + (size_t)b * PP * (EE / 4) + e4;
    float4 a = {0, 0, 0, 0};
    #pragma unroll 4
    for (int p = 0; p < PP; p++) {
        float ap = al[p];
        float4 v = ib[(size_t)p * (EE / 4)];
        a.x += ap * v.x; a.y += ap * v.y; a.z += ap * v.z; a.w += ap * v.w;
    }

    const int e = e4 << 2;
    float4 gs = *(const float4*)(bfb + e);
    #pragma unroll
    for (int z = 0; z < 4; z++) {
        float4 gp = *(const float4*)(qgp + (size_t)z * BB * QG + (size_t)b * QG + HH + e);
        gs.x += gp.x; gs.y += gp.y; gs.z += gp.z; gs.w += gp.w;
    }
    size_t o = (size_t)b * XK + HH + e;
    split2(a.x / (1.0f + expf(-gs.x)), Xh + o,     Xl + o);
    split2(a.y / (1.0f + expf(-gs.y)), Xh + o + 1, Xl + o + 1);
    split2(a.z / (1.0f + expf(-gs.z)), Xh + o + 2, Xl + o + 2);
    split2(a.w / (1.0f + expf(-gs.w)), Xh + o + 3, Xl + o + 3);
}

// LSTM + h history + emb for next step
__global__ void lstm_kernel(const float* __restrict__ gatesp, const float* __restrict__ bl,
                            float* __restrict__ c, bf16* __restrict__ Xh, bf16* __restrict__ Xl,
                            bf16* __restrict__ Hh, bf16* __restrict__ Hl,
                            const float* __restrict__ Wemb, const int* __restrict__ cap, int t)
{
    int i = blockIdx.x * 256 + threadIdx.x;
    int b = i >> 9, h = i & 511;
    float g[4];
    #pragma unroll
    for (int k = 0; k < 4; k++) {
        int j = k * HH + h;
        float s = bl[j];
        #pragma unroll
        for (int z = 0; z < 8; z++) s += gatesp[(size_t)z * BB * G4 + b * G4 + j];
        g[k] = s;
    }
    float ig = 1.0f / (1.0f + expf(-g[0]));
    float fg = 1.0f / (1.0f + expf(-g[1]));
    float gg = tanhf(g[2]);
    float og = 1.0f / (1.0f + expf(-g[3]));
    float cn = fg * c[i] + ig * gg;
    c[i] = cn;
    float hn = og * tanhf(cn);
    size_t o = (size_t)b * XK + 2560 + h;
    split2(hn, Xh + o, Xl + o);
    size_t oh = (size_t)(t * BB + b) * HH + h;
    split2(hn, Hh + oh, Hl + oh);
    int cw = cap[b * TT + (t + 1)];
    size_t oe = (size_t)b * XK + h;
    split2(Wemb[(size_t)cw * HH + h], Xh + oe, Xl + oe);
}

// ---------------- host launch ----------------
extern "C" void kernel_launch(void* const* d_in, const int* in_sizes, int n_in,
                              void* d_out, int out_size)
{
    const float* img   = (const float*)d_in[0];
    const int*   cap   = (const int*)  d_in[1];
    const float* U_att = (const float*)d_in[2];
    const float* bU    = (const float*)d_in[3];
    const float* W_att = (const float*)d_in[4];
    const float* bW    = (const float*)d_in[5];
    const float* v_att = (const float*)d_in[6];
    const float* bv    = (const float*)d_in[7];
    const float* Wih   = (const float*)d_in[8];
    const float* bih   = (const float*)d_in[9];
    const float* Wic   = (const float*)d_in[10];
    const float* bic   = (const float*)d_in[11];
    const float* Wfb   = (const float*)d_in[12];
    const float* bfb   = (const float*)d_in[13];
    const float* Wdo   = (const float*)d_in[14];
    const float* bdo   = (const float*)d_in[15];
    const float* Wemb  = (const float*)d_in[16];
    const float* Wl    = (const float*)d_in[17];
    const float* Ul    = (const float*)d_in[18];
    const float* bl    = (const float*)d_in[19];

    float* preds  = (float*)d_out;
    float* alphas = (float*)d_out + (size_t)BB * SS * VV;

    bf16 *imgh, *imgl, *BWatt_h, *BWatt_l, *BWihc_h, *BWihc_l;
    bf16 *Bqg_h, *Bqg_l, *BWcat_h, *BWcat_l, *BWdo_h, *BWdo_l;
    bf16 *avgh, *avgl, *Xh, *Xl, *Hh, *Hl;
    float *pWs, *pc, *palpha, *pqgp, *pgatesp;
    cudaGetSymbolAddress((void**)&imgh, g_imgh);     cudaGetSymbolAddress((void**)&imgl, g_imgl);
    cudaGetSymbolAddress((void**)&BWatt_h, g_BWatt_h); cudaGetSymbolAddress((void**)&BWatt_l, g_BWatt_l);
    cudaGetSymbolAddress((void**)&BWihc_h, g_BWihc_h); cudaGetSymbolAddress((void**)&BWihc_l, g_BWihc_l);
    cudaGetSymbolAddress((void**)&Bqg_h, g_Bqg_h);   cudaGetSymbolAddress((void**)&Bqg_l, g_Bqg_l);
    cudaGetSymbolAddress((void**)&BWcat_h, g_BWcat_h); cudaGetSymbolAddress((void**)&BWcat_l, g_BWcat_l);
    cudaGetSymbolAddress((void**)&BWdo_h, g_BWdo_h); cudaGetSymbolAddress((void**)&BWdo_l, g_BWdo_l);
    cudaGetSymbolAddress((void**)&avgh, g_avgh);     cudaGetSymbolAddress((void**)&avgl, g_avgl);
    cudaGetSymbolAddress((void**)&Xh, g_Xh);         cudaGetSymbolAddress((void**)&Xl, g_Xl);
    cudaGetSymbolAddress((void**)&Hh, g_Hh);         cudaGetSymbolAddress((void**)&Hl, g_Hl);
    cudaGetSymbolAddress((void**)&pWs, g_Ws);        cudaGetSymbolAddress((void**)&pc, g_c);
    cudaGetSymbolAddress((void**)&palpha, g_alpha);
    cudaGetSymbolAddress((void**)&pqgp, g_qgp);
    cudaGetSymbolAddress((void**)&pgatesp, g_gatesp);

    cudaFuncSetAttribute(tc_gemm, cudaFuncAttributeMaxDynamicSharedMemorySize, SMEM_SZ);

    // forked stream + events (created per call; host-side only, few calls total)
    cudaStream_t s2;
    cudaStreamCreateWithFlags(&s2, cudaStreamNonBlocking);
    cudaEvent_t evFork, evTsplit, evImg, evInit, evDone;
    cudaEvent_t evStep[SS];
    cudaEventCreateWithFlags(&evFork, cudaEventDisableTiming);
    cudaEventCreateWithFlags(&evTsplit, cudaEventDisableTiming);
    cudaEventCreateWithFlags(&evImg, cudaEventDisableTiming);
    cudaEventCreateWithFlags(&evInit, cudaEventDisableTiming);
    cudaEventCreateWithFlags(&evDone, cudaEventDisableTiming);
    for (int t = 0; t < SS; t++) cudaEventCreateWithFlags(&evStep[t], cudaEventDisableTiming);

    // fork s2 from main
    cudaEventRecord(evFork, 0);
    cudaStreamWaitEvent(s2, evFork, 0);

    // s2: all weight transposes
    {
        dim3 blk(32, 8);
        tsplit_kernel<<<dim3(16, 64), blk, 0, s2>>>(W_att, BWatt_h, BWatt_l, EE, HH, EE, 0);
        tsplit_kernel<<<dim3(16, 64), blk, 0, s2>>>(Wih, BWihc_h, BWihc_l, EE, HH, EE, 0);
        tsplit_kernel<<<dim3(16, 64), blk, 0, s2>>>(Wic, BWihc_h + (size_t)HH * EE,
                                                    BWihc_l + (size_t)HH * EE, EE, HH, EE, 0);
        tsplit_kernel<<<dim3(16, 16), blk, 0, s2>>>(U_att, Bqg_h, Bqg_l, HH, HH, HH, 0);
        tsplit_kernel<<<dim3(64, 16), blk, 0, s2>>>(Wfb, Bqg_h + (size_t)HH * HH,
                                                    Bqg_l + (size_t)HH * HH, HH, EE, HH, 0);
        tsplit_kernel<<<dim3(64, 80), blk, 0, s2>>>(Wl, BWcat_h, BWcat_l, 2560, G4, XK, 0);
        tsplit_kernel<<<dim3(64, 16), blk, 0, s2>>>(Ul, BWcat_h, BWcat_l, HH, G4, XK, 2560);
        tsplit_kernel<<<dim3(VPAD / 32, 16), blk, 0, s2>>>(Wdo, BWdo_h, BWdo_l, HH, VV, HH, 0);
        cudaEventRecord(evTsplit, s2);
    }

    // main: img split + avg (overlaps tsplits)
    imgprep_kernel<<<dim3(EE / 256, BB), 256>>>(img, imgh, imgl, avgh, avgl);
    cudaEventRecord(evImg, 0);

    // s2: merged h0|c0 GEMM (needs avg + BWihc) then combine; overlaps W_s on main
    cudaStreamWaitEvent(s2, evImg, 0);
    tc_gemm<<<dim3(HC / 128, 1, 8), 256, SMEM_SZ, s2>>>(avgh, avgl, EE, BWihc_h, BWihc_l,
                                                        nullptr, pgatesp, HC,
                                                        (long)128 * HC, HC, EE);
    combine_init<<<(BB * HH) / 256, 256, 0, s2>>>(pgatesp, bih, bic, Wemb, cap, pc, Xh, Xl);
    cudaEventRecord(evInit, s2);

    // main: W_s = img @ W_att + bW (needs imgh + BWatt)
    cudaStreamWaitEvent(0, evTsplit, 0);
    tc_gemm<<<dim3(4, 196, 1), 256, SMEM_SZ>>>(imgh, imgl, EE, BWatt_h, BWatt_l,
                                               bW, pWs, HH, (long)128 * HH, HH, EE);
    cudaStreamWaitEvent(0, evInit, 0);

    for (int t = 0; t < SS; t++) {
        tc_gemm<<<dim3(QG / 128, 1, 4), 256, SMEM_SZ>>>(Xh + 2560, Xl + 2560, XK,
                                                        Bqg_h, Bqg_l, nullptr, pqgp,
                                                        QG, (long)128 * QG, QG, HH);
        attention_kernel<<<BB, 1024>>>(pWs, pqgp, bU, v_att, bv, palpha,
                                       alphas + (size_t)t * PP);
        context_kernel<<<dim3(4, BB), 128>>>((const float4*)img, palpha, pqgp, bfb, Xh, Xl);
        tc_gemm<<<dim3(16, 1, 8), 256, SMEM_SZ>>>(Xh, Xl, XK,
                                                  BWcat_h, BWcat_l, nullptr, pgatesp,
                                                  G4, (long)128 * G4, G4, XK);
        lstm_kernel<<<(BB * HH) / 256, 256>>>(pgatesp, bl, pc, Xh, Xl, Hh, Hl, Wemb, cap, t);
        // pipeline this step's preds GEMM onto s2 (overlaps next step's work)
        cudaEventRecord(evStep[t], 0);
        cudaStreamWaitEvent(s2, evStep[t], 0);
        tc_gemm<<<dim3(VPAD / 128, 1, 1), 256, SMEM_SZ, s2>>>(
            Hh + (size_t)t * BB * HH, Hl + (size_t)t * BB * HH, HH,
            BWdo_h, BWdo_l, bdo, preds + (size_t)t * VV, SS * VV, 0L, VV, HH);
    }

    // join s2 back into main before capture ends
    cudaEventRecord(evDone, s2);
    cudaStreamWaitEvent(0, evDone, 0);
}

// round 15
// speedup vs baseline: 1.3675x; 1.0257x over previous
#include <cuda_runtime.h>
#include <cuda_bf16.h>
#include <cuda_fp16.h>
#include <math.h>
#include <stdint.h>

#define BB 128
#define PP 196
#define EE 2048
#define HH 512
#define VV 10000
#define VPAD 10112
#define TT 20
#define SS 19
#define XK 3072
#define G4 2048
#define QG 2560          // q(512) + gate(2048) merged output width
#define HC 1024          // h0(512) + c0(512) merged init output width

typedef __nv_bfloat16 bf16;

// ---------------- device global scratch ----------------
__device__ bf16   g_imgh[(size_t)BB * PP * EE];
__device__ bf16   g_imgl[(size_t)BB * PP * EE];
__device__ __half g_img16[(size_t)BB * PP * EE];     // fp16 img for ctx MMA
__device__ float  g_Ws[(size_t)BB * PP * HH];
__device__ bf16   g_BWatt_h[HH * EE],  g_BWatt_l[HH * EE];
__device__ bf16   g_BWihc_h[HC * EE],  g_BWihc_l[HC * EE];   // [Wih ; Wic]
__device__ bf16   g_Bqg_h[QG * HH],    g_Bqg_l[QG * HH];
__device__ bf16   g_BWcat_h[(size_t)G4 * XK], g_BWcat_l[(size_t)G4 * XK];
__device__ bf16   g_BWdo_h[(size_t)VPAD * HH], g_BWdo_l[(size_t)VPAD * HH];
__device__ bf16   g_avgh[BB * EE], g_avgl[BB * EE];
__device__ bf16   g_Xh[BB * XK],   g_Xl[BB * XK];
__device__ bf16   g_Hh[(size_t)SS * BB * HH], g_Hl[(size_t)SS * BB * HH];
__device__ float  g_c[BB * HH];
__device__ float  g_alpha[BB * PP];
__device__ float  g_qgp[4 * BB * QG];
__device__ float  g_gatesp[8 * BB * G4];

// ---------------- helpers ----------------
__device__ __forceinline__ uint32_t s2u(const void* p) {
    uint32_t a;
    asm("{ .reg .u64 t; cvta.to.shared.u64 t, %1; cvt.u32.u64 %0, t; }" : "=r"(a) : "l"(p));
    return a;
}
__device__ __forceinline__ void cp16(uint32_t s, const void* g) {
    asm volatile("cp.async.cg.shared.global [%0], [%1], 16;" :: "r"(s), "l"(g) : "memory");
}
__device__ __forceinline__ void cp_commit() { asm volatile("cp.async.commit_group;" ::: "memory"); }
template <int N> __device__ __forceinline__ void cp_wait() {
    asm volatile("cp.async.wait_group %0;" :: "n"(N) : "memory");
}
__device__ __forceinline__ void ldsm4(uint32_t* r, uint32_t addr) {
    asm volatile("ldmatrix.sync.aligned.m8n8.x4.shared.b16 {%0,%1,%2,%3}, [%4];"
                 : "=r"(r[0]), "=r"(r[1]), "=r"(r[2]), "=r"(r[3]) : "r"(addr));
}
__device__ __forceinline__ void ldsm2t(uint32_t* r, uint32_t addr) {
    asm volatile("ldmatrix.sync.aligned.m8n8.x2.trans.shared.b16 {%0,%1}, [%2];"
                 : "=r"(r[0]), "=r"(r[1]) : "r"(addr));
}
__device__ __forceinline__ void mma16816(float* d, const uint32_t* a, const uint32_t* b) {
    asm volatile("mma.sync.aligned.m16n8k16.row.col.f32.bf16.bf16.f32 "
                 "{%0,%1,%2,%3}, {%4,%5,%6,%7}, {%8,%9}, {%0,%1,%2,%3};"
                 : "+f"(d[0]), "+f"(d[1]), "+f"(d[2]), "+f"(d[3])
                 : "r"(a[0]), "r"(a[1]), "r"(a[2]), "r"(a[3]), "r"(b[0]), "r"(b[1]));
}
// fp16 variant (for ctx MMA)
__device__ __forceinline__ void mma16816h(float* d, const uint32_t* a, const uint32_t* b) {
    asm volatile("mma.sync.aligned.m16n8k16.row.col.f32.f16.f16.f32 "
                 "{%0,%1,%2,%3}, {%4,%5,%6,%7}, {%8,%9}, {%0,%1,%2,%3};"
                 : "+f"(d[0]), "+f"(d[1]), "+f"(d[2]), "+f"(d[3])
                 : "r"(a[0]), "r"(a[1]), "r"(a[2]), "r"(a[3]), "r"(b[0]), "r"(b[1]));
}
__device__ __forceinline__ float tanh_hw(float x) {
    float r;
    asm("tanh.approx.f32 %0, %1;" : "=f"(r) : "f"(x));
    return r;
}
__device__ __forceinline__ void split2(float v, bf16* ph, bf16* pl) {
    bf16 h = __float2bfloat16(v);
    *ph = h;
    *pl = __float2bfloat16(v - __bfloat162float(h));
}
__device__ __forceinline__ uint32_t pack_h2(__half a, __half b) {
    __half2 h2 = __halves2half2(a, b);
    uint32_t u;
    *(__half2*)&u = h2;
    return u;
}

// ---------------- split-bf16 HMMA GEMM, 4-stage pipeline, split-K via grid.z ----
#define TILE_B   10240
#define BUF_B    40960
#define SMEM_SZ  163840

__global__ void __launch_bounds__(256, 1)
tc_gemm(const bf16* __restrict__ Ah, const bf16* __restrict__ Al, int lda,
        const bf16* __restrict__ Bh, const bf16* __restrict__ Bl,
        const float* __restrict__ bias, float* __restrict__ C, int ldc,
        long tile_stride, int Nstore, int K)
{
    extern __shared__ char sm[];
    const int tid = threadIdx.x, lane = tid & 31, wid = tid >> 5;
    const int m0 = blockIdx.y << 7, n0 = blockIdx.x << 7;
    const int wy = wid & 1, wx = wid >> 1;
    const uint32_t sb = s2u(sm);

    const int kc = K / gridDim.z;
    const size_t kofs = (size_t)blockIdx.z * kc * 2;
    C += (size_t)blockIdx.z * gridDim.y * tile_stride + (size_t)blockIdx.y * tile_stride;

    const char* gAh = (const char*)(Ah + (size_t)m0 * lda) + kofs;
    const char* gAl = (const char*)(Al + (size_t)m0 * lda) + kofs;
    const char* gBh = (const char*)(Bh + (size_t)n0 * K) + kofs;
    const char* gBl = (const char*)(Bl + (size_t)n0 * K) + kofs;
    const size_t strA = (size_t)lda * 2, strB = (size_t)K * 2;

    const int arow = lane & 15;
    const int acol = (lane >> 4) << 4;
    const int brow = ((lane >> 4) << 3) + (lane & 7);
    const int bcol = ((lane >> 3) & 1) << 4;
    const uint32_t aoff = (uint32_t)((wy * 64 + arow) * 80 + acol);
    const uint32_t boff = (uint32_t)((wx * 32 + brow) * 80 + bcol);

    float acc[4][4][4] = {};
    const int nk = kc >> 5;

    auto issue = [&](int ch) {
        if (ch < nk) {
            const int k0b = ch << 6;
            const uint32_t s0 = sb + (ch & 3) * BUF_B;
            #pragma unroll
            for (int half = 0; half < 2; half++) {
                int u  = tid + half * 256;
                int r  = u >> 2;
                int sg = (u & 3) << 4;
                uint32_t s = s0 + r * 80 + sg;
                size_t gA = (size_t)r * strA + k0b + sg;
                size_t gB = (size_t)r * strB + k0b + sg;
                cp16(s,              gAh + gA);
                cp16(s + TILE_B,     gAl + gA);
                cp16(s + 2 * TILE_B, gBh + gB);
                cp16(s + 3 * TILE_B, gBl + gB);
            }
        }
        cp_commit();
    };

    issue(0); issue(1); issue(2);

    for (int ch = 0; ch < nk; ch++) {
        cp_wait<2>();
        __syncthreads();
        issue(ch + 3);

        const uint32_t base = sb + (ch & 3) * BUF_B;
        #pragma unroll
        for (int ks = 0; ks < 2; ks++) {
            uint32_t ah[4][4], al[4][4];
            #pragma unroll
            for (int mi = 0; mi < 4; mi++) {
                uint32_t o = aoff + mi * (16 * 80) + ks * 32;
                ldsm4(ah[mi], base + o);
                ldsm4(al[mi], base + TILE_B + o);
            }
            uint32_t bh[2][4], bl[2][4];
            #pragma unroll
            for (int nj = 0; nj < 2; nj++) {
                uint32_t o = boff + nj * (16 * 80) + ks * 32;
                ldsm4(bh[nj], base + 2 * TILE_B + o);
                ldsm4(bl[nj], base + 3 * TILE_B + o);
            }
            #pragma unroll
            for (int mi = 0; mi < 4; mi++) {
                #pragma unroll
                for (int n8 = 0; n8 < 4; n8++) {
                    const uint32_t* pbh = &bh[n8 >> 1][(n8 & 1) << 1];
                    const uint32_t* pbl = &bl[n8 >> 1][(n8 & 1) << 1];
                    mma16816(acc[mi][n8], ah[mi], pbh);
                    mma16816(acc[mi][n8], ah[mi], pbl);
                    mma16816(acc[mi][n8], al[mi], pbh);
                }
            }
        }
    }

    #pragma unroll
    for (int mi = 0; mi < 4; mi++) {
        #pragma unroll
        for (int n8 = 0; n8 < 4; n8++) {
            int rb = wy * 64 + mi * 16 + (lane >> 2);
            int nb = n0 + wx * 32 + n8 * 8 + ((lane & 3) << 1);
            #pragma unroll
            for (int g = 0; g < 2; g++) {
                int r = rb + g * 8;
                #pragma unroll
                for (int j = 0; j < 2; j++) {
                    int n = nb + j;
                    if (n < Nstore) {
                        float v = acc[mi][n8][g * 2 + j];
                        if (bias) v += bias[n];
                        C[(size_t)r * ldc + n] = v;
                    }
                }
            }
        }
    }
}

// ---------------- conversion kernels ----------------
// one img pass: hi/lo bf16 split + fp16 copy + patch average
__global__ void imgprep_kernel(const float* __restrict__ img,
                               bf16* __restrict__ imgh, bf16* __restrict__ imgl,
                               __half* __restrict__ img16,
                               bf16* __restrict__ ah, bf16* __restrict__ al)
{
    int b = blockIdx.y;
    int e = blockIdx.x * 256 + threadIdx.x;
    const size_t base = (size_t)b * PP * EE + e;
    const float* ib = img + base;
    float s = 0;
    #pragma unroll 4
    for (int p = 0; p < PP; p++) {
        float v = ib[(size_t)p * EE];
        s += v;
        size_t o = base + (size_t)p * EE;
        split2(v, imgh + o, imgl + o);
        img16[o] = __float2half(v);
    }
    split2(s * (1.0f / PP), ah + b * EE + e, al + b * EE + e);
}

__global__ void tsplit_kernel(const float* __restrict__ src, bf16* __restrict__ dh,
                              bf16* __restrict__ dl, int Ksrc, int N, int dst_ld, int koff)
{
    __shared__ float t[32][33];
    const int n0 = blockIdx.x << 5, k0 = blockIdx.y << 5;
    #pragma unroll
    for (int j = 0; j < 4; j++) {
        int kk = k0 + threadIdx.y + (j << 3);
        int n  = n0 + threadIdx.x;
        t[threadIdx.y + (j << 3)][threadIdx.x] = (n < N) ? src[(size_t)kk * N + n] : 0.0f;
    }
    __syncthreads();
    #pragma unroll
    for (int j = 0; j < 4; j++) {
        int nn = n0 + threadIdx.y + (j << 3);
        int k  = k0 + threadIdx.x;
        size_t o = (size_t)nn * dst_ld + koff + k;
        split2(t[threadIdx.x][threadIdx.y + (j << 3)], dh + o, dl + o);
    }
}

// ---------------- pointwise kernels ----------------
__global__ void combine_init(const float* __restrict__ hcp,
                             const float* __restrict__ bih, const float* __restrict__ bic,
                             const float* __restrict__ Wemb, const int* __restrict__ cap,
                             float* __restrict__ c, bf16* __restrict__ Xh, bf16* __restrict__ Xl)
{
    int i = blockIdx.x * 256 + threadIdx.x;   // B*H
    int b = i >> 9, h = i & 511;
    float sh = bih[h], sc = bic[h];
    #pragma unroll
    for (int z = 0; z < 8; z++) {
        sh += hcp[(size_t)z * BB * HC + b * HC + h];
        sc += hcp[(size_t)z * BB * HC + b * HC + HH + h];
    }
    c[i] = tanhf(sc);
    size_t o = (size_t)b * XK + 2560 + h;
    split2(tanhf(sh), Xh + o, Xl + o);
    int cw = cap[b * TT + 0];
    size_t oe = (size_t)b * XK + h;
    split2(Wemb[(size_t)cw * HH + h], Xh + oe, Xl + oe);
}

// ---------------- attention (scores + softmax), 1024 threads, hw tanh ---------
__global__ void __launch_bounds__(1024)
attention_kernel(const float* __restrict__ Ws, const float* __restrict__ qgp,
                 const float* __restrict__ bU,
                 const float* __restrict__ v_att, const float* __restrict__ bv,
                 float* __restrict__ alpha, float* __restrict__ alpha_out)
{
    __shared__ float qs[HH], vs[HH], es[PP], red[32];
    const int b = blockIdx.x, tid = threadIdx.x;
    const int lane = tid & 31, warp = tid >> 5;
    const size_t qb = (size_t)b * QG;

    for (int i = tid; i < HH; i += 1024) {
        float s = bU[i];
        #pragma unroll
        for (int z = 0; z < 4; z++) s += qgp[(size_t)z * BB * QG + qb + i];
        qs[i] = s;
        vs[i] = v_att[i];
    }
    __syncthreads();

    const float* Wb = Ws + (size_t)b * PP * HH;
    const float bv0 = bv[0];
    for (int p = warp; p < PP; p += 32) {
        const float* row = Wb + (size_t)p * HH;
        float s = 0.0f;
        #pragma unroll
        for (int i = 0; i < HH / 32; i++) {
            int h = lane + 32 * i;
            s += vs[h] * tanh_hw(row[h] + qs[h]);
        }
        #pragma unroll
        for (int o = 16; o; o >>= 1) s += __shfl_xor_sync(0xffffffffu, s, o);
        if (lane == 0) es[p] = s + bv0;
    }
    __syncthreads();

    float m = -1e30f;
    for (int p = tid; p < PP; p += 1024) m = fmaxf(m, es[p]);
    #pragma unroll
    for (int o = 16; o; o >>= 1) m = fmaxf(m, __shfl_xor_sync(0xffffffffu, m, o));
    if (lane == 0) red[warp] = m;
    __syncthreads();
    if (warp == 0) {
        float t = red[lane];
        #pragma unroll
        for (int o = 16; o; o >>= 1) t = fmaxf(t, __shfl_xor_sync(0xffffffffu, t, o));
        if (lane == 0) red[0] = t;
    }
    __syncthreads();
    m = red[0];
    __syncthreads();
    float sum = 0.0f;
    for (int p = tid; p < PP; p += 1024) { float ev = expf(es[p] - m); es[p] = ev; sum += ev; }
    #pragma unroll
    for (int o = 16; o; o >>= 1) sum += __shfl_xor_sync(0xffffffffu, sum, o);
    if (lane == 0) red[warp] = sum;
    __syncthreads();
    if (warp == 0) {
        float t = red[lane];
        #pragma unroll
        for (int o = 16; o; o >>= 1) t += __shfl_xor_sync(0xffffffffu, t, o);
        if (lane == 0) red[0] = t;
    }
    __syncthreads();
    float inv = 1.0f / red[0];
    for (int p = tid; p < PP; p += 1024) {
        float a = es[p] * inv;
        alpha[b * PP + p] = a;
        alpha_out[(size_t)b * (SS * PP) + p] = a;
    }
}

// ---------------- context as fp16 HMMA: ctx = alpha @ img16 per batch ---------
// grid (EE/512, BB), 256 threads (8 warps x 64 n-cols). K=196 padded to 208.
__global__ void __launch_bounds__(256)
ctx_mma_kernel(const __half* __restrict__ img16, const float* __restrict__ alpha,
               const float* __restrict__ qgp, const float* __restrict__ bfb,
               bf16* __restrict__ Xh, bf16* __restrict__ Xl)
{
    __shared__ __half tile[2][16][512];   // 32 KB
    __shared__ float  al_s[208];
    const int b = blockIdx.y;
    const int n_cta = blockIdx.x << 9;    // 512-wide slab
    const int tid = threadIdx.x, lane = tid & 31, warp = tid >> 5;

    for (int i = tid; i < 208; i += 256) al_s[i] = (i < PP) ? alpha[b * PP + i] : 0.0f;

    const __half* gimg = img16 + (size_t)b * PP * EE + n_cta;
    const uint32_t tb = s2u(&tile[0][0][0]);

    auto issue = [&](int ck, int buf) {
        #pragma unroll
        for (int i = 0; i < 4; i++) {
            int idx = tid + (i << 8);
            int r = idx >> 6, sg = (idx & 63) << 3;   // row, 8-half segment
            int p = (ck << 4) + r;
            if (p < PP)
                cp16(tb + (buf * 16 + r) * 1024 + sg * 2,
                     gimg + (size_t)p * EE + sg);
        }
        cp_commit();
    };

    const int NC = 13;   // 208/16
    issue(0, 0);

    float acc[8][4] = {};
    const int t4 = lane & 3;

    for (int ck = 0; ck < NC; ck++) {
        if (ck + 1 < NC) { issue(ck + 1, (ck + 1) & 1); cp_wait<1>(); }
        else             { cp_wait<0>(); }
        __syncthreads();

        // alpha fragments (row 0 only; hi + lo residual)
        uint32_t a_h[4] = {0, 0, 0, 0}, a_l[4] = {0, 0, 0, 0};
        if (lane < 4) {
            int k0 = (ck << 4) + (t4 << 1);
            float x0 = al_s[k0], x1 = al_s[k0 + 1];
            float x2 = al_s[k0 + 8], x3 = al_s[k0 + 9];
            __half h0 = __float2half(x0), h1 = __float2half(x1);
            __half h2 = __float2half(x2), h3 = __float2half(x3);
            a_h[0] = pack_h2(h0, h1);
            a_h[2] = pack_h2(h2, h3);
            a_l[0] = pack_h2(__float2half(x0 - __half2float(h0)),
                             __float2half(x1 - __half2float(h1)));
            a_l[2] = pack_h2(__float2half(x2 - __half2float(h2)),
                             __float2half(x3 - __half2float(h3)));
        }

        const uint32_t rowaddr = tb + ((ck & 1) * 16 + (lane & 15)) * 1024 + (warp << 7);
        #pragma unroll
        for (int f = 0; f < 8; f++) {
            uint32_t brg[2];
            ldsm2t(brg, rowaddr + (f << 4));
            mma16816h(acc[f], a_h, brg);
            mma16816h(acc[f], a_l, brg);
        }
        __syncthreads();
    }

    // stage gate = sigmoid(bfb + sum partials) into smem (reuse tile)
    float* gate_s = (float*)&tile[0][0][0];
    #pragma unroll
    for (int i = 0; i < 2; i++) {
        int el = tid + (i << 8);              // 0..511
        int e = n_cta + el;
        float gs = bfb[e];
        #pragma unroll
        for (int z = 0; z < 4; z++) gs += qgp[(size_t)z * BB * QG + (size_t)b * QG + HH + e];
        gate_s[el] = 1.0f / (1.0f + expf(-gs));
    }
    __syncthreads();

    if (lane < 4) {
        #pragma unroll
        for (int f = 0; f < 8; f++) {
            #pragma unroll
            for (int j = 0; j < 2; j++) {
                int el = (warp << 6) + (f << 3) + (t4 << 1) + j;
                int e = n_cta + el;
                float v = acc[f][j] * gate_s[el];
                size_t o = (size_t)b * XK + HH + e;
                split2(v, Xh + o, Xl + o);
            }
        }
    }
}

// LSTM + h history + emb for next step
__global__ void lstm_kernel(const float* __restrict__ gatesp, const float* __restrict__ bl,
                            float* __restrict__ c, bf16* __restrict__ Xh, bf16* __restrict__ Xl,
                            bf16* __restrict__ Hh, bf16* __restrict__ Hl,
                            const float* __restrict__ Wemb, const int* __restrict__ cap, int t)
{
    int i = blockIdx.x * 256 + threadIdx.x;
    int b = i >> 9, h = i & 511;
    float g[4];
    #pragma unroll
    for (int k = 0; k < 4; k++) {
        int j = k * HH + h;
        float s = bl[j];
        #pragma unroll
        for (int z = 0; z < 8; z++) s += gatesp[(size_t)z * BB * G4 + b * G4 + j];
        g[k] = s;
    }
    float ig = 1.0f / (1.0f + expf(-g[0]));
    float fg = 1.0f / (1.0f + expf(-g[1]));
    float gg = tanhf(g[2]);
    float og = 1.0f / (1.0f + expf(-g[3]));
    float cn = fg * c[i] + ig * gg;
    c[i] = cn;
    float hn = og * tanhf(cn);
    size_t o = (size_t)b * XK + 2560 + h;
    split2(hn, Xh + o, Xl + o);
    size_t oh = (size_t)(t * BB + b) * HH + h;
    split2(hn, Hh + oh, Hl + oh);
    int cw = cap[b * TT + (t + 1)];
    size_t oe = (size_t)b * XK + h;
    split2(Wemb[(size_t)cw * HH + h], Xh + oe, Xl + oe);
}

// ---------------- host launch ----------------
extern "C" void kernel_launch(void* const* d_in, const int* in_sizes, int n_in,
                              void* d_out, int out_size)
{
    const float* img   = (const float*)d_in[0];
    const int*   cap   = (const int*)  d_in[1];
    const float* U_att = (const float*)d_in[2];
    const float* bU    = (const float*)d_in[3];
    const float* W_att = (const float*)d_in[4];
    const float* bW    = (const float*)d_in[5];
    const float* v_att = (const float*)d_in[6];
    const float* bv    = (const float*)d_in[7];
    const float* Wih   = (const float*)d_in[8];
    const float* bih   = (const float*)d_in[9];
    const float* Wic   = (const float*)d_in[10];
    const float* bic   = (const float*)d_in[11];
    const float* Wfb   = (const float*)d_in[12];
    const float* bfb   = (const float*)d_in[13];
    const float* Wdo   = (const float*)d_in[14];
    const float* bdo   = (const float*)d_in[15];
    const float* Wemb  = (const float*)d_in[16];
    const float* Wl    = (const float*)d_in[17];
    const float* Ul    = (const float*)d_in[18];
    const float* bl    = (const float*)d_in[19];

    float* preds  = (float*)d_out;
    float* alphas = (float*)d_out + (size_t)BB * SS * VV;

    bf16 *imgh, *imgl, *BWatt_h, *BWatt_l, *BWihc_h, *BWihc_l;
    bf16 *Bqg_h, *Bqg_l, *BWcat_h, *BWcat_l, *BWdo_h, *BWdo_l;
    bf16 *avgh, *avgl, *Xh, *Xl, *Hh, *Hl;
    __half* img16;
    float *pWs, *pc, *palpha, *pqgp, *pgatesp;
    cudaGetSymbolAddress((void**)&imgh, g_imgh);     cudaGetSymbolAddress((void**)&imgl, g_imgl);
    cudaGetSymbolAddress((void**)&img16, g_img16);
    cudaGetSymbolAddress((void**)&BWatt_h, g_BWatt_h); cudaGetSymbolAddress((void**)&BWatt_l, g_BWatt_l);
    cudaGetSymbolAddress((void**)&BWihc_h, g_BWihc_h); cudaGetSymbolAddress((void**)&BWihc_l, g_BWihc_l);
    cudaGetSymbolAddress((void**)&Bqg_h, g_Bqg_h);   cudaGetSymbolAddress((void**)&Bqg_l, g_Bqg_l);
    cudaGetSymbolAddress((void**)&BWcat_h, g_BWcat_h); cudaGetSymbolAddress((void**)&BWcat_l, g_BWcat_l);
    cudaGetSymbolAddress((void**)&BWdo_h, g_BWdo_h); cudaGetSymbolAddress((void**)&BWdo_l, g_BWdo_l);
    cudaGetSymbolAddress((void**)&avgh, g_avgh);     cudaGetSymbolAddress((void**)&avgl, g_avgl);
    cudaGetSymbolAddress((void**)&Xh, g_Xh);         cudaGetSymbolAddress((void**)&Xl, g_Xl);
    cudaGetSymbolAddress((void**)&Hh, g_Hh);         cudaGetSymbolAddress((void**)&Hl, g_Hl);
    cudaGetSymbolAddress((void**)&pWs, g_Ws);        cudaGetSymbolAddress((void**)&pc, g_c);
    cudaGetSymbolAddress((void**)&palpha, g_alpha);
    cudaGetSymbolAddress((void**)&pqgp, g_qgp);
    cudaGetSymbolAddress((void**)&pgatesp, g_gatesp);

    cudaFuncSetAttribute(tc_gemm, cudaFuncAttributeMaxDynamicSharedMemorySize, SMEM_SZ);

    cudaStream_t s2;
    cudaStreamCreateWithFlags(&s2, cudaStreamNonBlocking);
    cudaEvent_t evFork, evTsplit, evImg, evInit, evDone;
    cudaEvent_t evStep[SS];
    cudaEventCreateWithFlags(&evFork, cudaEventDisableTiming);
    cudaEventCreateWithFlags(&evTsplit, cudaEventDisableTiming);
    cudaEventCreateWithFlags(&evImg, cudaEventDisableTiming);
    cudaEventCreateWithFlags(&evInit, cudaEventDisableTiming);
    cudaEventCreateWithFlags(&evDone, cudaEventDisableTiming);
    for (int t = 0; t < SS; t++) cudaEventCreateWithFlags(&evStep[t], cudaEventDisableTiming);

    cudaEventRecord(evFork, 0);
    cudaStreamWaitEvent(s2, evFork, 0);

    // s2: all weight transposes
    {
        dim3 blk(32, 8);
        tsplit_kernel<<<dim3(16, 64), blk, 0, s2>>>(W_att, BWatt_h, BWatt_l, EE, HH, EE, 0);
        tsplit_kernel<<<dim3(16, 64), blk, 0, s2>>>(Wih, BWihc_h, BWihc_l, EE, HH, EE, 0);
        tsplit_kernel<<<dim3(16, 64), blk, 0, s2>>>(Wic, BWihc_h + (size_t)HH * EE,
                                                    BWihc_l + (size_t)HH * EE, EE, HH, EE, 0);
        tsplit_kernel<<<dim3(16, 16), blk, 0, s2>>>(U_att, Bqg_h, Bqg_l, HH, HH, HH, 0);
        tsplit_kernel<<<dim3(64, 16), blk, 0, s2>>>(Wfb, Bqg_h + (size_t)HH * HH,
                                                    Bqg_l + (size_t)HH * HH, HH, EE, HH, 0);
        tsplit_kernel<<<dim3(64, 80), blk, 0, s2>>>(Wl, BWcat_h, BWcat_l, 2560, G4, XK, 0);
        tsplit_kernel<<<dim3(64, 16), blk, 0, s2>>>(Ul, BWcat_h, BWcat_l, HH, G4, XK, 2560);
        tsplit_kernel<<<dim3(VPAD / 32, 16), blk, 0, s2>>>(Wdo, BWdo_h, BWdo_l, HH, VV, HH, 0);
        cudaEventRecord(evTsplit, s2);
    }

    // main: img split + fp16 + avg
    imgprep_kernel<<<dim3(EE / 256, BB), 256>>>(img, imgh, imgl, img16, avgh, avgl);
    cudaEventRecord(evImg, 0);

    // s2: merged h0|c0 GEMM + combine
    cudaStreamWaitEvent(s2, evImg, 0);
    tc_gemm<<<dim3(HC / 128, 1, 8), 256, SMEM_SZ, s2>>>(avgh, avgl, EE, BWihc_h, BWihc_l,
                                                        nullptr, pgatesp, HC,
                                                        (long)128 * HC, HC, EE);
    combine_init<<<(BB * HH) / 256, 256, 0, s2>>>(pgatesp, bih, bic, Wemb, cap, pc, Xh, Xl);
    cudaEventRecord(evInit, s2);

    // main: W_s
    cudaStreamWaitEvent(0, evTsplit, 0);
    tc_gemm<<<dim3(4, 196, 1), 256, SMEM_SZ>>>(imgh, imgl, EE, BWatt_h, BWatt_l,
                                               bW, pWs, HH, (long)128 * HH, HH, EE);
    cudaStreamWaitEvent(0, evInit, 0);

    for (int t = 0; t < SS; t++) {
        tc_gemm<<<dim3(QG / 128, 1, 4), 256, SMEM_SZ>>>(Xh + 2560, Xl + 2560, XK,
                                                        Bqg_h, Bqg_l, nullptr, pqgp,
                                                        QG, (long)128 * QG, QG, HH);
        attention_kernel<<<BB, 1024>>>(pWs, pqgp, bU, v_att, bv, palpha,
                                       alphas + (size_t)t * PP);
        ctx_mma_kernel<<<dim3(EE / 512, BB), 256>>>(img16, palpha, pqgp, bfb, Xh, Xl);
        tc_gemm<<<dim3(16, 1, 8), 256, SMEM_SZ>>>(Xh, Xl, XK,
                                                  BWcat_h, BWcat_l, nullptr, pgatesp,
                                                  G4, (long)128 * G4, G4, XK);
        lstm_kernel<<<(BB * HH) / 256, 256>>>(pgatesp, bl, pc, Xh, Xl, Hh, Hl, Wemb, cap, t);
        cudaEventRecord(evStep[t], 0);
        cudaStreamWaitEvent(s2, evStep[t], 0);
        tc_gemm<<<dim3(VPAD / 128, 1, 1), 256, SMEM_SZ, s2>>>(
            Hh + (size_t)t * BB * HH, Hl + (size_t)t * BB * HH, HH,
            BWdo_h, BWdo_l, bdo, preds + (size_t)t * VV, SS * VV, 0L, VV, HH);
    }

    cudaEventRecord(evDone, s2);
    cudaStreamWaitEvent(0, evDone, 0);
}

// round 16
// speedup vs baseline: 1.4080x; 1.0296x over previous
#include <cuda_runtime.h>
#include <cuda_bf16.h>
#include <cuda_fp16.h>
#include <math.h>
#include <stdint.h>

#define BB 128
#define PP 196
#define EE 2048
#define HH 512
#define VV 10000
#define VPAD 10112
#define TT 20
#define SS 19
#define XK 3072
#define G4 2048
#define QG 2560          // q(512) + gate(2048) merged output width
#define HC 1024          // h0(512) + c0(512) merged init output width

typedef __nv_bfloat16 bf16;

// ---------------- device global scratch ----------------
__device__ bf16   g_imgh[(size_t)BB * PP * EE];
__device__ bf16   g_imgl[(size_t)BB * PP * EE];
__device__ __half g_img16[(size_t)BB * PP * EE];     // fp16 img for ctx MMA
__device__ __half g_Ws16[(size_t)BB * PP * HH];      // fp16 W_s for attention
__device__ bf16   g_BWatt_h[HH * EE],  g_BWatt_l[HH * EE];
__device__ bf16   g_BWihc_h[HC * EE],  g_BWihc_l[HC * EE];   // [Wih ; Wic]
__device__ bf16   g_Bqg_h[QG * HH],    g_Bqg_l[QG * HH];
__device__ bf16   g_BWcat_h[(size_t)G4 * XK], g_BWcat_l[(size_t)G4 * XK];
__device__ bf16   g_BWdo_h[(size_t)VPAD * HH], g_BWdo_l[(size_t)VPAD * HH];
__device__ bf16   g_avgh[BB * EE], g_avgl[BB * EE];
__device__ bf16   g_Xh[BB * XK],   g_Xl[BB * XK];
__device__ bf16   g_Hh[(size_t)SS * BB * HH], g_Hl[(size_t)SS * BB * HH];
__device__ float  g_c[BB * HH];
__device__ float  g_alpha[BB * PP];
__device__ float  g_qgp[4 * BB * QG];
__device__ float  g_gatesp[8 * BB * G4];

// ---------------- helpers ----------------
__device__ __forceinline__ uint32_t s2u(const void* p) {
    uint32_t a;
    asm("{ .reg .u64 t; cvta.to.shared.u64 t, %1; cvt.u32.u64 %0, t; }" : "=r"(a) : "l"(p));
    return a;
}
__device__ __forceinline__ void cp16(uint32_t s, const void* g) {
    asm volatile("cp.async.cg.shared.global [%0], [%1], 16;" :: "r"(s), "l"(g) : "memory");
}
__device__ __forceinline__ void cp_commit() { asm volatile("cp.async.commit_group;" ::: "memory"); }
template <int N> __device__ __forceinline__ void cp_wait() {
    asm volatile("cp.async.wait_group %0;" :: "n"(N) : "memory");
}
__device__ __forceinline__ void ldsm4(uint32_t* r, uint32_t addr) {
    asm volatile("ldmatrix.sync.aligned.m8n8.x4.shared.b16 {%0,%1,%2,%3}, [%4];"
                 : "=r"(r[0]), "=r"(r[1]), "=r"(r[2]), "=r"(r[3]) : "r"(addr));
}
__device__ __forceinline__ void ldsm2t(uint32_t* r, uint32_t addr) {
    asm volatile("ldmatrix.sync.aligned.m8n8.x2.trans.shared.b16 {%0,%1}, [%2];"
                 : "=r"(r[0]), "=r"(r[1]) : "r"(addr));
}
__device__ __forceinline__ void mma16816(float* d, const uint32_t* a, const uint32_t* b) {
    asm volatile("mma.sync.aligned.m16n8k16.row.col.f32.bf16.bf16.f32 "
                 "{%0,%1,%2,%3}, {%4,%5,%6,%7}, {%8,%9}, {%0,%1,%2,%3};"
                 : "+f"(d[0]), "+f"(d[1]), "+f"(d[2]), "+f"(d[3])
                 : "r"(a[0]), "r"(a[1]), "r"(a[2]), "r"(a[3]), "r"(b[0]), "r"(b[1]));
}
__device__ __forceinline__ void mma16816h(float* d, const uint32_t* a, const uint32_t* b) {
    asm volatile("mma.sync.aligned.m16n8k16.row.col.f32.f16.f16.f32 "
                 "{%0,%1,%2,%3}, {%4,%5,%6,%7}, {%8,%9}, {%0,%1,%2,%3};"
                 : "+f"(d[0]), "+f"(d[1]), "+f"(d[2]), "+f"(d[3])
                 : "r"(a[0]), "r"(a[1]), "r"(a[2]), "r"(a[3]), "r"(b[0]), "r"(b[1]));
}
__device__ __forceinline__ float tanh_hw(float x) {
    float r;
    asm("tanh.approx.f32 %0, %1;" : "=f"(r) : "f"(x));
    return r;
}
__device__ __forceinline__ void split2(float v, bf16* ph, bf16* pl) {
    bf16 h = __float2bfloat16(v);
    *ph = h;
    *pl = __float2bfloat16(v - __bfloat162float(h));
}
__device__ __forceinline__ uint32_t pack_h2(__half a, __half b) {
    __half2 h2 = __halves2half2(a, b);
    uint32_t u;
    *(__half2*)&u = h2;
    return u;
}
__device__ __forceinline__ void store_out(float* p, float v) { *p = v; }
__device__ __forceinline__ void store_out(__half* p, float v) { *p = __float2half(v); }

// ---------------- split-bf16 HMMA GEMM, 4-stage pipeline, split-K via grid.z ----
#define TILE_B   10240
#define BUF_B    40960
#define SMEM_SZ  163840

template <typename OT>
__global__ void __launch_bounds__(256, 1)
tc_gemm(const bf16* __restrict__ Ah, const bf16* __restrict__ Al, int lda,
        const bf16* __restrict__ Bh, const bf16* __restrict__ Bl,
        const float* __restrict__ bias, OT* __restrict__ C, int ldc,
        long tile_stride, int Nstore, int K)
{
    extern __shared__ char sm[];
    const int tid = threadIdx.x, lane = tid & 31, wid = tid >> 5;
    const int m0 = blockIdx.y << 7, n0 = blockIdx.x << 7;
    const int wy = wid & 1, wx = wid >> 1;
    const uint32_t sb = s2u(sm);

    const int kc = K / gridDim.z;
    const size_t kofs = (size_t)blockIdx.z * kc * 2;
    C += (size_t)blockIdx.z * gridDim.y * tile_stride + (size_t)blockIdx.y * tile_stride;

    const char* gAh = (const char*)(Ah + (size_t)m0 * lda) + kofs;
    const char* gAl = (const char*)(Al + (size_t)m0 * lda) + kofs;
    const char* gBh = (const char*)(Bh + (size_t)n0 * K) + kofs;
    const char* gBl = (const char*)(Bl + (size_t)n0 * K) + kofs;
    const size_t strA = (size_t)lda * 2, strB = (size_t)K * 2;

    const int arow = lane & 15;
    const int acol = (lane >> 4) << 4;
    const int brow = ((lane >> 4) << 3) + (lane & 7);
    const int bcol = ((lane >> 3) & 1) << 4;
    const uint32_t aoff = (uint32_t)((wy * 64 + arow) * 80 + acol);
    const uint32_t boff = (uint32_t)((wx * 32 + brow) * 80 + bcol);

    float acc[4][4][4] = {};
    const int nk = kc >> 5;

    auto issue = [&](int ch) {
        if (ch < nk) {
            const int k0b = ch << 6;
            const uint32_t s0 = sb + (ch & 3) * BUF_B;
            #pragma unroll
            for (int half = 0; half < 2; half++) {
                int u  = tid + half * 256;
                int r  = u >> 2;
                int sg = (u & 3) << 4;
                uint32_t s = s0 + r * 80 + sg;
                size_t gA = (size_t)r * strA + k0b + sg;
                size_t gB = (size_t)r * strB + k0b + sg;
                cp16(s,              gAh + gA);
                cp16(s + TILE_B,     gAl + gA);
                cp16(s + 2 * TILE_B, gBh + gB);
                cp16(s + 3 * TILE_B, gBl + gB);
            }
        }
        cp_commit();
    };

    issue(0); issue(1); issue(2);

    for (int ch = 0; ch < nk; ch++) {
        cp_wait<2>();
        __syncthreads();
        issue(ch + 3);

        const uint32_t base = sb + (ch & 3) * BUF_B;
        #pragma unroll
        for (int ks = 0; ks < 2; ks++) {
            uint32_t ah[4][4], al[4][4];
            #pragma unroll
            for (int mi = 0; mi < 4; mi++) {
                uint32_t o = aoff + mi * (16 * 80) + ks * 32;
                ldsm4(ah[mi], base + o);
                ldsm4(al[mi], base + TILE_B + o);
            }
            uint32_t bh[2][4], bl[2][4];
            #pragma unroll
            for (int nj = 0; nj < 2; nj++) {
                uint32_t o = boff + nj * (16 * 80) + ks * 32;
                ldsm4(bh[nj], base + 2 * TILE_B + o);
                ldsm4(bl[nj], base + 3 * TILE_B + o);
            }
            #pragma unroll
            for (int mi = 0; mi < 4; mi++) {
                #pragma unroll
                for (int n8 = 0; n8 < 4; n8++) {
                    const uint32_t* pbh = &bh[n8 >> 1][(n8 & 1) << 1];
                    const uint32_t* pbl = &bl[n8 >> 1][(n8 & 1) << 1];
                    mma16816(acc[mi][n8], ah[mi], pbh);
                    mma16816(acc[mi][n8], ah[mi], pbl);
                    mma16816(acc[mi][n8], al[mi], pbh);
                }
            }
        }
    }

    #pragma unroll
    for (int mi = 0; mi < 4; mi++) {
        #pragma unroll
        for (int n8 = 0; n8 < 4; n8++) {
            int rb = wy * 64 + mi * 16 + (lane >> 2);
            int nb = n0 + wx * 32 + n8 * 8 + ((lane & 3) << 1);
            #pragma unroll
            for (int g = 0; g < 2; g++) {
                int r = rb + g * 8;
                #pragma unroll
                for (int j = 0; j < 2; j++) {
                    int n = nb + j;
                    if (n < Nstore) {
                        float v = acc[mi][n8][g * 2 + j];
                        if (bias) v += bias[n];
                        store_out(C + (size_t)r * ldc + n, v);
                    }
                }
            }
        }
    }
}

// ---------------- conversion kernels ----------------
__global__ void imgprep_kernel(const float* __restrict__ img,
                               bf16* __restrict__ imgh, bf16* __restrict__ imgl,
                               __half* __restrict__ img16,
                               bf16* __restrict__ ah, bf16* __restrict__ al)
{
    int b = blockIdx.y;
    int e = blockIdx.x * 256 + threadIdx.x;
    const size_t base = (size_t)b * PP * EE + e;
    const float* ib = img + base;
    float s = 0;
    #pragma unroll 4
    for (int p = 0; p < PP; p++) {
        float v = ib[(size_t)p * EE];
        s += v;
        size_t o = base + (size_t)p * EE;
        split2(v, imgh + o, imgl + o);
        img16[o] = __float2half(v);
    }
    split2(s * (1.0f / PP), ah + b * EE + e, al + b * EE + e);
}

__global__ void tsplit_kernel(const float* __restrict__ src, bf16* __restrict__ dh,
                              bf16* __restrict__ dl, int Ksrc, int N, int dst_ld, int koff)
{
    __shared__ float t[32][33];
    const int n0 = blockIdx.x << 5, k0 = blockIdx.y << 5;
    #pragma unroll
    for (int j = 0; j < 4; j++) {
        int kk = k0 + threadIdx.y + (j << 3);
        int n  = n0 + threadIdx.x;
        t[threadIdx.y + (j << 3)][threadIdx.x] = (n < N) ? src[(size_t)kk * N + n] : 0.0f;
    }
    __syncthreads();
    #pragma unroll
    for (int j = 0; j < 4; j++) {
        int nn = n0 + threadIdx.y + (j << 3);
        int k  = k0 + threadIdx.x;
        size_t o = (size_t)nn * dst_ld + koff + k;
        split2(t[threadIdx.x][threadIdx.y + (j << 3)], dh + o, dl + o);
    }
}

// ---------------- pointwise kernels ----------------
__global__ void combine_init(const float* __restrict__ hcp,
                             const float* __restrict__ bih, const float* __restrict__ bic,
                             const float* __restrict__ Wemb, const int* __restrict__ cap,
                             float* __restrict__ c, bf16* __restrict__ Xh, bf16* __restrict__ Xl)
{
    int i = blockIdx.x * 256 + threadIdx.x;   // B*H
    int b = i >> 9, h = i & 511;
    float sh = bih[h], sc = bic[h];
    #pragma unroll
    for (int z = 0; z < 8; z++) {
        sh += hcp[(size_t)z * BB * HC + b * HC + h];
        sc += hcp[(size_t)z * BB * HC + b * HC + HH + h];
    }
    c[i] = tanhf(sc);
    size_t o = (size_t)b * XK + 2560 + h;
    split2(tanhf(sh), Xh + o, Xl + o);
    int cw = cap[b * TT + 0];
    size_t oe = (size_t)b * XK + h;
    split2(Wemb[(size_t)cw * HH + h], Xh + oe, Xl + oe);
}

// ---------------- attention (scores + softmax), fp16 W_s, 1024 threads --------
__global__ void __launch_bounds__(1024)
attention_kernel(const __half* __restrict__ Ws, const float* __restrict__ qgp,
                 const float* __restrict__ bU,
                 const float* __restrict__ v_att, const float* __restrict__ bv,
                 float* __restrict__ alpha, float* __restrict__ alpha_out)
{
    __shared__ float qs[HH], vs[HH], es[PP], red[32];
    const int b = blockIdx.x, tid = threadIdx.x;
    const int lane = tid & 31, warp = tid >> 5;
    const size_t qb = (size_t)b * QG;

    for (int i = tid; i < HH; i += 1024) {
        float s = bU[i];
        #pragma unroll
        for (int z = 0; z < 4; z++) s += qgp[(size_t)z * BB * QG + qb + i];
        qs[i] = s;
        vs[i] = v_att[i];
    }
    __syncthreads();

    const __half* Wb = Ws + (size_t)b * PP * HH;
    const float bv0 = bv[0];
    for (int p = warp; p < PP; p += 32) {
        const __half* row = Wb + (size_t)p * HH;
        float s = 0.0f;
        #pragma unroll
        for (int i = 0; i < 8; i++) {
            int h = (lane << 1) + (i << 6);    // coalesced half2 per lane
            float2 f = __half22float2(*(const __half2*)(row + h));
            s += vs[h]     * tanh_hw(f.x + qs[h]);
            s += vs[h + 1] * tanh_hw(f.y + qs[h + 1]);
        }
        #pragma unroll
        for (int o = 16; o; o >>= 1) s += __shfl_xor_sync(0xffffffffu, s, o);
        if (lane == 0) es[p] = s + bv0;
    }
    __syncthreads();

    float m = -1e30f;
    for (int p = tid; p < PP; p += 1024) m = fmaxf(m, es[p]);
    #pragma unroll
    for (int o = 16; o; o >>= 1) m = fmaxf(m, __shfl_xor_sync(0xffffffffu, m, o));
    if (lane == 0) red[warp] = m;
    __syncthreads();
    if (warp == 0) {
        float t = red[lane];
        #pragma unroll
        for (int o = 16; o; o >>= 1) t = fmaxf(t, __shfl_xor_sync(0xffffffffu, t, o));
        if (lane == 0) red[0] = t;
    }
    __syncthreads();
    m = red[0];
    __syncthreads();
    float sum = 0.0f;
    for (int p = tid; p < PP; p += 1024) { float ev = expf(es[p] - m); es[p] = ev; sum += ev; }
    #pragma unroll
    for (int o = 16; o; o >>= 1) sum += __shfl_xor_sync(0xffffffffu, sum, o);
    if (lane == 0) red[warp] = sum;
    __syncthreads();
    if (warp == 0) {
        float t = red[lane];
        #pragma unroll
        for (int o = 16; o; o >>= 1) t += __shfl_xor_sync(0xffffffffu, t, o);
        if (lane == 0) red[0] = t;
    }
    __syncthreads();
    float inv = 1.0f / red[0];
    for (int p = tid; p < PP; p += 1024) {
        float a = es[p] * inv;
        alpha[b * PP + p] = a;
        alpha_out[(size_t)b * (SS * PP) + p] = a;
    }
}

// ---------------- context as fp16 HMMA: ctx = alpha @ img16 per batch ---------
__global__ void __launch_bounds__(256)
ctx_mma_kernel(const __half* __restrict__ img16, const float* __restrict__ alpha,
               const float* __restrict__ qgp, const float* __restrict__ bfb,
               bf16* __restrict__ Xh, bf16* __restrict__ Xl)
{
    __shared__ __half tile[2][16][512];   // 32 KB
    __shared__ float  al_s[208];
    const int b = blockIdx.y;
    const int n_cta = blockIdx.x << 9;
    const int tid = threadIdx.x, lane = tid & 31, warp = tid >> 5;

    for (int i = tid; i < 208; i += 256) al_s[i] = (i < PP) ? alpha[b * PP + i] : 0.0f;

    const __half* gimg = img16 + (size_t)b * PP * EE + n_cta;
    const uint32_t tb = s2u(&tile[0][0][0]);

    auto issue = [&](int ck, int buf) {
        #pragma unroll
        for (int i = 0; i < 4; i++) {
            int idx = tid + (i << 8);
            int r = idx >> 6, sg = (idx & 63) << 3;
            int p = (ck << 4) + r;
            if (p < PP)
                cp16(tb + (buf * 16 + r) * 1024 + sg * 2,
                     gimg + (size_t)p * EE + sg);
        }
        cp_commit();
    };

    const int NC = 13;
    issue(0, 0);

    float acc[8][4] = {};
    const int t4 = lane & 3;

    for (int ck = 0; ck < NC; ck++) {
        if (ck + 1 < NC) { issue(ck + 1, (ck + 1) & 1); cp_wait<1>(); }
        else             { cp_wait<0>(); }
        __syncthreads();

        uint32_t a_h[4] = {0, 0, 0, 0}, a_l[4] = {0, 0, 0, 0};
        if (lane < 4) {
            int k0 = (ck << 4) + (t4 << 1);
            float x0 = al_s[k0], x1 = al_s[k0 + 1];
            float x2 = al_s[k0 + 8], x3 = al_s[k0 + 9];
            __half h0 = __float2half(x0), h1 = __float2half(x1);
            __half h2 = __float2half(x2), h3 = __float2half(x3);
            a_h[0] = pack_h2(h0, h1);
            a_h[2] = pack_h2(h2, h3);
            a_l[0] = pack_h2(__float2half(x0 - __half2float(h0)),
                             __float2half(x1 - __half2float(h1)));
            a_l[2] = pack_h2(__float2half(x2 - __half2float(h2)),
                             __float2half(x3 - __half2float(h3)));
        }

        const uint32_t rowaddr = tb + ((ck & 1) * 16 + (lane & 15)) * 1024 + (warp << 7);
        #pragma unroll
        for (int f = 0; f < 8; f++) {
            uint32_t brg[2];
            ldsm2t(brg, rowaddr + (f << 4));
            mma16816h(acc[f], a_h, brg);
            mma16816h(acc[f], a_l, brg);
        }
        __syncthreads();
    }

    float* gate_s = (float*)&tile[0][0][0];
    #pragma unroll
    for (int i = 0; i < 2; i++) {
        int el = tid + (i << 8);
        int e = n_cta + el;
        float gs = bfb[e];
        #pragma unroll
        for (int z = 0; z < 4; z++) gs += qgp[(size_t)z * BB * QG + (size_t)b * QG + HH + e];
        gate_s[el] = 1.0f / (1.0f + expf(-gs));
    }
    __syncthreads();

    if (lane < 4) {
        #pragma unroll
        for (int f = 0; f < 8; f++) {
            #pragma unroll
            for (int j = 0; j < 2; j++) {
                int el = (warp << 6) + (f << 3) + (t4 << 1) + j;
                int e = n_cta + el;
                float v = acc[f][j] * gate_s[el];
                size_t o = (size_t)b * XK + HH + e;
                split2(v, Xh + o, Xl + o);
            }
        }
    }
}

// LSTM + h history + emb for next step
__global__ void lstm_kernel(const float* __restrict__ gatesp, const float* __restrict__ bl,
                            float* __restrict__ c, bf16* __restrict__ Xh, bf16* __restrict__ Xl,
                            bf16* __restrict__ Hh, bf16* __restrict__ Hl,
                            const float* __restrict__ Wemb, const int* __restrict__ cap, int t)
{
    int i = blockIdx.x * 256 + threadIdx.x;
    int b = i >> 9, h = i & 511;
    float g[4];
    #pragma unroll
    for (int k = 0; k < 4; k++) {
        int j = k * HH + h;
        float s = bl[j];
        #pragma unroll
        for (int z = 0; z < 8; z++) s += gatesp[(size_t)z * BB * G4 + b * G4 + j];
        g[k] = s;
    }
    float ig = 1.0f / (1.0f + expf(-g[0]));
    float fg = 1.0f / (1.0f + expf(-g[1]));
    float gg = tanhf(g[2]);
    float og = 1.0f / (1.0f + expf(-g[3]));
    float cn = fg * c[i] + ig * gg;
    c[i] = cn;
    float hn = og * tanhf(cn);
    size_t o = (size_t)b * XK + 2560 + h;
    split2(hn, Xh + o, Xl + o);
    size_t oh = (size_t)(t * BB + b) * HH + h;
    split2(hn, Hh + oh, Hl + oh);
    int cw = cap[b * TT + (t + 1)];
    size_t oe = (size_t)b * XK + h;
    split2(Wemb[(size_t)cw * HH + h], Xh + oe, Xl + oe);
}

// ---------------- host launch ----------------
extern "C" void kernel_launch(void* const* d_in, const int* in_sizes, int n_in,
                              void* d_out, int out_size)
{
    const float* img   = (const float*)d_in[0];
    const int*   cap   = (const int*)  d_in[1];
    const float* U_att = (const float*)d_in[2];
    const float* bU    = (const float*)d_in[3];
    const float* W_att = (const float*)d_in[4];
    const float* bW    = (const float*)d_in[5];
    const float* v_att = (const float*)d_in[6];
    const float* bv    = (const float*)d_in[7];
    const float* Wih   = (const float*)d_in[8];
    const float* bih   = (const float*)d_in[9];
    const float* Wic   = (const float*)d_in[10];
    const float* bic   = (const float*)d_in[11];
    const float* Wfb   = (const float*)d_in[12];
    const float* bfb   = (const float*)d_in[13];
    const float* Wdo   = (const float*)d_in[14];
    const float* bdo   = (const float*)d_in[15];
    const float* Wemb  = (const float*)d_in[16];
    const float* Wl    = (const float*)d_in[17];
    const float* Ul    = (const float*)d_in[18];
    const float* bl    = (const float*)d_in[19];

    float* preds  = (float*)d_out;
    float* alphas = (float*)d_out + (size_t)BB * SS * VV;

    bf16 *imgh, *imgl, *BWatt_h, *BWatt_l, *BWihc_h, *BWihc_l;
    bf16 *Bqg_h, *Bqg_l, *BWcat_h, *BWcat_l, *BWdo_h, *BWdo_l;
    bf16 *avgh, *avgl, *Xh, *Xl, *Hh, *Hl;
    __half *img16, *pWs16;
    float *pc, *palpha, *pqgp, *pgatesp;
    cudaGetSymbolAddress((void**)&imgh, g_imgh);     cudaGetSymbolAddress((void**)&imgl, g_imgl);
    cudaGetSymbolAddress((void**)&img16, g_img16);   cudaGetSymbolAddress((void**)&pWs16, g_Ws16);
    cudaGetSymbolAddress((void**)&BWatt_h, g_BWatt_h); cudaGetSymbolAddress((void**)&BWatt_l, g_BWatt_l);
    cudaGetSymbolAddress((void**)&BWihc_h, g_BWihc_h); cudaGetSymbolAddress((void**)&BWihc_l, g_BWihc_l);
    cudaGetSymbolAddress((void**)&Bqg_h, g_Bqg_h);   cudaGetSymbolAddress((void**)&Bqg_l, g_Bqg_l);
    cudaGetSymbolAddress((void**)&BWcat_h, g_BWcat_h); cudaGetSymbolAddress((void**)&BWcat_l, g_BWcat_l);
    cudaGetSymbolAddress((void**)&BWdo_h, g_BWdo_h); cudaGetSymbolAddress((void**)&BWdo_l, g_BWdo_l);
    cudaGetSymbolAddress((void**)&avgh, g_avgh);     cudaGetSymbolAddress((void**)&avgl, g_avgl);
    cudaGetSymbolAddress((void**)&Xh, g_Xh);         cudaGetSymbolAddress((void**)&Xl, g_Xl);
    cudaGetSymbolAddress((void**)&Hh, g_Hh);         cudaGetSymbolAddress((void**)&Hl, g_Hl);
    cudaGetSymbolAddress((void**)&pc, g_c);          cudaGetSymbolAddress((void**)&palpha, g_alpha);
    cudaGetSymbolAddress((void**)&pqgp, g_qgp);
    cudaGetSymbolAddress((void**)&pgatesp, g_gatesp);

    cudaFuncSetAttribute(tc_gemm<float>,  cudaFuncAttributeMaxDynamicSharedMemorySize, SMEM_SZ);
    cudaFuncSetAttribute(tc_gemm<__half>, cudaFuncAttributeMaxDynamicSharedMemorySize, SMEM_SZ);

    cudaStream_t s2;
    cudaStreamCreateWithFlags(&s2, cudaStreamNonBlocking);
    cudaEvent_t evFork, evTsplit, evImg, evInit, evDone;
    cudaEvent_t evStep[SS];
    cudaEventCreateWithFlags(&evFork, cudaEventDisableTiming);
    cudaEventCreateWithFlags(&evTsplit, cudaEventDisableTiming);
    cudaEventCreateWithFlags(&evImg, cudaEventDisableTiming);
    cudaEventCreateWithFlags(&evInit, cudaEventDisableTiming);
    cudaEventCreateWithFlags(&evDone, cudaEventDisableTiming);
    for (int t = 0; t < SS; t++) cudaEventCreateWithFlags(&evStep[t], cudaEventDisableTiming);

    cudaEventRecord(evFork, 0);
    cudaStreamWaitEvent(s2, evFork, 0);

    // s2: all weight transposes
    {
        dim3 blk(32, 8);
        tsplit_kernel<<<dim3(16, 64), blk, 0, s2>>>(W_att, BWatt_h, BWatt_l, EE, HH, EE, 0);
        tsplit_kernel<<<dim3(16, 64), blk, 0, s2>>>(Wih, BWihc_h, BWihc_l, EE, HH, EE, 0);
        tsplit_kernel<<<dim3(16, 64), blk, 0, s2>>>(Wic, BWihc_h + (size_t)HH * EE,
                                                    BWihc_l + (size_t)HH * EE, EE, HH, EE, 0);
        tsplit_kernel<<<dim3(16, 16), blk, 0, s2>>>(U_att, Bqg_h, Bqg_l, HH, HH, HH, 0);
        tsplit_kernel<<<dim3(64, 16), blk, 0, s2>>>(Wfb, Bqg_h + (size_t)HH * HH,
                                                    Bqg_l + (size_t)HH * HH, HH, EE, HH, 0);
        tsplit_kernel<<<dim3(64, 80), blk, 0, s2>>>(Wl, BWcat_h, BWcat_l, 2560, G4, XK, 0);
        tsplit_kernel<<<dim3(64, 16), blk, 0, s2>>>(Ul, BWcat_h, BWcat_l, HH, G4, XK, 2560);
        tsplit_kernel<<<dim3(VPAD / 32, 16), blk, 0, s2>>>(Wdo, BWdo_h, BWdo_l, HH, VV, HH, 0);
        cudaEventRecord(evTsplit, s2);
    }

    // main: img split + fp16 + avg
    imgprep_kernel<<<dim3(EE / 256, BB), 256>>>(img, imgh, imgl, img16, avgh, avgl);
    cudaEventRecord(evImg, 0);

    // s2: merged h0|c0 GEMM + combine
    cudaStreamWaitEvent(s2, evImg, 0);
    tc_gemm<float><<<dim3(HC / 128, 1, 8), 256, SMEM_SZ, s2>>>(
        avgh, avgl, EE, BWihc_h, BWihc_l, nullptr, pgatesp, HC, (long)128 * HC, HC, EE);
    combine_init<<<(BB * HH) / 256, 256, 0, s2>>>(pgatesp, bih, bic, Wemb, cap, pc, Xh, Xl);
    cudaEventRecord(evInit, s2);

    // main: W_s (fp16 output)
    cudaStreamWaitEvent(0, evTsplit, 0);
    tc_gemm<__half><<<dim3(4, 196, 1), 256, SMEM_SZ>>>(imgh, imgl, EE, BWatt_h, BWatt_l,
                                                       bW, pWs16, HH, (long)128 * HH, HH, EE);
    cudaStreamWaitEvent(0, evInit, 0);

    for (int t = 0; t < SS; t++) {
        tc_gemm<float><<<dim3(QG / 128, 1, 4), 256, SMEM_SZ>>>(
            Xh + 2560, Xl + 2560, XK, Bqg_h, Bqg_l, nullptr, pqgp,
            QG, (long)128 * QG, QG, HH);
        attention_kernel<<<BB, 1024>>>(pWs16, pqgp, bU, v_att, bv, palpha,
                                       alphas + (size_t)t * PP);
        ctx_mma_kernel<<<dim3(EE / 512, BB), 256>>>(img16, palpha, pqgp, bfb, Xh, Xl);
        tc_gemm<float><<<dim3(16, 1, 8), 256, SMEM_SZ>>>(
            Xh, Xl, XK, BWcat_h, BWcat_l, nullptr, pgatesp,
            G4, (long)128 * G4, G4, XK);
        lstm_kernel<<<(BB * HH) / 256, 256>>>(pgatesp, bl, pc, Xh, Xl, Hh, Hl, Wemb, cap, t);
        cudaEventRecord(evStep[t], 0);
        cudaStreamWaitEvent(s2, evStep[t], 0);
        tc_gemm<float><<<dim3(VPAD / 128, 1, 1), 256, SMEM_SZ, s2>>>(
            Hh + (size_t)t * BB * HH, Hl + (size_t)t * BB * HH, HH,
            BWdo_h, BWdo_l, bdo, preds + (size_t)t * VV, SS * VV, 0L, VV, HH);
    }

    cudaEventRecord(evDone, s2);
    cudaStreamWaitEvent(0, evDone, 0);
}